// round 6
// baseline (speedup 1.0000x reference)
#include <cuda_runtime.h>
#include <cuda_bf16.h>
#include <mma.h>
#include <math.h>
#include <cstdint>

using namespace nvcuda;

#define BB 2
#define SS 2048
#define DD 1024
#define HH 16
#define KHH 4
#define DKK 64
#define REP 4
#define NQKV 1536   // 1024 Q | 256 K | 256 V

// fp32 scratch
__device__ float g_qkv[BB * SS * NQKV];      // packed Q|K|V per (b,s) row
__device__ float g_o[BB * SS * HH * DKK];    // attention out, (b,s,h,dk)
__device__ float g_cos[SS * 32];
__device__ float g_sin[SS * 32];
__device__ float g_bqkv[NQKV];

// bf16 split scratch
__device__ __nv_bfloat16 g_xhi[BB * SS * DD],    g_xlo[BB * SS * DD];
__device__ __nv_bfloat16 g_ohi[BB * SS * DD],    g_olo[BB * SS * DD];
__device__ __nv_bfloat16 g_wqkvhi[DD * NQKV],    g_wqkvlo[DD * NQKV];
__device__ __nv_bfloat16 g_wohi[DD * DD],        g_wolo[DD * DD];
__device__ __nv_bfloat16 g_qkvhi[BB * SS * NQKV], g_qkvlo[BB * SS * NQKV];

// ---------------------------------------------------------------------------
// cp.async helpers
// ---------------------------------------------------------------------------
__device__ __forceinline__ void cp_async16(void* sptr, const void* gptr) {
    unsigned int s = (unsigned int)__cvta_generic_to_shared(sptr);
    asm volatile("cp.async.cg.shared.global [%0], [%1], 16;\n" :: "r"(s), "l"(gptr));
}
__device__ __forceinline__ void cp_commit() {
    asm volatile("cp.async.commit_group;\n");
}
__device__ __forceinline__ void cp_wait1() {
    asm volatile("cp.async.wait_group 1;\n");
}
__device__ __forceinline__ void cp_wait0() {
    asm volatile("cp.async.wait_group 0;\n");
}

// ---------------------------------------------------------------------------
// Split fp32 -> (bf16 hi, bf16 lo)
// ---------------------------------------------------------------------------
__global__ void split_kernel(const float* __restrict__ in,
                             __nv_bfloat16* __restrict__ hi,
                             __nv_bfloat16* __restrict__ lo, int n) {
    int i = blockIdx.x * blockDim.x + threadIdx.x;
    if (i >= n) return;
    float f = in[i];
    __nv_bfloat16 h = __float2bfloat16(f);
    hi[i] = h;
    lo[i] = __float2bfloat16(f - __bfloat162float(h));
}

// Pack Wq|Wk|Wv -> [1024][1536] hi/lo, and bq|bk|bv -> g_bqkv
__global__ void pack_wqkv_kernel(const float* __restrict__ Wq, const float* __restrict__ Wk,
                                 const float* __restrict__ Wv, const float* __restrict__ bq,
                                 const float* __restrict__ bk, const float* __restrict__ bv,
                                 __nv_bfloat16* __restrict__ hi, __nv_bfloat16* __restrict__ lo,
                                 float* __restrict__ bqkv) {
    int i = blockIdx.x * blockDim.x + threadIdx.x;
    int n = DD * NQKV;
    if (i < NQKV) {
        int c = i;
        bqkv[c] = (c < 1024) ? bq[c] : (c < 1280 ? bk[c - 1024] : bv[c - 1280]);
    }
    if (i >= n) return;
    int row = i / NQKV;
    int col = i % NQKV;
    float f;
    if (col < 1024)      f = Wq[row * 1024 + col];
    else if (col < 1280) f = Wk[row * 256 + col - 1024];
    else                 f = Wv[row * 256 + col - 1280];
    __nv_bfloat16 h = __float2bfloat16(f);
    hi[i] = h;
    lo[i] = __float2bfloat16(f - __bfloat162float(h));
}

// ---------------------------------------------------------------------------
// bf16x3 GEMM v2 (unchanged from R5)
// ---------------------------------------------------------------------------
#define GSM_A_BYTES (2 * 2 * 128 * 40 * 2)
#define GSM_B_BYTES (2 * 2 * 32 * 136 * 2)
#define GSM_STAGE_BYTES (8 * 16 * 20 * 4)
#define GSM_TOTAL (GSM_A_BYTES + GSM_B_BYTES + GSM_STAGE_BYTES)

__device__ __forceinline__ int sA_idx(int buf, int part, int r, int c) {
    return ((buf * 2 + part) * 128 + r) * 40 + c;
}
__device__ __forceinline__ int sB_idx(int buf, int part, int r, int c) {
    return ((buf * 2 + part) * 32 + r) * 136 + c;
}

__global__ __launch_bounds__(256)
void gemm_bf16x3_v2(const __nv_bfloat16* __restrict__ Ahi,
                    const __nv_bfloat16* __restrict__ Alo,
                    const __nv_bfloat16* __restrict__ Bhi,
                    const __nv_bfloat16* __restrict__ Blo,
                    const float* __restrict__ bias, float* __restrict__ C,
                    int M, int N, int K) {
    extern __shared__ __align__(16) unsigned char smraw[];
    __nv_bfloat16* sA = (__nv_bfloat16*)smraw;
    __nv_bfloat16* sB = (__nv_bfloat16*)(smraw + GSM_A_BYTES);
    float* stage = (float*)(smraw + GSM_A_BYTES + GSM_B_BYTES);

    const int tid = threadIdx.x;
    const int warp = tid >> 5;
    const int lane = tid & 31;
    const int m0 = blockIdx.y * 128;
    const int n0 = blockIdx.x * 128;
    const int wm = warp >> 1;
    const int wn = warp & 1;

    wmma::fragment<wmma::accumulator, 16, 16, 16, float> acc[2][4];
#pragma unroll
    for (int i = 0; i < 2; i++)
#pragma unroll
        for (int j = 0; j < 4; j++) wmma::fill_fragment(acc[i][j], 0.0f);

    const int nk = K / 32;

    auto load_stage = [&](int buf, int k0) {
#pragma unroll
        for (int c = tid; c < 512; c += 256) {
            int r = c >> 2;
            int cc = (c & 3) * 8;
            size_t g = (size_t)(m0 + r) * K + k0 + cc;
            cp_async16(&sA[sA_idx(buf, 0, r, cc)], &Ahi[g]);
            cp_async16(&sA[sA_idx(buf, 1, r, cc)], &Alo[g]);
        }
#pragma unroll
        for (int c = tid; c < 512; c += 256) {
            int r = c >> 4;
            int cc = (c & 15) * 8;
            size_t g = (size_t)(k0 + r) * N + n0 + cc;
            cp_async16(&sB[sB_idx(buf, 0, r, cc)], &Bhi[g]);
            cp_async16(&sB[sB_idx(buf, 1, r, cc)], &Blo[g]);
        }
        cp_commit();
    };

    load_stage(0, 0);

    for (int kt = 0; kt < nk; kt++) {
        int buf = kt & 1;
        if (kt + 1 < nk) {
            load_stage(buf ^ 1, (kt + 1) * 32);
            cp_wait1();
        } else {
            cp_wait0();
        }
        __syncthreads();

#pragma unroll
        for (int ks = 0; ks < 2; ks++) {
            wmma::fragment<wmma::matrix_a, 16, 16, 16, __nv_bfloat16, wmma::row_major> ahi[2], alo[2];
#pragma unroll
            for (int i = 0; i < 2; i++) {
                wmma::load_matrix_sync(ahi[i], &sA[sA_idx(buf, 0, wm * 32 + i * 16, ks * 16)], 40);
                wmma::load_matrix_sync(alo[i], &sA[sA_idx(buf, 1, wm * 32 + i * 16, ks * 16)], 40);
            }
#pragma unroll
            for (int j = 0; j < 4; j++) {
                wmma::fragment<wmma::matrix_b, 16, 16, 16, __nv_bfloat16, wmma::row_major> bhi, blo;
                wmma::load_matrix_sync(bhi, &sB[sB_idx(buf, 0, ks * 16, wn * 64 + j * 16)], 136);
                wmma::load_matrix_sync(blo, &sB[sB_idx(buf, 1, ks * 16, wn * 64 + j * 16)], 136);
#pragma unroll
                for (int i = 0; i < 2; i++) {
                    wmma::mma_sync(acc[i][j], ahi[i], bhi, acc[i][j]);
                    wmma::mma_sync(acc[i][j], ahi[i], blo, acc[i][j]);
                    wmma::mma_sync(acc[i][j], alo[i], bhi, acc[i][j]);
                }
            }
        }
        __syncthreads();
    }

    float* wstage = stage + warp * 16 * 20;
#pragma unroll
    for (int i = 0; i < 2; i++) {
#pragma unroll
        for (int j = 0; j < 4; j++) {
            wmma::store_matrix_sync(wstage, acc[i][j], 20, wmma::mem_row_major);
            __syncwarp();
            int row0 = m0 + wm * 32 + i * 16;
            int col0 = n0 + wn * 64 + j * 16;
#pragma unroll
            for (int e = 0; e < 8; e++) {
                int t = e * 32 + lane;
                int r = t >> 4;
                int c = t & 15;
                C[(size_t)(row0 + r) * N + col0 + c] = wstage[r * 20 + c] + bias[col0 + c];
            }
            __syncwarp();
        }
    }
}

// ---------------------------------------------------------------------------
// RoPE table + apply (unchanged)
// ---------------------------------------------------------------------------
__global__ void rope_table_kernel(float* __restrict__ ctab, float* __restrict__ stab) {
    int idx = blockIdx.x * blockDim.x + threadIdx.x;
    if (idx >= SS * 32) return;
    int s = idx >> 5;
    int d = idx & 31;
    double theta = pow(10000.0, -(double)d / 32.0);
    double f = (double)s * theta;
    ctab[idx] = (float)cos(f);
    stab[idx] = (float)sin(f);
}

__global__ void rope_apply_kernel(float* __restrict__ qkv,
                                  const float* __restrict__ ctab,
                                  const float* __restrict__ stab) {
    const int NQp = BB * SS * HH * 32;
    const int NKp = BB * SS * KHH * 32;
    int idx = blockIdx.x * blockDim.x + threadIdx.x;
    if (idx >= NQp + NKp) return;

    float* p;
    int s, d;
    if (idx < NQp) {
        int bs = idx / (HH * 32);
        int rem = idx % (HH * 32);
        int h = rem >> 5;
        d = rem & 31;
        s = bs % SS;
        p = qkv + (size_t)bs * NQKV + h * DKK;
    } else {
        int i2 = idx - NQp;
        int bs = i2 / (KHH * 32);
        int rem = i2 % (KHH * 32);
        int kh = rem >> 5;
        d = rem & 31;
        s = bs % SS;
        p = qkv + (size_t)bs * NQKV + 1024 + kh * DKK;
    }

    int t = s * 32 + d;
    float c = ctab[t];
    float sn = stab[t];
    float x1 = p[d];
    float x2 = p[d + 32];
    p[d] = x1 * c - x2 * sn;
    p[d + 32] = x2 * c + x1 * sn;
}

// ---------------------------------------------------------------------------
// Tensor-core flash attention (causal, GQA), bf16 hi/lo compensated.
// Block: 64 q-rows x (h, b). 256 threads = 8 warps (4m x 2n), warp tile 16x32.
// ---------------------------------------------------------------------------
// smem byte offsets
#define FO_QHI 0
#define FO_QLO 9216
#define FO_KHI 18432
#define FO_KLO 27648
#define FO_VHI 36864
#define FO_VLO 46080
#define FO_PHI 55296
#define FO_PLO 64512
#define FO_SF  73728
#define FO_M   91136
#define FO_L   91392
#define FO_AL  91648
#define FL_SMEM_TOTAL 91904

__global__ __launch_bounds__(256, 2)
void flash_tc_kernel(const __nv_bfloat16* __restrict__ qh,
                     const __nv_bfloat16* __restrict__ ql,
                     float* __restrict__ o) {
    extern __shared__ __align__(16) unsigned char fsm[];
    __nv_bfloat16* Qhi = (__nv_bfloat16*)(fsm + FO_QHI);
    __nv_bfloat16* Qlo = (__nv_bfloat16*)(fsm + FO_QLO);
    __nv_bfloat16* Khi = (__nv_bfloat16*)(fsm + FO_KHI);
    __nv_bfloat16* Klo = (__nv_bfloat16*)(fsm + FO_KLO);
    __nv_bfloat16* Vhi = (__nv_bfloat16*)(fsm + FO_VHI);
    __nv_bfloat16* Vlo = (__nv_bfloat16*)(fsm + FO_VLO);
    __nv_bfloat16* Phi = (__nv_bfloat16*)(fsm + FO_PHI);
    __nv_bfloat16* Plo = (__nv_bfloat16*)(fsm + FO_PLO);
    float* Sf   = (float*)(fsm + FO_SF);
    float* m_sh = (float*)(fsm + FO_M);
    float* l_sh = (float*)(fsm + FO_L);
    float* al_sh= (float*)(fsm + FO_AL);

    const int tid = threadIdx.x;
    const int warp = tid >> 5;
    const int qt = blockIdx.x;
    const int h = blockIdx.y;
    const int b = blockIdx.z;
    const int kh = h >> 2;
    const int s0q = qt * 64;
    const int wm = warp >> 1;       // 0..3
    const int wn = warp & 1;        // 0..1

    // Load Q tile (64 x 64 bf16, hi+lo)
    for (int t = tid; t < 512; t += 256) {
        int r = t >> 3;
        int ch = (t & 7) * 8;
        size_t g = (size_t)(b * SS + s0q + r) * NQKV + h * DKK + ch;
        *reinterpret_cast<uint4*>(&Qhi[r * 72 + ch]) = *reinterpret_cast<const uint4*>(&qh[g]);
        *reinterpret_cast<uint4*>(&Qlo[r * 72 + ch]) = *reinterpret_cast<const uint4*>(&ql[g]);
    }
    if (tid < 64) { m_sh[tid] = -1e30f; l_sh[tid] = 0.0f; }

    const int orow = tid >> 2;       // 0..63
    const int oq = tid & 3;
    const int oc0 = oq * 16;
    float ov[16];
#pragma unroll
    for (int i = 0; i < 16; i++) ov[i] = 0.0f;

    for (int kt = 0; kt <= qt; kt++) {
        const int s0k = kt * 64;

        // Load K and V tiles (hi+lo)
        for (int t = tid; t < 512; t += 256) {
            int r = t >> 3;
            int ch = (t & 7) * 8;
            size_t g = (size_t)(b * SS + s0k + r) * NQKV + 1024 + kh * DKK + ch;
            *reinterpret_cast<uint4*>(&Khi[r * 72 + ch]) = *reinterpret_cast<const uint4*>(&qh[g]);
            *reinterpret_cast<uint4*>(&Klo[r * 72 + ch]) = *reinterpret_cast<const uint4*>(&ql[g]);
            *reinterpret_cast<uint4*>(&Vhi[r * 72 + ch]) = *reinterpret_cast<const uint4*>(&qh[g + 256]);
            *reinterpret_cast<uint4*>(&Vlo[r * 72 + ch]) = *reinterpret_cast<const uint4*>(&ql[g + 256]);
        }
        __syncthreads();

        // S = Q @ K^T (hi/lo compensated)
        {
            wmma::fragment<wmma::accumulator, 16, 16, 16, float> accs[2];
#pragma unroll
            for (int j = 0; j < 2; j++) wmma::fill_fragment(accs[j], 0.0f);
#pragma unroll
            for (int ks = 0; ks < 4; ks++) {
                wmma::fragment<wmma::matrix_a, 16, 16, 16, __nv_bfloat16, wmma::row_major> a_hi, a_lo;
                wmma::load_matrix_sync(a_hi, &Qhi[(wm * 16) * 72 + ks * 16], 72);
                wmma::load_matrix_sync(a_lo, &Qlo[(wm * 16) * 72 + ks * 16], 72);
#pragma unroll
                for (int j = 0; j < 2; j++) {
                    wmma::fragment<wmma::matrix_b, 16, 16, 16, __nv_bfloat16, wmma::col_major> b_hi, b_lo;
                    wmma::load_matrix_sync(b_hi, &Khi[(wn * 32 + j * 16) * 72 + ks * 16], 72);
                    wmma::load_matrix_sync(b_lo, &Klo[(wn * 32 + j * 16) * 72 + ks * 16], 72);
                    wmma::mma_sync(accs[j], a_hi, b_hi, accs[j]);
                    wmma::mma_sync(accs[j], a_hi, b_lo, accs[j]);
                    wmma::mma_sync(accs[j], a_lo, b_hi, accs[j]);
                }
            }
#pragma unroll
            for (int j = 0; j < 2; j++)
                wmma::store_matrix_sync(&Sf[(wm * 16) * 68 + wn * 32 + j * 16], accs[j], 68,
                                        wmma::mem_row_major);
        }
        __syncthreads();

        // Softmax (4 threads per row), write P hi/lo
        {
            const int r = orow;
            float mo = m_sh[r];
            float sv[16];
            float vmax = -1e30f;
#pragma unroll
            for (int i = 0; i < 16; i++) {
                float s = Sf[r * 68 + oc0 + i] * 0.125f;
                if (s0k + oc0 + i > s0q + r) s = -1e30f;
                sv[i] = s;
                vmax = fmaxf(vmax, s);
            }
            vmax = fmaxf(vmax, __shfl_xor_sync(0xffffffffu, vmax, 1));
            vmax = fmaxf(vmax, __shfl_xor_sync(0xffffffffu, vmax, 2));
            float mx = fmaxf(mo, vmax);
            float al = __expf(mo - mx);
            float sum = 0.0f;
#pragma unroll
            for (int i = 0; i < 16; i++) {
                float p = __expf(sv[i] - mx);
                sum += p;
                __nv_bfloat16 ph = __float2bfloat16(p);
                Phi[r * 72 + oc0 + i] = ph;
                Plo[r * 72 + oc0 + i] = __float2bfloat16(p - __bfloat162float(ph));
            }
            sum += __shfl_xor_sync(0xffffffffu, sum, 1);
            sum += __shfl_xor_sync(0xffffffffu, sum, 2);
            if (oq == 0) {
                m_sh[r] = mx;
                l_sh[r] = l_sh[r] * al + sum;
                al_sh[r] = al;
            }
        }
        __syncthreads();

        // PV (hi/lo compensated), stage into Sf
        {
            wmma::fragment<wmma::accumulator, 16, 16, 16, float> acco[2];
#pragma unroll
            for (int j = 0; j < 2; j++) wmma::fill_fragment(acco[j], 0.0f);
#pragma unroll
            for (int ks = 0; ks < 4; ks++) {
                wmma::fragment<wmma::matrix_a, 16, 16, 16, __nv_bfloat16, wmma::row_major> p_hi, p_lo;
                wmma::load_matrix_sync(p_hi, &Phi[(wm * 16) * 72 + ks * 16], 72);
                wmma::load_matrix_sync(p_lo, &Plo[(wm * 16) * 72 + ks * 16], 72);
#pragma unroll
                for (int j = 0; j < 2; j++) {
                    wmma::fragment<wmma::matrix_b, 16, 16, 16, __nv_bfloat16, wmma::row_major> v_hi, v_lo;
                    wmma::load_matrix_sync(v_hi, &Vhi[(ks * 16) * 72 + wn * 32 + j * 16], 72);
                    wmma::load_matrix_sync(v_lo, &Vlo[(ks * 16) * 72 + wn * 32 + j * 16], 72);
                    wmma::mma_sync(acco[j], p_hi, v_hi, acco[j]);
                    wmma::mma_sync(acco[j], p_hi, v_lo, acco[j]);
                    wmma::mma_sync(acco[j], p_lo, v_hi, acco[j]);
                }
            }
#pragma unroll
            for (int j = 0; j < 2; j++)
                wmma::store_matrix_sync(&Sf[(wm * 16) * 68 + wn * 32 + j * 16], acco[j], 68,
                                        wmma::mem_row_major);
        }
        __syncthreads();

        // O update in registers
        {
            float al = al_sh[orow];
#pragma unroll
            for (int i = 0; i < 16; i++)
                ov[i] = ov[i] * al + Sf[orow * 68 + oc0 + i];
        }
        __syncthreads();
    }

    float invl = 1.0f / l_sh[orow];
#pragma unroll
    for (int i = 0; i < 16; i++)
        o[(size_t)(b * SS + s0q + orow) * (HH * DKK) + h * DKK + oc0 + i] = ov[i] * invl;
}

// ---------------------------------------------------------------------------
// Launch
// ---------------------------------------------------------------------------
extern "C" void kernel_launch(void* const* d_in, const int* in_sizes, int n_in,
                              void* d_out, int out_size) {
    const float* x  = (const float*)d_in[0];
    const float* Wq = (const float*)d_in[2];
    const float* bq = (const float*)d_in[3];
    const float* Wk = (const float*)d_in[4];
    const float* bk = (const float*)d_in[5];
    const float* Wv = (const float*)d_in[6];
    const float* bv = (const float*)d_in[7];
    const float* Wo = (const float*)d_in[8];
    const float* bo = (const float*)d_in[9];
    float* out = (float*)d_out;

    float *gqkv, *go, *gc, *gs, *gbqkv;
    cudaGetSymbolAddress((void**)&gqkv, g_qkv);
    cudaGetSymbolAddress((void**)&go, g_o);
    cudaGetSymbolAddress((void**)&gc, g_cos);
    cudaGetSymbolAddress((void**)&gs, g_sin);
    cudaGetSymbolAddress((void**)&gbqkv, g_bqkv);

    __nv_bfloat16 *xhi, *xlo, *ohi, *olo, *wqkvhi, *wqkvlo, *wohi, *wolo, *qkvhi, *qkvlo;
    cudaGetSymbolAddress((void**)&xhi, g_xhi);
    cudaGetSymbolAddress((void**)&xlo, g_xlo);
    cudaGetSymbolAddress((void**)&ohi, g_ohi);
    cudaGetSymbolAddress((void**)&olo, g_olo);
    cudaGetSymbolAddress((void**)&wqkvhi, g_wqkvhi);
    cudaGetSymbolAddress((void**)&wqkvlo, g_wqkvlo);
    cudaGetSymbolAddress((void**)&wohi, g_wohi);
    cudaGetSymbolAddress((void**)&wolo, g_wolo);
    cudaGetSymbolAddress((void**)&qkvhi, g_qkvhi);
    cudaGetSymbolAddress((void**)&qkvlo, g_qkvlo);

    const int M = BB * SS;  // 4096
    dim3 blk(256);

    rope_table_kernel<<<(SS * 32 + 255) / 256, 256>>>(gc, gs);

    int nx = M * DD;
    split_kernel<<<(nx + 255) / 256, 256>>>(x, xhi, xlo, nx);
    pack_wqkv_kernel<<<(DD * NQKV + 255) / 256, 256>>>(Wq, Wk, Wv, bq, bk, bv,
                                                       wqkvhi, wqkvlo, gbqkv);
    split_kernel<<<(DD * DD + 255) / 256, 256>>>(Wo, wohi, wolo, DD * DD);

    cudaFuncSetAttribute(gemm_bf16x3_v2, cudaFuncAttributeMaxDynamicSharedMemorySize,
                         GSM_TOTAL);

    // QKV = x @ Wqkv + bqkv
    gemm_bf16x3_v2<<<dim3(NQKV / 128, M / 128), blk, GSM_TOTAL>>>(
        xhi, xlo, wqkvhi, wqkvlo, gbqkv, gqkv, M, NQKV, 1024);

    int nrope = BB * SS * (HH + KHH) * 32;
    rope_apply_kernel<<<(nrope + 255) / 256, 256>>>(gqkv, gc, gs);

    // Split roped QKV to bf16 hi/lo for tensor-core flash
    int nqkv = M * NQKV;
    split_kernel<<<(nqkv + 255) / 256, 256>>>(gqkv, qkvhi, qkvlo, nqkv);

    cudaFuncSetAttribute(flash_tc_kernel, cudaFuncAttributeMaxDynamicSharedMemorySize,
                         FL_SMEM_TOTAL);
    flash_tc_kernel<<<dim3(SS / 64, HH, BB), blk, FL_SMEM_TOTAL>>>(qkvhi, qkvlo, go);

    split_kernel<<<(nx + 255) / 256, 256>>>(go, ohi, olo, nx);
    gemm_bf16x3_v2<<<dim3(1024 / 128, M / 128), blk, GSM_TOTAL>>>(
        ohi, olo, wohi, wolo, bo, out, M, 1024, 1024);
}

// round 7
// speedup vs baseline: 1.3968x; 1.3968x over previous
#include <cuda_runtime.h>
#include <cuda_bf16.h>
#include <mma.h>
#include <math.h>
#include <cstdint>

using namespace nvcuda;

#define BB 2
#define SS 2048
#define DD 1024
#define HH 16
#define KHH 4
#define DKK 64
#define REP 4
#define NQKV 1536   // 1024 Q | 256 K | 256 V

// fp32 scratch
__device__ float g_qkv[BB * SS * NQKV];
__device__ float g_o[BB * SS * HH * DKK];
__device__ float g_cos[SS * 32];
__device__ float g_sin[SS * 32];
__device__ float g_bqkv[NQKV];

// bf16 split scratch
__device__ __nv_bfloat16 g_xhi[BB * SS * DD],    g_xlo[BB * SS * DD];
__device__ __nv_bfloat16 g_ohi[BB * SS * DD],    g_olo[BB * SS * DD];
__device__ __nv_bfloat16 g_wqkvhi[DD * NQKV],    g_wqkvlo[DD * NQKV];
__device__ __nv_bfloat16 g_wohi[DD * DD],        g_wolo[DD * DD];
__device__ __nv_bfloat16 g_qkvhi[BB * SS * NQKV], g_qkvlo[BB * SS * NQKV];

// ---------------------------------------------------------------------------
// cp.async helpers
// ---------------------------------------------------------------------------
__device__ __forceinline__ void cp_async16(void* sptr, const void* gptr) {
    unsigned int s = (unsigned int)__cvta_generic_to_shared(sptr);
    asm volatile("cp.async.cg.shared.global [%0], [%1], 16;\n" :: "r"(s), "l"(gptr));
}
__device__ __forceinline__ void cp_commit() {
    asm volatile("cp.async.commit_group;\n");
}
__device__ __forceinline__ void cp_wait1() {
    asm volatile("cp.async.wait_group 1;\n");
}
__device__ __forceinline__ void cp_wait0() {
    asm volatile("cp.async.wait_group 0;\n");
}

// ---------------------------------------------------------------------------
// Split fp32 -> (bf16 hi, bf16 lo)
// ---------------------------------------------------------------------------
__global__ void split_kernel(const float* __restrict__ in,
                             __nv_bfloat16* __restrict__ hi,
                             __nv_bfloat16* __restrict__ lo, int n) {
    int i = blockIdx.x * blockDim.x + threadIdx.x;
    if (i >= n) return;
    float f = in[i];
    __nv_bfloat16 h = __float2bfloat16(f);
    hi[i] = h;
    lo[i] = __float2bfloat16(f - __bfloat162float(h));
}

// Pack Wq|Wk|Wv -> [1024][1536] hi/lo, and bq|bk|bv -> g_bqkv
__global__ void pack_wqkv_kernel(const float* __restrict__ Wq, const float* __restrict__ Wk,
                                 const float* __restrict__ Wv, const float* __restrict__ bq,
                                 const float* __restrict__ bk, const float* __restrict__ bv,
                                 __nv_bfloat16* __restrict__ hi, __nv_bfloat16* __restrict__ lo,
                                 float* __restrict__ bqkv) {
    int i = blockIdx.x * blockDim.x + threadIdx.x;
    int n = DD * NQKV;
    if (i < NQKV) {
        int c = i;
        bqkv[c] = (c < 1024) ? bq[c] : (c < 1280 ? bk[c - 1024] : bv[c - 1280]);
    }
    if (i >= n) return;
    int row = i / NQKV;
    int col = i % NQKV;
    float f;
    if (col < 1024)      f = Wq[row * 1024 + col];
    else if (col < 1280) f = Wk[row * 256 + col - 1024];
    else                 f = Wv[row * 256 + col - 1280];
    __nv_bfloat16 h = __float2bfloat16(f);
    hi[i] = h;
    lo[i] = __float2bfloat16(f - __bfloat162float(h));
}

// ---------------------------------------------------------------------------
// bf16x3 GEMM v2 (unchanged, known-good)
// ---------------------------------------------------------------------------
#define GSM_A_BYTES (2 * 2 * 128 * 40 * 2)
#define GSM_B_BYTES (2 * 2 * 32 * 136 * 2)
#define GSM_STAGE_BYTES (8 * 16 * 20 * 4)
#define GSM_TOTAL (GSM_A_BYTES + GSM_B_BYTES + GSM_STAGE_BYTES)

__device__ __forceinline__ int sA_idx(int buf, int part, int r, int c) {
    return ((buf * 2 + part) * 128 + r) * 40 + c;
}
__device__ __forceinline__ int sB_idx(int buf, int part, int r, int c) {
    return ((buf * 2 + part) * 32 + r) * 136 + c;
}

__global__ __launch_bounds__(256)
void gemm_bf16x3_v2(const __nv_bfloat16* __restrict__ Ahi,
                    const __nv_bfloat16* __restrict__ Alo,
                    const __nv_bfloat16* __restrict__ Bhi,
                    const __nv_bfloat16* __restrict__ Blo,
                    const float* __restrict__ bias, float* __restrict__ C,
                    int M, int N, int K) {
    extern __shared__ __align__(16) unsigned char smraw[];
    __nv_bfloat16* sA = (__nv_bfloat16*)smraw;
    __nv_bfloat16* sB = (__nv_bfloat16*)(smraw + GSM_A_BYTES);
    float* stage = (float*)(smraw + GSM_A_BYTES + GSM_B_BYTES);

    const int tid = threadIdx.x;
    const int warp = tid >> 5;
    const int lane = tid & 31;
    const int m0 = blockIdx.y * 128;
    const int n0 = blockIdx.x * 128;
    const int wm = warp >> 1;
    const int wn = warp & 1;

    wmma::fragment<wmma::accumulator, 16, 16, 16, float> acc[2][4];
#pragma unroll
    for (int i = 0; i < 2; i++)
#pragma unroll
        for (int j = 0; j < 4; j++) wmma::fill_fragment(acc[i][j], 0.0f);

    const int nk = K / 32;

    auto load_stage = [&](int buf, int k0) {
#pragma unroll
        for (int c = tid; c < 512; c += 256) {
            int r = c >> 2;
            int cc = (c & 3) * 8;
            size_t g = (size_t)(m0 + r) * K + k0 + cc;
            cp_async16(&sA[sA_idx(buf, 0, r, cc)], &Ahi[g]);
            cp_async16(&sA[sA_idx(buf, 1, r, cc)], &Alo[g]);
        }
#pragma unroll
        for (int c = tid; c < 512; c += 256) {
            int r = c >> 4;
            int cc = (c & 15) * 8;
            size_t g = (size_t)(k0 + r) * N + n0 + cc;
            cp_async16(&sB[sB_idx(buf, 0, r, cc)], &Bhi[g]);
            cp_async16(&sB[sB_idx(buf, 1, r, cc)], &Blo[g]);
        }
        cp_commit();
    };

    load_stage(0, 0);

    for (int kt = 0; kt < nk; kt++) {
        int buf = kt & 1;
        if (kt + 1 < nk) {
            load_stage(buf ^ 1, (kt + 1) * 32);
            cp_wait1();
        } else {
            cp_wait0();
        }
        __syncthreads();

#pragma unroll
        for (int ks = 0; ks < 2; ks++) {
            wmma::fragment<wmma::matrix_a, 16, 16, 16, __nv_bfloat16, wmma::row_major> ahi[2], alo[2];
#pragma unroll
            for (int i = 0; i < 2; i++) {
                wmma::load_matrix_sync(ahi[i], &sA[sA_idx(buf, 0, wm * 32 + i * 16, ks * 16)], 40);
                wmma::load_matrix_sync(alo[i], &sA[sA_idx(buf, 1, wm * 32 + i * 16, ks * 16)], 40);
            }
#pragma unroll
            for (int j = 0; j < 4; j++) {
                wmma::fragment<wmma::matrix_b, 16, 16, 16, __nv_bfloat16, wmma::row_major> bhi, blo;
                wmma::load_matrix_sync(bhi, &sB[sB_idx(buf, 0, ks * 16, wn * 64 + j * 16)], 136);
                wmma::load_matrix_sync(blo, &sB[sB_idx(buf, 1, ks * 16, wn * 64 + j * 16)], 136);
#pragma unroll
                for (int i = 0; i < 2; i++) {
                    wmma::mma_sync(acc[i][j], ahi[i], bhi, acc[i][j]);
                    wmma::mma_sync(acc[i][j], ahi[i], blo, acc[i][j]);
                    wmma::mma_sync(acc[i][j], alo[i], bhi, acc[i][j]);
                }
            }
        }
        __syncthreads();
    }

    float* wstage = stage + warp * 16 * 20;
#pragma unroll
    for (int i = 0; i < 2; i++) {
#pragma unroll
        for (int j = 0; j < 4; j++) {
            wmma::store_matrix_sync(wstage, acc[i][j], 20, wmma::mem_row_major);
            __syncwarp();
            int row0 = m0 + wm * 32 + i * 16;
            int col0 = n0 + wn * 64 + j * 16;
#pragma unroll
            for (int e = 0; e < 8; e++) {
                int t = e * 32 + lane;
                int r = t >> 4;
                int c = t & 15;
                C[(size_t)(row0 + r) * N + col0 + c] = wstage[r * 20 + c] + bias[col0 + c];
            }
            __syncwarp();
        }
    }
}

// ---------------------------------------------------------------------------
// RoPE table + apply (unchanged)
// ---------------------------------------------------------------------------
__global__ void rope_table_kernel(float* __restrict__ ctab, float* __restrict__ stab) {
    int idx = blockIdx.x * blockDim.x + threadIdx.x;
    if (idx >= SS * 32) return;
    int s = idx >> 5;
    int d = idx & 31;
    double theta = pow(10000.0, -(double)d / 32.0);
    double f = (double)s * theta;
    ctab[idx] = (float)cos(f);
    stab[idx] = (float)sin(f);
}

__global__ void rope_apply_kernel(float* __restrict__ qkv,
                                  const float* __restrict__ ctab,
                                  const float* __restrict__ stab) {
    const int NQp = BB * SS * HH * 32;
    const int NKp = BB * SS * KHH * 32;
    int idx = blockIdx.x * blockDim.x + threadIdx.x;
    if (idx >= NQp + NKp) return;

    float* p;
    int s, d;
    if (idx < NQp) {
        int bs = idx / (HH * 32);
        int rem = idx % (HH * 32);
        int h = rem >> 5;
        d = rem & 31;
        s = bs % SS;
        p = qkv + (size_t)bs * NQKV + h * DKK;
    } else {
        int i2 = idx - NQp;
        int bs = i2 / (KHH * 32);
        int rem = i2 % (KHH * 32);
        int kh = rem >> 5;
        d = rem & 31;
        s = bs % SS;
        p = qkv + (size_t)bs * NQKV + 1024 + kh * DKK;
    }

    int t = s * 32 + d;
    float c = ctab[t];
    float sn = stab[t];
    float x1 = p[d];
    float x2 = p[d + 32];
    p[d] = x1 * c - x2 * sn;
    p[d + 32] = x2 * c + x1 * sn;
}

// ---------------------------------------------------------------------------
// flash_tc_v2: GQA-grouped tensor-core flash attention.
// Block = (64 q-rows, kv-head, b). 512 threads = 16 warps. M = 256 (4 heads).
// smem: Q hi/lo (256x72) | K/V hi/lo (64x72) | SfP union (Sf f32 256x68 /
//       P hi/lo 256x72) | m/l/al.
// ---------------------------------------------------------------------------
#define F2_QHI 0
#define F2_QLO 36864
#define F2_KHI 73728
#define F2_KLO 82944
#define F2_VHI 92160
#define F2_VLO 101376
#define F2_SFP 110592           // Sf f32 (69632 B) and P hi/lo (2x36864 B) union
#define F2_PHI 110592
#define F2_PLO 147456
#define F2_M   184320
#define F2_L   185344
#define F2_AL  186368
#define F2_SMEM_TOTAL 187392

__global__ __launch_bounds__(512, 1)
void flash_tc_v2(const __nv_bfloat16* __restrict__ qh,
                 const __nv_bfloat16* __restrict__ ql,
                 float* __restrict__ o) {
    extern __shared__ __align__(16) unsigned char fsm[];
    __nv_bfloat16* Qhi = (__nv_bfloat16*)(fsm + F2_QHI);
    __nv_bfloat16* Qlo = (__nv_bfloat16*)(fsm + F2_QLO);
    __nv_bfloat16* Khi = (__nv_bfloat16*)(fsm + F2_KHI);
    __nv_bfloat16* Klo = (__nv_bfloat16*)(fsm + F2_KLO);
    __nv_bfloat16* Vhi = (__nv_bfloat16*)(fsm + F2_VHI);
    __nv_bfloat16* Vlo = (__nv_bfloat16*)(fsm + F2_VLO);
    float* Sf  = (float*)(fsm + F2_SFP);
    __nv_bfloat16* Phi = (__nv_bfloat16*)(fsm + F2_PHI);
    __nv_bfloat16* Plo = (__nv_bfloat16*)(fsm + F2_PLO);
    float* m_sh = (float*)(fsm + F2_M);
    float* l_sh = (float*)(fsm + F2_L);
    float* al_sh= (float*)(fsm + F2_AL);

    const int tid = threadIdx.x;
    const int warp = tid >> 5;
    const int qt = (int)gridDim.x - 1 - (int)blockIdx.x;   // long blocks first
    const int kh = blockIdx.y;
    const int b = blockIdx.z;
    const int s0q = qt * 64;
    const int m0w = warp * 16;          // warp's M-row base (0..240)

    // KV tile async loader (K|V hi|lo: 4 arrays x 64 x 64 bf16)
    __nv_bfloat16* kvdst[4] = {Khi, Klo, Vhi, Vlo};
    auto load_kv = [&](int s0k) {
        for (int t = tid; t < 2048; t += 512) {
            int arr = t >> 9;               // 0..3
            int r = (t >> 3) & 63;
            int ch = (t & 7) * 8;
            const __nv_bfloat16* src = (arr & 1) ? ql : qh;
            size_t g = (size_t)(b * SS + s0k + r) * NQKV + 1024 + kh * 64 +
                       ((arr >> 1) ? 256 : 0) + ch;
            cp_async16(&kvdst[arr][r * 72 + ch], &src[g]);
        }
        cp_commit();
    };

    load_kv(0);   // prefetch kt=0

    // Load Q for the 4 heads of this group: M-row m = g*64 + rr
    for (int t = tid; t < 4096; t += 512) {
        int part = t >> 11;                 // 0 = hi, 1 = lo
        int m = (t >> 3) & 255;
        int ch = (t & 7) * 8;
        int g_head = m >> 6;
        int rr = m & 63;
        const __nv_bfloat16* src = part ? ql : qh;
        size_t gaddr = (size_t)(b * SS + s0q + rr) * NQKV + (kh * 4 + g_head) * 64 + ch;
        __nv_bfloat16* dst = part ? Qlo : Qhi;
        *reinterpret_cast<uint4*>(&dst[m * 72 + ch]) =
            *reinterpret_cast<const uint4*>(&src[gaddr]);
    }
    if (tid < 256) { m_sh[tid] = -1e30f; l_sh[tid] = 0.0f; }

    const int srow = tid >> 1;          // softmax/O row (0..255)
    const int sc0 = (tid & 1) * 32;     // col half
    const int srr = srow & 63;          // q position within tile
    float ov[32];
#pragma unroll
    for (int i = 0; i < 32; i++) ov[i] = 0.0f;

    for (int kt = 0; kt <= qt; kt++) {
        const int s0k = kt * 64;
        cp_wait0();
        __syncthreads();                                 // #1 KV (and Q on iter 0) ready

        // ---- S = Q @ K^T (hi/lo compensated) ----
        {
            wmma::fragment<wmma::accumulator, 16, 16, 16, float> accs[4];
#pragma unroll
            for (int j = 0; j < 4; j++) wmma::fill_fragment(accs[j], 0.0f);
#pragma unroll
            for (int ks = 0; ks < 4; ks++) {
                wmma::fragment<wmma::matrix_a, 16, 16, 16, __nv_bfloat16, wmma::row_major> a_hi, a_lo;
                wmma::load_matrix_sync(a_hi, &Qhi[m0w * 72 + ks * 16], 72);
                wmma::load_matrix_sync(a_lo, &Qlo[m0w * 72 + ks * 16], 72);
#pragma unroll
                for (int j = 0; j < 4; j++) {
                    wmma::fragment<wmma::matrix_b, 16, 16, 16, __nv_bfloat16, wmma::col_major> b_hi, b_lo;
                    wmma::load_matrix_sync(b_hi, &Khi[(j * 16) * 72 + ks * 16], 72);
                    wmma::load_matrix_sync(b_lo, &Klo[(j * 16) * 72 + ks * 16], 72);
                    wmma::mma_sync(accs[j], a_hi, b_hi, accs[j]);
                    wmma::mma_sync(accs[j], a_hi, b_lo, accs[j]);
                    wmma::mma_sync(accs[j], a_lo, b_hi, accs[j]);
                }
            }
#pragma unroll
            for (int j = 0; j < 4; j++)
                wmma::store_matrix_sync(&Sf[m0w * 68 + j * 16], accs[j], 68, wmma::mem_row_major);
        }
        __syncthreads();                                 // #2 S staged

        // ---- softmax (2 threads/row), register-staged (Sf/P alias) ----
        float sv[32];
        {
            float vmax = -1e30f;
#pragma unroll
            for (int i = 0; i < 32; i++) {
                float s = Sf[srow * 68 + sc0 + i] * 0.125f;
                if (s0k + sc0 + i > s0q + srr) s = -1e30f;
                sv[i] = s;
                vmax = fmaxf(vmax, s);
            }
            vmax = fmaxf(vmax, __shfl_xor_sync(0xffffffffu, vmax, 1));
            float mo = m_sh[srow];
            float mx = fmaxf(mo, vmax);
            float al = __expf(mo - mx);
            __syncthreads();                             // #3 all Sf reads done
            float sum = 0.0f;
#pragma unroll
            for (int i = 0; i < 32; i++) {
                float p = __expf(sv[i] - mx);
                sum += p;
                __nv_bfloat16 ph = __float2bfloat16(p);
                Phi[srow * 72 + sc0 + i] = ph;
                Plo[srow * 72 + sc0 + i] = __float2bfloat16(p - __bfloat162float(ph));
            }
            sum += __shfl_xor_sync(0xffffffffu, sum, 1);
            if ((tid & 1) == 0) {
                m_sh[srow] = mx;
                l_sh[srow] = l_sh[srow] * al + sum;
                al_sh[srow] = al;
            }
        }
        __syncthreads();                                 // #4 P ready

        // ---- PV (hi/lo compensated) ----
        {
            wmma::fragment<wmma::accumulator, 16, 16, 16, float> acco[4];
#pragma unroll
            for (int j = 0; j < 4; j++) wmma::fill_fragment(acco[j], 0.0f);
#pragma unroll
            for (int ks = 0; ks < 4; ks++) {
                wmma::fragment<wmma::matrix_a, 16, 16, 16, __nv_bfloat16, wmma::row_major> p_hi, p_lo;
                wmma::load_matrix_sync(p_hi, &Phi[m0w * 72 + ks * 16], 72);
                wmma::load_matrix_sync(p_lo, &Plo[m0w * 72 + ks * 16], 72);
#pragma unroll
                for (int j = 0; j < 4; j++) {
                    wmma::fragment<wmma::matrix_b, 16, 16, 16, __nv_bfloat16, wmma::row_major> v_hi, v_lo;
                    wmma::load_matrix_sync(v_hi, &Vhi[(ks * 16) * 72 + j * 16], 72);
                    wmma::load_matrix_sync(v_lo, &Vlo[(ks * 16) * 72 + j * 16], 72);
                    wmma::mma_sync(acco[j], p_hi, v_hi, acco[j]);
                    wmma::mma_sync(acco[j], p_hi, v_lo, acco[j]);
                    wmma::mma_sync(acco[j], p_lo, v_hi, acco[j]);
                }
            }
            __syncthreads();                             // #5 P/V reads done, SfP & KV free

            if (kt < qt) load_kv(s0k + 64);              // prefetch next KV (overlaps below)

#pragma unroll
            for (int j = 0; j < 4; j++)
                wmma::store_matrix_sync(&Sf[m0w * 68 + j * 16], acco[j], 68, wmma::mem_row_major);
        }
        __syncthreads();                                 // #6 O staged

        {
            float al = al_sh[srow];
#pragma unroll
            for (int i = 0; i < 32; i++)
                ov[i] = ov[i] * al + Sf[srow * 68 + sc0 + i];
        }
        // loop-top sync (#1) protects Sf before next S store
    }

    float invl = 1.0f / l_sh[srow];
    int g_head = srow >> 6;
#pragma unroll
    for (int i = 0; i < 32; i++)
        o[(size_t)(b * SS + s0q + srr) * (HH * DKK) + (kh * 4 + g_head) * 64 + sc0 + i] =
            ov[i] * invl;
}

// ---------------------------------------------------------------------------
// Launch
// ---------------------------------------------------------------------------
extern "C" void kernel_launch(void* const* d_in, const int* in_sizes, int n_in,
                              void* d_out, int out_size) {
    const float* x  = (const float*)d_in[0];
    const float* Wq = (const float*)d_in[2];
    const float* bq = (const float*)d_in[3];
    const float* Wk = (const float*)d_in[4];
    const float* bk = (const float*)d_in[5];
    const float* Wv = (const float*)d_in[6];
    const float* bv = (const float*)d_in[7];
    const float* Wo = (const float*)d_in[8];
    const float* bo = (const float*)d_in[9];
    float* out = (float*)d_out;

    float *gqkv, *go, *gc, *gs, *gbqkv;
    cudaGetSymbolAddress((void**)&gqkv, g_qkv);
    cudaGetSymbolAddress((void**)&go, g_o);
    cudaGetSymbolAddress((void**)&gc, g_cos);
    cudaGetSymbolAddress((void**)&gs, g_sin);
    cudaGetSymbolAddress((void**)&gbqkv, g_bqkv);

    __nv_bfloat16 *xhi, *xlo, *ohi, *olo, *wqkvhi, *wqkvlo, *wohi, *wolo, *qkvhi, *qkvlo;
    cudaGetSymbolAddress((void**)&xhi, g_xhi);
    cudaGetSymbolAddress((void**)&xlo, g_xlo);
    cudaGetSymbolAddress((void**)&ohi, g_ohi);
    cudaGetSymbolAddress((void**)&olo, g_olo);
    cudaGetSymbolAddress((void**)&wqkvhi, g_wqkvhi);
    cudaGetSymbolAddress((void**)&wqkvlo, g_wqkvlo);
    cudaGetSymbolAddress((void**)&wohi, g_wohi);
    cudaGetSymbolAddress((void**)&wolo, g_wolo);
    cudaGetSymbolAddress((void**)&qkvhi, g_qkvhi);
    cudaGetSymbolAddress((void**)&qkvlo, g_qkvlo);

    const int M = BB * SS;  // 4096
    dim3 blk(256);

    rope_table_kernel<<<(SS * 32 + 255) / 256, 256>>>(gc, gs);

    int nx = M * DD;
    split_kernel<<<(nx + 255) / 256, 256>>>(x, xhi, xlo, nx);
    pack_wqkv_kernel<<<(DD * NQKV + 255) / 256, 256>>>(Wq, Wk, Wv, bq, bk, bv,
                                                       wqkvhi, wqkvlo, gbqkv);
    split_kernel<<<(DD * DD + 255) / 256, 256>>>(Wo, wohi, wolo, DD * DD);

    cudaFuncSetAttribute(gemm_bf16x3_v2, cudaFuncAttributeMaxDynamicSharedMemorySize,
                         GSM_TOTAL);

    // QKV = x @ Wqkv + bqkv
    gemm_bf16x3_v2<<<dim3(NQKV / 128, M / 128), blk, GSM_TOTAL>>>(
        xhi, xlo, wqkvhi, wqkvlo, gbqkv, gqkv, M, NQKV, 1024);

    int nrope = BB * SS * (HH + KHH) * 32;
    rope_apply_kernel<<<(nrope + 255) / 256, 256>>>(gqkv, gc, gs);

    // Split roped QKV to bf16 hi/lo
    int nqkv = M * NQKV;
    split_kernel<<<(nqkv + 255) / 256, 256>>>(gqkv, qkvhi, qkvlo, nqkv);

    cudaFuncSetAttribute(flash_tc_v2, cudaFuncAttributeMaxDynamicSharedMemorySize,
                         F2_SMEM_TOTAL);
    flash_tc_v2<<<dim3(SS / 64, KHH, BB), 512, F2_SMEM_TOTAL>>>(qkvhi, qkvlo, go);

    split_kernel<<<(nx + 255) / 256, 256>>>(go, ohi, olo, nx);
    gemm_bf16x3_v2<<<dim3(1024 / 128, M / 128), blk, GSM_TOTAL>>>(
        ohi, olo, wohi, wolo, bo, out, M, 1024, 1024);
}

// round 8
// speedup vs baseline: 1.4015x; 1.0034x over previous
#include <cuda_runtime.h>
#include <cuda_bf16.h>
#include <mma.h>
#include <math.h>
#include <cstdint>

using namespace nvcuda;

#define BB 2
#define SS 2048
#define DD 1024
#define HH 16
#define KHH 4
#define DKK 64
#define REP 4
#define NQKV 1536   // 1024 Q | 256 K | 256 V

// fp32 scratch
__device__ float g_qkv[BB * SS * NQKV];
__device__ float g_cos[SS * 32];
__device__ float g_sin[SS * 32];
__device__ float g_bqkv[NQKV];

// bf16 split scratch
__device__ __nv_bfloat16 g_xhi[BB * SS * DD],    g_xlo[BB * SS * DD];
__device__ __nv_bfloat16 g_ohi[BB * SS * DD],    g_olo[BB * SS * DD];
__device__ __nv_bfloat16 g_wqkvhi[DD * NQKV],    g_wqkvlo[DD * NQKV];
__device__ __nv_bfloat16 g_wohi[DD * DD],        g_wolo[DD * DD];
__device__ __nv_bfloat16 g_qkvhi[BB * SS * NQKV], g_qkvlo[BB * SS * NQKV];

// ---------------------------------------------------------------------------
// cp.async helpers
// ---------------------------------------------------------------------------
__device__ __forceinline__ void cp_async16(void* sptr, const void* gptr) {
    unsigned int s = (unsigned int)__cvta_generic_to_shared(sptr);
    asm volatile("cp.async.cg.shared.global [%0], [%1], 16;\n" :: "r"(s), "l"(gptr));
}
__device__ __forceinline__ void cp_commit() {
    asm volatile("cp.async.commit_group;\n");
}
__device__ __forceinline__ void cp_wait1() {
    asm volatile("cp.async.wait_group 1;\n");
}
__device__ __forceinline__ void cp_wait0() {
    asm volatile("cp.async.wait_group 0;\n");
}

// ---------------------------------------------------------------------------
// Split fp32 -> (bf16 hi, bf16 lo)
// ---------------------------------------------------------------------------
__global__ void split_kernel(const float* __restrict__ in,
                             __nv_bfloat16* __restrict__ hi,
                             __nv_bfloat16* __restrict__ lo, int n) {
    int i = blockIdx.x * blockDim.x + threadIdx.x;
    if (i >= n) return;
    float f = in[i];
    __nv_bfloat16 h = __float2bfloat16(f);
    hi[i] = h;
    lo[i] = __float2bfloat16(f - __bfloat162float(h));
}

// Pack Wq|Wk|Wv -> [1024][1536] hi/lo, and bq|bk|bv -> g_bqkv
__global__ void pack_wqkv_kernel(const float* __restrict__ Wq, const float* __restrict__ Wk,
                                 const float* __restrict__ Wv, const float* __restrict__ bq,
                                 const float* __restrict__ bk, const float* __restrict__ bv,
                                 __nv_bfloat16* __restrict__ hi, __nv_bfloat16* __restrict__ lo,
                                 float* __restrict__ bqkv) {
    int i = blockIdx.x * blockDim.x + threadIdx.x;
    int n = DD * NQKV;
    if (i < NQKV) {
        int c = i;
        bqkv[c] = (c < 1024) ? bq[c] : (c < 1280 ? bk[c - 1024] : bv[c - 1280]);
    }
    if (i >= n) return;
    int row = i / NQKV;
    int col = i % NQKV;
    float f;
    if (col < 1024)      f = Wq[row * 1024 + col];
    else if (col < 1280) f = Wk[row * 256 + col - 1024];
    else                 f = Wv[row * 256 + col - 1280];
    __nv_bfloat16 h = __float2bfloat16(f);
    hi[i] = h;
    lo[i] = __float2bfloat16(f - __bfloat162float(h));
}

// Final bias add: out[i] += b[i % 1024]
__global__ void bias_add_kernel(float* __restrict__ out, const float* __restrict__ b, int n) {
    int i = blockIdx.x * blockDim.x + threadIdx.x;
    if (i < n) out[i] += b[i & (DD - 1)];
}

// ---------------------------------------------------------------------------
// bf16x3 GEMM v3: C[M,N] = Ahi@Bhi + Ahi@Blo + Alo@Bhi  (NO bias)
// 128x128 block tile, BK=32, cp.async double-buffered, direct fragment
// stores to gmem. 256 thr = 8 warps (4m x 2n), warp tile 32x64.
// ---------------------------------------------------------------------------
#define GSM_A_BYTES (2 * 2 * 128 * 40 * 2)
#define GSM_B_BYTES (2 * 2 * 32 * 136 * 2)
#define GSM_TOTAL (GSM_A_BYTES + GSM_B_BYTES)

__device__ __forceinline__ int sA_idx(int buf, int part, int r, int c) {
    return ((buf * 2 + part) * 128 + r) * 40 + c;
}
__device__ __forceinline__ int sB_idx(int buf, int part, int r, int c) {
    return ((buf * 2 + part) * 32 + r) * 136 + c;
}

__global__ __launch_bounds__(256, 2)
void gemm_bf16x3_v3(const __nv_bfloat16* __restrict__ Ahi,
                    const __nv_bfloat16* __restrict__ Alo,
                    const __nv_bfloat16* __restrict__ Bhi,
                    const __nv_bfloat16* __restrict__ Blo,
                    float* __restrict__ C, int M, int N, int K) {
    extern __shared__ __align__(16) unsigned char smraw[];
    __nv_bfloat16* sA = (__nv_bfloat16*)smraw;
    __nv_bfloat16* sB = (__nv_bfloat16*)(smraw + GSM_A_BYTES);

    const int tid = threadIdx.x;
    const int warp = tid >> 5;
    const int m0 = blockIdx.y * 128;
    const int n0 = blockIdx.x * 128;
    const int wm = warp >> 1;
    const int wn = warp & 1;

    wmma::fragment<wmma::accumulator, 16, 16, 16, float> acc[2][4];
#pragma unroll
    for (int i = 0; i < 2; i++)
#pragma unroll
        for (int j = 0; j < 4; j++) wmma::fill_fragment(acc[i][j], 0.0f);

    const int nk = K / 32;

    auto load_stage = [&](int buf, int k0) {
#pragma unroll
        for (int c = tid; c < 512; c += 256) {
            int r = c >> 2;
            int cc = (c & 3) * 8;
            size_t g = (size_t)(m0 + r) * K + k0 + cc;
            cp_async16(&sA[sA_idx(buf, 0, r, cc)], &Ahi[g]);
            cp_async16(&sA[sA_idx(buf, 1, r, cc)], &Alo[g]);
        }
#pragma unroll
        for (int c = tid; c < 512; c += 256) {
            int r = c >> 4;
            int cc = (c & 15) * 8;
            size_t g = (size_t)(k0 + r) * N + n0 + cc;
            cp_async16(&sB[sB_idx(buf, 0, r, cc)], &Bhi[g]);
            cp_async16(&sB[sB_idx(buf, 1, r, cc)], &Blo[g]);
        }
        cp_commit();
    };

    load_stage(0, 0);

    for (int kt = 0; kt < nk; kt++) {
        int buf = kt & 1;
        if (kt + 1 < nk) {
            load_stage(buf ^ 1, (kt + 1) * 32);
            cp_wait1();
        } else {
            cp_wait0();
        }
        __syncthreads();

#pragma unroll
        for (int ks = 0; ks < 2; ks++) {
            wmma::fragment<wmma::matrix_a, 16, 16, 16, __nv_bfloat16, wmma::row_major> ahi[2], alo[2];
#pragma unroll
            for (int i = 0; i < 2; i++) {
                wmma::load_matrix_sync(ahi[i], &sA[sA_idx(buf, 0, wm * 32 + i * 16, ks * 16)], 40);
                wmma::load_matrix_sync(alo[i], &sA[sA_idx(buf, 1, wm * 32 + i * 16, ks * 16)], 40);
            }
#pragma unroll
            for (int j = 0; j < 4; j++) {
                wmma::fragment<wmma::matrix_b, 16, 16, 16, __nv_bfloat16, wmma::row_major> bhi, blo;
                wmma::load_matrix_sync(bhi, &sB[sB_idx(buf, 0, ks * 16, wn * 64 + j * 16)], 136);
                wmma::load_matrix_sync(blo, &sB[sB_idx(buf, 1, ks * 16, wn * 64 + j * 16)], 136);
#pragma unroll
                for (int i = 0; i < 2; i++) {
                    wmma::mma_sync(acc[i][j], ahi[i], bhi, acc[i][j]);
                    wmma::mma_sync(acc[i][j], ahi[i], blo, acc[i][j]);
                    wmma::mma_sync(acc[i][j], alo[i], bhi, acc[i][j]);
                }
            }
        }
        __syncthreads();
    }

    // Direct fragment stores to gmem
#pragma unroll
    for (int i = 0; i < 2; i++) {
#pragma unroll
        for (int j = 0; j < 4; j++) {
            int row0 = m0 + wm * 32 + i * 16;
            int col0 = n0 + wn * 64 + j * 16;
            wmma::store_matrix_sync(&C[(size_t)row0 * N + col0], acc[i][j], N,
                                    wmma::mem_row_major);
        }
    }
}

// ---------------------------------------------------------------------------
// RoPE table
// ---------------------------------------------------------------------------
__global__ void rope_table_kernel(float* __restrict__ ctab, float* __restrict__ stab) {
    int idx = blockIdx.x * blockDim.x + threadIdx.x;
    if (idx >= SS * 32) return;
    int s = idx >> 5;
    int d = idx & 31;
    double theta = pow(10000.0, -(double)d / 32.0);
    double f = (double)s * theta;
    ctab[idx] = (float)cos(f);
    stab[idx] = (float)sin(f);
}

// ---------------------------------------------------------------------------
// Fused bias + RoPE + bf16 hi/lo split over packed QKV.
// Region 1: roped pairs (Q 16 heads + K 4 heads, cols 0..1279), d<32.
// Region 2: V cols 1280..1535, bias + split only.
// ---------------------------------------------------------------------------
__global__ void rope_split_kernel(const float* __restrict__ qkv,
                                  const float* __restrict__ bias,
                                  const float* __restrict__ ctab,
                                  const float* __restrict__ stab,
                                  __nv_bfloat16* __restrict__ hi,
                                  __nv_bfloat16* __restrict__ lo) {
    const int NR = BB * SS * 20 * 32;   // roped pairs
    const int NV = BB * SS * 256;       // V elements
    int idx = blockIdx.x * blockDim.x + threadIdx.x;
    if (idx < NR) {
        int bs = idx / (20 * 32);
        int rem = idx % (20 * 32);
        int hd = rem >> 5;              // 0..19 (heads: 16 Q then 4 K)
        int d = rem & 31;
        int col = hd * 64 + d;
        int s = bs % SS;
        size_t base = (size_t)bs * NQKV + col;
        float x1 = qkv[base] + bias[col];
        float x2 = qkv[base + 32] + bias[col + 32];
        int t = s * 32 + d;
        float c = ctab[t];
        float sn = stab[t];
        float r1 = x1 * c - x2 * sn;
        float r2 = x2 * c + x1 * sn;
        __nv_bfloat16 h1 = __float2bfloat16(r1);
        __nv_bfloat16 h2 = __float2bfloat16(r2);
        hi[base] = h1;
        lo[base] = __float2bfloat16(r1 - __bfloat162float(h1));
        hi[base + 32] = h2;
        lo[base + 32] = __float2bfloat16(r2 - __bfloat162float(h2));
    } else if (idx < NR + NV) {
        int i2 = idx - NR;
        int bs = i2 >> 8;
        int col = 1280 + (i2 & 255);
        size_t base = (size_t)bs * NQKV + col;
        float f = qkv[base] + bias[col];
        __nv_bfloat16 h = __float2bfloat16(f);
        hi[base] = h;
        lo[base] = __float2bfloat16(f - __bfloat162float(h));
    }
}

// ---------------------------------------------------------------------------
// flash_tc_v2: GQA-grouped tensor-core flash attention.
// Block = (64 q-rows, kv-head, b). 512 threads = 16 warps. M = 256 (4 heads).
// Writes O as bf16 hi/lo directly.
// ---------------------------------------------------------------------------
#define F2_QHI 0
#define F2_QLO 36864
#define F2_KHI 73728
#define F2_KLO 82944
#define F2_VHI 92160
#define F2_VLO 101376
#define F2_SFP 110592
#define F2_PHI 110592
#define F2_PLO 147456
#define F2_M   184320
#define F2_L   185344
#define F2_AL  186368
#define F2_SMEM_TOTAL 187392

__global__ __launch_bounds__(512, 1)
void flash_tc_v2(const __nv_bfloat16* __restrict__ qh,
                 const __nv_bfloat16* __restrict__ ql,
                 __nv_bfloat16* __restrict__ ohi,
                 __nv_bfloat16* __restrict__ olo) {
    extern __shared__ __align__(16) unsigned char fsm[];
    __nv_bfloat16* Qhi = (__nv_bfloat16*)(fsm + F2_QHI);
    __nv_bfloat16* Qlo = (__nv_bfloat16*)(fsm + F2_QLO);
    __nv_bfloat16* Khi = (__nv_bfloat16*)(fsm + F2_KHI);
    __nv_bfloat16* Klo = (__nv_bfloat16*)(fsm + F2_KLO);
    __nv_bfloat16* Vhi = (__nv_bfloat16*)(fsm + F2_VHI);
    __nv_bfloat16* Vlo = (__nv_bfloat16*)(fsm + F2_VLO);
    float* Sf  = (float*)(fsm + F2_SFP);
    __nv_bfloat16* Phi = (__nv_bfloat16*)(fsm + F2_PHI);
    __nv_bfloat16* Plo = (__nv_bfloat16*)(fsm + F2_PLO);
    float* m_sh = (float*)(fsm + F2_M);
    float* l_sh = (float*)(fsm + F2_L);
    float* al_sh= (float*)(fsm + F2_AL);

    const int tid = threadIdx.x;
    const int warp = tid >> 5;
    const int qt = (int)gridDim.x - 1 - (int)blockIdx.x;   // long blocks first
    const int kh = blockIdx.y;
    const int b = blockIdx.z;
    const int s0q = qt * 64;
    const int m0w = warp * 16;

    __nv_bfloat16* kvdst[4] = {Khi, Klo, Vhi, Vlo};
    auto load_kv = [&](int s0k) {
        for (int t = tid; t < 2048; t += 512) {
            int arr = t >> 9;
            int r = (t >> 3) & 63;
            int ch = (t & 7) * 8;
            const __nv_bfloat16* src = (arr & 1) ? ql : qh;
            size_t g = (size_t)(b * SS + s0k + r) * NQKV + 1024 + kh * 64 +
                       ((arr >> 1) ? 256 : 0) + ch;
            cp_async16(&kvdst[arr][r * 72 + ch], &src[g]);
        }
        cp_commit();
    };

    load_kv(0);

    for (int t = tid; t < 4096; t += 512) {
        int part = t >> 11;
        int m = (t >> 3) & 255;
        int ch = (t & 7) * 8;
        int g_head = m >> 6;
        int rr = m & 63;
        const __nv_bfloat16* src = part ? ql : qh;
        size_t gaddr = (size_t)(b * SS + s0q + rr) * NQKV + (kh * 4 + g_head) * 64 + ch;
        __nv_bfloat16* dst = part ? Qlo : Qhi;
        *reinterpret_cast<uint4*>(&dst[m * 72 + ch]) =
            *reinterpret_cast<const uint4*>(&src[gaddr]);
    }
    if (tid < 256) { m_sh[tid] = -1e30f; l_sh[tid] = 0.0f; }

    const int srow = tid >> 1;
    const int sc0 = (tid & 1) * 32;
    const int srr = srow & 63;
    float ov[32];
#pragma unroll
    for (int i = 0; i < 32; i++) ov[i] = 0.0f;

    for (int kt = 0; kt <= qt; kt++) {
        const int s0k = kt * 64;
        cp_wait0();
        __syncthreads();

        // S = Q @ K^T
        {
            wmma::fragment<wmma::accumulator, 16, 16, 16, float> accs[4];
#pragma unroll
            for (int j = 0; j < 4; j++) wmma::fill_fragment(accs[j], 0.0f);
#pragma unroll
            for (int ks = 0; ks < 4; ks++) {
                wmma::fragment<wmma::matrix_a, 16, 16, 16, __nv_bfloat16, wmma::row_major> a_hi, a_lo;
                wmma::load_matrix_sync(a_hi, &Qhi[m0w * 72 + ks * 16], 72);
                wmma::load_matrix_sync(a_lo, &Qlo[m0w * 72 + ks * 16], 72);
#pragma unroll
                for (int j = 0; j < 4; j++) {
                    wmma::fragment<wmma::matrix_b, 16, 16, 16, __nv_bfloat16, wmma::col_major> b_hi, b_lo;
                    wmma::load_matrix_sync(b_hi, &Khi[(j * 16) * 72 + ks * 16], 72);
                    wmma::load_matrix_sync(b_lo, &Klo[(j * 16) * 72 + ks * 16], 72);
                    wmma::mma_sync(accs[j], a_hi, b_hi, accs[j]);
                    wmma::mma_sync(accs[j], a_hi, b_lo, accs[j]);
                    wmma::mma_sync(accs[j], a_lo, b_hi, accs[j]);
                }
            }
#pragma unroll
            for (int j = 0; j < 4; j++)
                wmma::store_matrix_sync(&Sf[m0w * 68 + j * 16], accs[j], 68, wmma::mem_row_major);
        }
        __syncthreads();

        // softmax
        float sv[32];
        {
            float vmax = -1e30f;
#pragma unroll
            for (int i = 0; i < 32; i++) {
                float s = Sf[srow * 68 + sc0 + i] * 0.125f;
                if (s0k + sc0 + i > s0q + srr) s = -1e30f;
                sv[i] = s;
                vmax = fmaxf(vmax, s);
            }
            vmax = fmaxf(vmax, __shfl_xor_sync(0xffffffffu, vmax, 1));
            float mo = m_sh[srow];
            float mx = fmaxf(mo, vmax);
            float al = __expf(mo - mx);
            __syncthreads();
            float sum = 0.0f;
#pragma unroll
            for (int i = 0; i < 32; i++) {
                float p = __expf(sv[i] - mx);
                sum += p;
                __nv_bfloat16 ph = __float2bfloat16(p);
                Phi[srow * 72 + sc0 + i] = ph;
                Plo[srow * 72 + sc0 + i] = __float2bfloat16(p - __bfloat162float(ph));
            }
            sum += __shfl_xor_sync(0xffffffffu, sum, 1);
            if ((tid & 1) == 0) {
                m_sh[srow] = mx;
                l_sh[srow] = l_sh[srow] * al + sum;
                al_sh[srow] = al;
            }
        }
        __syncthreads();

        // PV
        {
            wmma::fragment<wmma::accumulator, 16, 16, 16, float> acco[4];
#pragma unroll
            for (int j = 0; j < 4; j++) wmma::fill_fragment(acco[j], 0.0f);
#pragma unroll
            for (int ks = 0; ks < 4; ks++) {
                wmma::fragment<wmma::matrix_a, 16, 16, 16, __nv_bfloat16, wmma::row_major> p_hi, p_lo;
                wmma::load_matrix_sync(p_hi, &Phi[m0w * 72 + ks * 16], 72);
                wmma::load_matrix_sync(p_lo, &Plo[m0w * 72 + ks * 16], 72);
#pragma unroll
                for (int j = 0; j < 4; j++) {
                    wmma::fragment<wmma::matrix_b, 16, 16, 16, __nv_bfloat16, wmma::row_major> v_hi, v_lo;
                    wmma::load_matrix_sync(v_hi, &Vhi[(ks * 16) * 72 + j * 16], 72);
                    wmma::load_matrix_sync(v_lo, &Vlo[(ks * 16) * 72 + j * 16], 72);
                    wmma::mma_sync(acco[j], p_hi, v_hi, acco[j]);
                    wmma::mma_sync(acco[j], p_hi, v_lo, acco[j]);
                    wmma::mma_sync(acco[j], p_lo, v_hi, acco[j]);
                }
            }
            __syncthreads();

            if (kt < qt) load_kv(s0k + 64);

#pragma unroll
            for (int j = 0; j < 4; j++)
                wmma::store_matrix_sync(&Sf[m0w * 68 + j * 16], acco[j], 68, wmma::mem_row_major);
        }
        __syncthreads();

        {
            float al = al_sh[srow];
#pragma unroll
            for (int i = 0; i < 32; i++)
                ov[i] = ov[i] * al + Sf[srow * 68 + sc0 + i];
        }
    }

    float invl = 1.0f / l_sh[srow];
    int g_head = srow >> 6;
#pragma unroll
    for (int i = 0; i < 32; i++) {
        float f = ov[i] * invl;
        size_t oaddr = (size_t)(b * SS + s0q + srr) * DD + (kh * 4 + g_head) * 64 + sc0 + i;
        __nv_bfloat16 h = __float2bfloat16(f);
        ohi[oaddr] = h;
        olo[oaddr] = __float2bfloat16(f - __bfloat162float(h));
    }
}

// ---------------------------------------------------------------------------
// Launch
// ---------------------------------------------------------------------------
extern "C" void kernel_launch(void* const* d_in, const int* in_sizes, int n_in,
                              void* d_out, int out_size) {
    const float* x  = (const float*)d_in[0];
    const float* Wq = (const float*)d_in[2];
    const float* bq = (const float*)d_in[3];
    const float* Wk = (const float*)d_in[4];
    const float* bk = (const float*)d_in[5];
    const float* Wv = (const float*)d_in[6];
    const float* bv = (const float*)d_in[7];
    const float* Wo = (const float*)d_in[8];
    const float* bo = (const float*)d_in[9];
    float* out = (float*)d_out;

    float *gqkv, *gc, *gs, *gbqkv;
    cudaGetSymbolAddress((void**)&gqkv, g_qkv);
    cudaGetSymbolAddress((void**)&gc, g_cos);
    cudaGetSymbolAddress((void**)&gs, g_sin);
    cudaGetSymbolAddress((void**)&gbqkv, g_bqkv);

    __nv_bfloat16 *xhi, *xlo, *ohi, *olo, *wqkvhi, *wqkvlo, *wohi, *wolo, *qkvhi, *qkvlo;
    cudaGetSymbolAddress((void**)&xhi, g_xhi);
    cudaGetSymbolAddress((void**)&xlo, g_xlo);
    cudaGetSymbolAddress((void**)&ohi, g_ohi);
    cudaGetSymbolAddress((void**)&olo, g_olo);
    cudaGetSymbolAddress((void**)&wqkvhi, g_wqkvhi);
    cudaGetSymbolAddress((void**)&wqkvlo, g_wqkvlo);
    cudaGetSymbolAddress((void**)&wohi, g_wohi);
    cudaGetSymbolAddress((void**)&wolo, g_wolo);
    cudaGetSymbolAddress((void**)&qkvhi, g_qkvhi);
    cudaGetSymbolAddress((void**)&qkvlo, g_qkvlo);

    const int M = BB * SS;  // 4096
    dim3 blk(256);

    rope_table_kernel<<<(SS * 32 + 255) / 256, 256>>>(gc, gs);

    int nx = M * DD;
    split_kernel<<<(nx + 255) / 256, 256>>>(x, xhi, xlo, nx);
    pack_wqkv_kernel<<<(DD * NQKV + 255) / 256, 256>>>(Wq, Wk, Wv, bq, bk, bv,
                                                       wqkvhi, wqkvlo, gbqkv);
    split_kernel<<<(DD * DD + 255) / 256, 256>>>(Wo, wohi, wolo, DD * DD);

    cudaFuncSetAttribute(gemm_bf16x3_v3, cudaFuncAttributeMaxDynamicSharedMemorySize,
                         GSM_TOTAL);

    // QKV = x @ Wqkv (bias deferred to rope_split)
    gemm_bf16x3_v3<<<dim3(NQKV / 128, M / 128), blk, GSM_TOTAL>>>(
        xhi, xlo, wqkvhi, wqkvlo, gqkv, M, NQKV, 1024);

    // Fused bias + RoPE + split -> bf16 hi/lo
    int nrs = BB * SS * 20 * 32 + BB * SS * 256;
    rope_split_kernel<<<(nrs + 255) / 256, 256>>>(gqkv, gbqkv, gc, gs, qkvhi, qkvlo);

    cudaFuncSetAttribute(flash_tc_v2, cudaFuncAttributeMaxDynamicSharedMemorySize,
                         F2_SMEM_TOTAL);
    flash_tc_v2<<<dim3(SS / 64, KHH, BB), 512, F2_SMEM_TOTAL>>>(qkvhi, qkvlo, ohi, olo);

    // out = attn_out @ Wo (bias added after)
    gemm_bf16x3_v3<<<dim3(1024 / 128, M / 128), blk, GSM_TOTAL>>>(
        ohi, olo, wohi, wolo, out, M, 1024, 1024);
    bias_add_kernel<<<(nx + 255) / 256, 256>>>(out, bo, nx);
}

// round 10
// speedup vs baseline: 1.4763x; 1.0534x over previous
#include <cuda_runtime.h>
#include <cuda_bf16.h>
#include <mma.h>
#include <math.h>
#include <cstdint>

using namespace nvcuda;

#define BB 2
#define SS 2048
#define DD 1024
#define HH 16
#define KHH 4
#define DKK 64
#define REP 4
#define NQKV 1536   // 1024 Q | 256 K | 256 V

// fp32 scratch
__device__ float g_qkv[BB * SS * NQKV];
__device__ float g_cos[SS * 32];
__device__ float g_sin[SS * 32];
__device__ float g_bqkv[NQKV];

// bf16 split scratch
__device__ __nv_bfloat16 g_xhi[BB * SS * DD],    g_xlo[BB * SS * DD];
__device__ __nv_bfloat16 g_ohi[BB * SS * DD],    g_olo[BB * SS * DD];
__device__ __nv_bfloat16 g_wqkvhi[DD * NQKV],    g_wqkvlo[DD * NQKV];
__device__ __nv_bfloat16 g_wohi[DD * DD],        g_wolo[DD * DD];
__device__ __nv_bfloat16 g_qkvhi[BB * SS * NQKV], g_qkvlo[BB * SS * NQKV];

// ---------------------------------------------------------------------------
// cp.async helpers
// ---------------------------------------------------------------------------
__device__ __forceinline__ void cp_async16(void* sptr, const void* gptr) {
    unsigned int s = (unsigned int)__cvta_generic_to_shared(sptr);
    asm volatile("cp.async.cg.shared.global [%0], [%1], 16;\n" :: "r"(s), "l"(gptr));
}
__device__ __forceinline__ void cp_commit() { asm volatile("cp.async.commit_group;\n"); }
__device__ __forceinline__ void cp_wait1() { asm volatile("cp.async.wait_group 1;\n"); }
__device__ __forceinline__ void cp_wait0() { asm volatile("cp.async.wait_group 0;\n"); }

// ---------------------------------------------------------------------------
// Small kernels
// ---------------------------------------------------------------------------
__global__ void split_kernel(const float* __restrict__ in,
                             __nv_bfloat16* __restrict__ hi,
                             __nv_bfloat16* __restrict__ lo, int n) {
    int i = blockIdx.x * blockDim.x + threadIdx.x;
    if (i >= n) return;
    float f = in[i];
    __nv_bfloat16 h = __float2bfloat16(f);
    hi[i] = h;
    lo[i] = __float2bfloat16(f - __bfloat162float(h));
}

__global__ void pack_wqkv_kernel(const float* __restrict__ Wq, const float* __restrict__ Wk,
                                 const float* __restrict__ Wv, const float* __restrict__ bq,
                                 const float* __restrict__ bk, const float* __restrict__ bv,
                                 __nv_bfloat16* __restrict__ hi, __nv_bfloat16* __restrict__ lo,
                                 float* __restrict__ bqkv) {
    int i = blockIdx.x * blockDim.x + threadIdx.x;
    int n = DD * NQKV;
    if (i < NQKV) {
        int c = i;
        bqkv[c] = (c < 1024) ? bq[c] : (c < 1280 ? bk[c - 1024] : bv[c - 1280]);
    }
    if (i >= n) return;
    int row = i / NQKV;
    int col = i % NQKV;
    float f;
    if (col < 1024)      f = Wq[row * 1024 + col];
    else if (col < 1280) f = Wk[row * 256 + col - 1024];
    else                 f = Wv[row * 256 + col - 1280];
    __nv_bfloat16 h = __float2bfloat16(f);
    hi[i] = h;
    lo[i] = __float2bfloat16(f - __bfloat162float(h));
}

__global__ void bias_add_kernel(float* __restrict__ out, const float* __restrict__ b, int n) {
    int i = blockIdx.x * blockDim.x + threadIdx.x;
    if (i < n) out[i] += b[i & (DD - 1)];
}

__global__ void rope_table_kernel(float* __restrict__ ctab, float* __restrict__ stab) {
    int idx = blockIdx.x * blockDim.x + threadIdx.x;
    if (idx >= SS * 32) return;
    int s = idx >> 5;
    int d = idx & 31;
    double theta = pow(10000.0, -(double)d / 32.0);
    double f = (double)s * theta;
    ctab[idx] = (float)cos(f);
    stab[idx] = (float)sin(f);
}

__global__ void rope_split_kernel(const float* __restrict__ qkv,
                                  const float* __restrict__ bias,
                                  const float* __restrict__ ctab,
                                  const float* __restrict__ stab,
                                  __nv_bfloat16* __restrict__ hi,
                                  __nv_bfloat16* __restrict__ lo) {
    const int NR = BB * SS * 20 * 32;
    const int NV = BB * SS * 256;
    int idx = blockIdx.x * blockDim.x + threadIdx.x;
    if (idx < NR) {
        int bs = idx / (20 * 32);
        int rem = idx % (20 * 32);
        int hd = rem >> 5;
        int d = rem & 31;
        int col = hd * 64 + d;
        int s = bs % SS;
        size_t base = (size_t)bs * NQKV + col;
        float x1 = qkv[base] + bias[col];
        float x2 = qkv[base + 32] + bias[col + 32];
        int t = s * 32 + d;
        float c = ctab[t];
        float sn = stab[t];
        float r1 = x1 * c - x2 * sn;
        float r2 = x2 * c + x1 * sn;
        __nv_bfloat16 h1 = __float2bfloat16(r1);
        __nv_bfloat16 h2 = __float2bfloat16(r2);
        hi[base] = h1;
        lo[base] = __float2bfloat16(r1 - __bfloat162float(h1));
        hi[base + 32] = h2;
        lo[base + 32] = __float2bfloat16(r2 - __bfloat162float(h2));
    } else if (idx < NR + NV) {
        int i2 = idx - NR;
        int bs = i2 >> 8;
        int col = 1280 + (i2 & 255);
        size_t base = (size_t)bs * NQKV + col;
        float f = qkv[base] + bias[col];
        __nv_bfloat16 h = __float2bfloat16(f);
        hi[base] = h;
        lo[base] = __float2bfloat16(f - __bfloat162float(h));
    }
}

// ---------------------------------------------------------------------------
// bf16x3 GEMM v3 (wmma; known-good from R8)
// ---------------------------------------------------------------------------
#define GSM_A_BYTES (2 * 2 * 128 * 40 * 2)
#define GSM_B_BYTES (2 * 2 * 32 * 136 * 2)
#define GSM_TOTAL (GSM_A_BYTES + GSM_B_BYTES)

__device__ __forceinline__ int sA_idx(int buf, int part, int r, int c) {
    return ((buf * 2 + part) * 128 + r) * 40 + c;
}
__device__ __forceinline__ int sB_idx(int buf, int part, int r, int c) {
    return ((buf * 2 + part) * 32 + r) * 136 + c;
}

__global__ __launch_bounds__(256, 2)
void gemm_bf16x3_v3(const __nv_bfloat16* __restrict__ Ahi,
                    const __nv_bfloat16* __restrict__ Alo,
                    const __nv_bfloat16* __restrict__ Bhi,
                    const __nv_bfloat16* __restrict__ Blo,
                    float* __restrict__ C, int M, int N, int K) {
    extern __shared__ __align__(16) unsigned char smraw[];
    __nv_bfloat16* sA = (__nv_bfloat16*)smraw;
    __nv_bfloat16* sB = (__nv_bfloat16*)(smraw + GSM_A_BYTES);

    const int tid = threadIdx.x;
    const int warp = tid >> 5;
    const int m0 = blockIdx.y * 128;
    const int n0 = blockIdx.x * 128;
    const int wm = warp >> 1;
    const int wn = warp & 1;

    wmma::fragment<wmma::accumulator, 16, 16, 16, float> acc[2][4];
#pragma unroll
    for (int i = 0; i < 2; i++)
#pragma unroll
        for (int j = 0; j < 4; j++) wmma::fill_fragment(acc[i][j], 0.0f);

    const int nk = K / 32;

    auto load_stage = [&](int buf, int k0) {
#pragma unroll
        for (int c = tid; c < 512; c += 256) {
            int r = c >> 2;
            int cc = (c & 3) * 8;
            size_t g = (size_t)(m0 + r) * K + k0 + cc;
            cp_async16(&sA[sA_idx(buf, 0, r, cc)], &Ahi[g]);
            cp_async16(&sA[sA_idx(buf, 1, r, cc)], &Alo[g]);
        }
#pragma unroll
        for (int c = tid; c < 512; c += 256) {
            int r = c >> 4;
            int cc = (c & 15) * 8;
            size_t g = (size_t)(k0 + r) * N + n0 + cc;
            cp_async16(&sB[sB_idx(buf, 0, r, cc)], &Bhi[g]);
            cp_async16(&sB[sB_idx(buf, 1, r, cc)], &Blo[g]);
        }
        cp_commit();
    };

    load_stage(0, 0);

    for (int kt = 0; kt < nk; kt++) {
        int buf = kt & 1;
        if (kt + 1 < nk) {
            load_stage(buf ^ 1, (kt + 1) * 32);
            cp_wait1();
        } else {
            cp_wait0();
        }
        __syncthreads();

#pragma unroll
        for (int ks = 0; ks < 2; ks++) {
            wmma::fragment<wmma::matrix_a, 16, 16, 16, __nv_bfloat16, wmma::row_major> ahi[2], alo[2];
#pragma unroll
            for (int i = 0; i < 2; i++) {
                wmma::load_matrix_sync(ahi[i], &sA[sA_idx(buf, 0, wm * 32 + i * 16, ks * 16)], 40);
                wmma::load_matrix_sync(alo[i], &sA[sA_idx(buf, 1, wm * 32 + i * 16, ks * 16)], 40);
            }
#pragma unroll
            for (int j = 0; j < 4; j++) {
                wmma::fragment<wmma::matrix_b, 16, 16, 16, __nv_bfloat16, wmma::row_major> bhi, blo;
                wmma::load_matrix_sync(bhi, &sB[sB_idx(buf, 0, ks * 16, wn * 64 + j * 16)], 136);
                wmma::load_matrix_sync(blo, &sB[sB_idx(buf, 1, ks * 16, wn * 64 + j * 16)], 136);
#pragma unroll
                for (int i = 0; i < 2; i++) {
                    wmma::mma_sync(acc[i][j], ahi[i], bhi, acc[i][j]);
                    wmma::mma_sync(acc[i][j], ahi[i], blo, acc[i][j]);
                    wmma::mma_sync(acc[i][j], alo[i], bhi, acc[i][j]);
                }
            }
        }
        __syncthreads();
    }

#pragma unroll
    for (int i = 0; i < 2; i++) {
#pragma unroll
        for (int j = 0; j < 4; j++) {
            int row0 = m0 + wm * 32 + i * 16;
            int col0 = n0 + wn * 64 + j * 16;
            wmma::store_matrix_sync(&C[(size_t)row0 * N + col0], acc[i][j], N,
                                    wmma::mem_row_major);
        }
    }
}

// ---------------------------------------------------------------------------
// flash_tc_v3: GQA tensor-core flash, M=128 (2 Q-heads), 256 threads/8 warps.
// smem 109.5KB -> 2 CTAs/SM for cross-CTA latency hiding.
// ---------------------------------------------------------------------------
#define F3_QHI 0
#define F3_QLO 18432
#define F3_KHI 36864
#define F3_KLO 46080
#define F3_VHI 55296
#define F3_VLO 64512
#define F3_SFP 73728            // Sf f32 (128x68) / P hi|lo union
#define F3_PHI 73728
#define F3_PLO 92160
#define F3_M   110592
#define F3_L   111104
#define F3_AL  111616
#define F3_SMEM_TOTAL 112128

__global__ __launch_bounds__(256, 2)
void flash_tc_v3(const __nv_bfloat16* __restrict__ qh,
                 const __nv_bfloat16* __restrict__ ql,
                 __nv_bfloat16* __restrict__ ohi,
                 __nv_bfloat16* __restrict__ olo) {
    extern __shared__ __align__(16) unsigned char fsm[];
    __nv_bfloat16* Qhi = (__nv_bfloat16*)(fsm + F3_QHI);
    __nv_bfloat16* Qlo = (__nv_bfloat16*)(fsm + F3_QLO);
    __nv_bfloat16* Khi = (__nv_bfloat16*)(fsm + F3_KHI);
    __nv_bfloat16* Klo = (__nv_bfloat16*)(fsm + F3_KLO);
    __nv_bfloat16* Vhi = (__nv_bfloat16*)(fsm + F3_VHI);
    __nv_bfloat16* Vlo = (__nv_bfloat16*)(fsm + F3_VLO);
    float* Sf  = (float*)(fsm + F3_SFP);
    __nv_bfloat16* Phi = (__nv_bfloat16*)(fsm + F3_PHI);
    __nv_bfloat16* Plo = (__nv_bfloat16*)(fsm + F3_PLO);
    float* m_sh = (float*)(fsm + F3_M);
    float* l_sh = (float*)(fsm + F3_L);
    float* al_sh= (float*)(fsm + F3_AL);

    const int tid = threadIdx.x;
    const int warp = tid >> 5;
    const int qt = (int)gridDim.x - 1 - (int)blockIdx.x;   // long blocks first
    const int kh = blockIdx.y >> 1;
    const int pair = blockIdx.y & 1;                       // head pair within group
    const int b = blockIdx.z;
    const int s0q = qt * 64;
    const int m0w = warp * 16;          // 0..112

    __nv_bfloat16* kvdst[4] = {Khi, Klo, Vhi, Vlo};
    auto load_kv = [&](int s0k) {
        for (int t = tid; t < 2048; t += 256) {
            int arr = t >> 9;
            int r = (t >> 3) & 63;
            int ch = (t & 7) * 8;
            const __nv_bfloat16* src = (arr & 1) ? ql : qh;
            size_t g = (size_t)(b * SS + s0k + r) * NQKV + 1024 + kh * 64 +
                       ((arr >> 1) ? 256 : 0) + ch;
            cp_async16(&kvdst[arr][r * 72 + ch], &src[g]);
        }
        cp_commit();
    };

    load_kv(0);

    // Q for 2 heads: m = head_in_pair*64 + rr
    for (int t = tid; t < 2048; t += 256) {
        int part = t >> 10;
        int m = (t >> 3) & 127;
        int ch = (t & 7) * 8;
        int hp = m >> 6;                // 0..1
        int rr = m & 63;
        const __nv_bfloat16* src = part ? ql : qh;
        size_t gaddr = (size_t)(b * SS + s0q + rr) * NQKV +
                       (kh * 4 + pair * 2 + hp) * 64 + ch;
        __nv_bfloat16* dst = part ? Qlo : Qhi;
        *reinterpret_cast<uint4*>(&dst[m * 72 + ch]) =
            *reinterpret_cast<const uint4*>(&src[gaddr]);
    }
    if (tid < 128) { m_sh[tid] = -1e30f; l_sh[tid] = 0.0f; }

    const int srow = tid >> 1;          // 0..127
    const int sc0 = (tid & 1) * 32;
    const int srr = srow & 63;
    float ov[32];
#pragma unroll
    for (int i = 0; i < 32; i++) ov[i] = 0.0f;

    for (int kt = 0; kt <= qt; kt++) {
        const int s0k = kt * 64;
        cp_wait0();
        __syncthreads();

        // S = Q @ K^T
        {
            wmma::fragment<wmma::accumulator, 16, 16, 16, float> accs[4];
#pragma unroll
            for (int j = 0; j < 4; j++) wmma::fill_fragment(accs[j], 0.0f);
#pragma unroll
            for (int ks = 0; ks < 4; ks++) {
                wmma::fragment<wmma::matrix_a, 16, 16, 16, __nv_bfloat16, wmma::row_major> a_hi, a_lo;
                wmma::load_matrix_sync(a_hi, &Qhi[m0w * 72 + ks * 16], 72);
                wmma::load_matrix_sync(a_lo, &Qlo[m0w * 72 + ks * 16], 72);
#pragma unroll
                for (int j = 0; j < 4; j++) {
                    wmma::fragment<wmma::matrix_b, 16, 16, 16, __nv_bfloat16, wmma::col_major> b_hi, b_lo;
                    wmma::load_matrix_sync(b_hi, &Khi[(j * 16) * 72 + ks * 16], 72);
                    wmma::load_matrix_sync(b_lo, &Klo[(j * 16) * 72 + ks * 16], 72);
                    wmma::mma_sync(accs[j], a_hi, b_hi, accs[j]);
                    wmma::mma_sync(accs[j], a_hi, b_lo, accs[j]);
                    wmma::mma_sync(accs[j], a_lo, b_hi, accs[j]);
                }
            }
#pragma unroll
            for (int j = 0; j < 4; j++)
                wmma::store_matrix_sync(&Sf[m0w * 68 + j * 16], accs[j], 68, wmma::mem_row_major);
        }
        __syncthreads();

        // softmax (2 threads per row), register-staged (Sf/P alias)
        float sv[32];
        {
            float vmax = -1e30f;
#pragma unroll
            for (int i = 0; i < 32; i++) {
                float s = Sf[srow * 68 + sc0 + i] * 0.125f;
                if (s0k + sc0 + i > s0q + srr) s = -1e30f;
                sv[i] = s;
                vmax = fmaxf(vmax, s);
            }
            vmax = fmaxf(vmax, __shfl_xor_sync(0xffffffffu, vmax, 1));
            float mo = m_sh[srow];
            float mx = fmaxf(mo, vmax);
            float al = __expf(mo - mx);
            __syncthreads();            // all Sf reads done before P overwrite
            float sum = 0.0f;
#pragma unroll
            for (int i = 0; i < 32; i++) {
                float p = __expf(sv[i] - mx);
                sum += p;
                __nv_bfloat16 ph = __float2bfloat16(p);
                Phi[srow * 72 + sc0 + i] = ph;
                Plo[srow * 72 + sc0 + i] = __float2bfloat16(p - __bfloat162float(ph));
            }
            sum += __shfl_xor_sync(0xffffffffu, sum, 1);
            if ((tid & 1) == 0) {
                m_sh[srow] = mx;
                l_sh[srow] = l_sh[srow] * al + sum;
                al_sh[srow] = al;
            }
        }
        __syncthreads();

        // PV
        {
            wmma::fragment<wmma::accumulator, 16, 16, 16, float> acco[4];
#pragma unroll
            for (int j = 0; j < 4; j++) wmma::fill_fragment(acco[j], 0.0f);
#pragma unroll
            for (int ks = 0; ks < 4; ks++) {
                wmma::fragment<wmma::matrix_a, 16, 16, 16, __nv_bfloat16, wmma::row_major> p_hi, p_lo;
                wmma::load_matrix_sync(p_hi, &Phi[m0w * 72 + ks * 16], 72);
                wmma::load_matrix_sync(p_lo, &Plo[m0w * 72 + ks * 16], 72);
#pragma unroll
                for (int j = 0; j < 4; j++) {
                    wmma::fragment<wmma::matrix_b, 16, 16, 16, __nv_bfloat16, wmma::row_major> v_hi, v_lo;
                    wmma::load_matrix_sync(v_hi, &Vhi[(ks * 16) * 72 + j * 16], 72);
                    wmma::load_matrix_sync(v_lo, &Vlo[(ks * 16) * 72 + j * 16], 72);
                    wmma::mma_sync(acco[j], p_hi, v_hi, acco[j]);
                    wmma::mma_sync(acco[j], p_hi, v_lo, acco[j]);
                    wmma::mma_sync(acco[j], p_lo, v_hi, acco[j]);
                }
            }
            __syncthreads();            // P/V reads done; KV & SfP reusable

            if (kt < qt) load_kv(s0k + 64);   // prefetch overlaps O update

#pragma unroll
            for (int j = 0; j < 4; j++)
                wmma::store_matrix_sync(&Sf[m0w * 68 + j * 16], acco[j], 68, wmma::mem_row_major);
        }
        __syncthreads();

        {
            float al = al_sh[srow];
#pragma unroll
            for (int i = 0; i < 32; i++)
                ov[i] = ov[i] * al + Sf[srow * 68 + sc0 + i];
        }
    }

    float invl = 1.0f / l_sh[srow];
    int hp = srow >> 6;
#pragma unroll
    for (int i = 0; i < 32; i++) {
        float f = ov[i] * invl;
        size_t oaddr = (size_t)(b * SS + s0q + srr) * DD +
                       (kh * 4 + pair * 2 + hp) * 64 + sc0 + i;
        __nv_bfloat16 h = __float2bfloat16(f);
        ohi[oaddr] = h;
        olo[oaddr] = __float2bfloat16(f - __bfloat162float(h));
    }
}

// ---------------------------------------------------------------------------
// Launch
// ---------------------------------------------------------------------------
extern "C" void kernel_launch(void* const* d_in, const int* in_sizes, int n_in,
                              void* d_out, int out_size) {
    const float* x  = (const float*)d_in[0];
    const float* Wq = (const float*)d_in[2];
    const float* bq = (const float*)d_in[3];
    const float* Wk = (const float*)d_in[4];
    const float* bk = (const float*)d_in[5];
    const float* Wv = (const float*)d_in[6];
    const float* bv = (const float*)d_in[7];
    const float* Wo = (const float*)d_in[8];
    const float* bo = (const float*)d_in[9];
    float* out = (float*)d_out;

    float *gqkv, *gc, *gs, *gbqkv;
    cudaGetSymbolAddress((void**)&gqkv, g_qkv);
    cudaGetSymbolAddress((void**)&gc, g_cos);
    cudaGetSymbolAddress((void**)&gs, g_sin);
    cudaGetSymbolAddress((void**)&gbqkv, g_bqkv);

    __nv_bfloat16 *xhi, *xlo, *ohi, *olo, *wqkvhi, *wqkvlo, *wohi, *wolo, *qkvhi, *qkvlo;
    cudaGetSymbolAddress((void**)&xhi, g_xhi);
    cudaGetSymbolAddress((void**)&xlo, g_xlo);
    cudaGetSymbolAddress((void**)&ohi, g_ohi);
    cudaGetSymbolAddress((void**)&olo, g_olo);
    cudaGetSymbolAddress((void**)&wqkvhi, g_wqkvhi);
    cudaGetSymbolAddress((void**)&wqkvlo, g_wqkvlo);
    cudaGetSymbolAddress((void**)&wohi, g_wohi);
    cudaGetSymbolAddress((void**)&wolo, g_wolo);
    cudaGetSymbolAddress((void**)&qkvhi, g_qkvhi);
    cudaGetSymbolAddress((void**)&qkvlo, g_qkvlo);

    const int M = BB * SS;  // 4096
    dim3 blk(256);

    rope_table_kernel<<<(SS * 32 + 255) / 256, 256>>>(gc, gs);

    int nx = M * DD;
    split_kernel<<<(nx + 255) / 256, 256>>>(x, xhi, xlo, nx);
    pack_wqkv_kernel<<<(DD * NQKV + 255) / 256, 256>>>(Wq, Wk, Wv, bq, bk, bv,
                                                       wqkvhi, wqkvlo, gbqkv);
    split_kernel<<<(DD * DD + 255) / 256, 256>>>(Wo, wohi, wolo, DD * DD);

    cudaFuncSetAttribute(gemm_bf16x3_v3, cudaFuncAttributeMaxDynamicSharedMemorySize,
                         GSM_TOTAL);

    // QKV = x @ Wqkv (bias deferred to rope_split)
    gemm_bf16x3_v3<<<dim3(NQKV / 128, M / 128), blk, GSM_TOTAL>>>(
        xhi, xlo, wqkvhi, wqkvlo, gqkv, M, NQKV, 1024);

    // Fused bias + RoPE + split
    int nrs = BB * SS * 20 * 32 + BB * SS * 256;
    rope_split_kernel<<<(nrs + 255) / 256, 256>>>(gqkv, gbqkv, gc, gs, qkvhi, qkvlo);

    cudaFuncSetAttribute(flash_tc_v3, cudaFuncAttributeMaxDynamicSharedMemorySize,
                         F3_SMEM_TOTAL);
    flash_tc_v3<<<dim3(SS / 64, KHH * 2, BB), 256, F3_SMEM_TOTAL>>>(qkvhi, qkvlo, ohi, olo);

    // out = attn_out @ Wo, then bias
    gemm_bf16x3_v3<<<dim3(1024 / 128, M / 128), blk, GSM_TOTAL>>>(
        ohi, olo, wohi, wolo, out, M, 1024, 1024);
    bias_add_kernel<<<(nx + 255) / 256, 256>>>(out, bo, nx);
}

// round 11
// speedup vs baseline: 1.5166x; 1.0273x over previous
#include <cuda_runtime.h>
#include <cuda_bf16.h>
#include <mma.h>
#include <math.h>
#include <cstdint>

using namespace nvcuda;

#define BB 2
#define SS 2048
#define DD 1024
#define HH 16
#define KHH 4
#define DKK 64
#define REP 4
#define NQKV 1536   // 1024 Q | 256 K | 256 V

// fp32 scratch
__device__ float g_qkv[BB * SS * NQKV];
__device__ float g_cos[SS * 32];
__device__ float g_sin[SS * 32];
__device__ float g_bqkv[NQKV];

// bf16 split scratch
__device__ __nv_bfloat16 g_xhi[BB * SS * DD],    g_xlo[BB * SS * DD];
__device__ __nv_bfloat16 g_ohi[BB * SS * DD],    g_olo[BB * SS * DD];
__device__ __nv_bfloat16 g_wqkvhi[DD * NQKV],    g_wqkvlo[DD * NQKV];
__device__ __nv_bfloat16 g_wohi[DD * DD],        g_wolo[DD * DD];
__device__ __nv_bfloat16 g_qkvhi[BB * SS * NQKV], g_qkvlo[BB * SS * NQKV];

// ---------------------------------------------------------------------------
// cp.async helpers
// ---------------------------------------------------------------------------
__device__ __forceinline__ void cp_async16(void* sptr, const void* gptr) {
    unsigned int s = (unsigned int)__cvta_generic_to_shared(sptr);
    asm volatile("cp.async.cg.shared.global [%0], [%1], 16;\n" :: "r"(s), "l"(gptr));
}
__device__ __forceinline__ void cp_commit() { asm volatile("cp.async.commit_group;\n"); }
__device__ __forceinline__ void cp_wait1() { asm volatile("cp.async.wait_group 1;\n"); }
__device__ __forceinline__ void cp_wait0() { asm volatile("cp.async.wait_group 0;\n"); }

// ---------------------------------------------------------------------------
// Small kernels
// ---------------------------------------------------------------------------
__global__ void split_kernel(const float* __restrict__ in,
                             __nv_bfloat16* __restrict__ hi,
                             __nv_bfloat16* __restrict__ lo, int n) {
    int i = blockIdx.x * blockDim.x + threadIdx.x;
    if (i >= n) return;
    float f = in[i];
    __nv_bfloat16 h = __float2bfloat16(f);
    hi[i] = h;
    lo[i] = __float2bfloat16(f - __bfloat162float(h));
}

__global__ void pack_wqkv_kernel(const float* __restrict__ Wq, const float* __restrict__ Wk,
                                 const float* __restrict__ Wv, const float* __restrict__ bq,
                                 const float* __restrict__ bk, const float* __restrict__ bv,
                                 __nv_bfloat16* __restrict__ hi, __nv_bfloat16* __restrict__ lo,
                                 float* __restrict__ bqkv) {
    int i = blockIdx.x * blockDim.x + threadIdx.x;
    int n = DD * NQKV;
    if (i < NQKV) {
        int c = i;
        bqkv[c] = (c < 1024) ? bq[c] : (c < 1280 ? bk[c - 1024] : bv[c - 1280]);
    }
    if (i >= n) return;
    int row = i / NQKV;
    int col = i % NQKV;
    float f;
    if (col < 1024)      f = Wq[row * 1024 + col];
    else if (col < 1280) f = Wk[row * 256 + col - 1024];
    else                 f = Wv[row * 256 + col - 1280];
    __nv_bfloat16 h = __float2bfloat16(f);
    hi[i] = h;
    lo[i] = __float2bfloat16(f - __bfloat162float(h));
}

__global__ void bias_add_kernel(float* __restrict__ out, const float* __restrict__ b, int n) {
    int i = blockIdx.x * blockDim.x + threadIdx.x;
    if (i < n) out[i] += b[i & (DD - 1)];
}

__global__ void rope_table_kernel(float* __restrict__ ctab, float* __restrict__ stab) {
    int idx = blockIdx.x * blockDim.x + threadIdx.x;
    if (idx >= SS * 32) return;
    int s = idx >> 5;
    int d = idx & 31;
    double theta = pow(10000.0, -(double)d / 32.0);
    double f = (double)s * theta;
    ctab[idx] = (float)cos(f);
    stab[idx] = (float)sin(f);
}

__global__ void rope_split_kernel(const float* __restrict__ qkv,
                                  const float* __restrict__ bias,
                                  const float* __restrict__ ctab,
                                  const float* __restrict__ stab,
                                  __nv_bfloat16* __restrict__ hi,
                                  __nv_bfloat16* __restrict__ lo) {
    const int NR = BB * SS * 20 * 32;
    const int NV = BB * SS * 256;
    int idx = blockIdx.x * blockDim.x + threadIdx.x;
    if (idx < NR) {
        int bs = idx / (20 * 32);
        int rem = idx % (20 * 32);
        int hd = rem >> 5;
        int d = rem & 31;
        int col = hd * 64 + d;
        int s = bs % SS;
        size_t base = (size_t)bs * NQKV + col;
        float x1 = qkv[base] + bias[col];
        float x2 = qkv[base + 32] + bias[col + 32];
        int t = s * 32 + d;
        float c = ctab[t];
        float sn = stab[t];
        float r1 = x1 * c - x2 * sn;
        float r2 = x2 * c + x1 * sn;
        __nv_bfloat16 h1 = __float2bfloat16(r1);
        __nv_bfloat16 h2 = __float2bfloat16(r2);
        hi[base] = h1;
        lo[base] = __float2bfloat16(r1 - __bfloat162float(h1));
        hi[base + 32] = h2;
        lo[base + 32] = __float2bfloat16(r2 - __bfloat162float(h2));
    } else if (idx < NR + NV) {
        int i2 = idx - NR;
        int bs = i2 >> 8;
        int col = 1280 + (i2 & 255);
        size_t base = (size_t)bs * NQKV + col;
        float f = qkv[base] + bias[col];
        __nv_bfloat16 h = __float2bfloat16(f);
        hi[base] = h;
        lo[base] = __float2bfloat16(f - __bfloat162float(h));
    }
}

// ---------------------------------------------------------------------------
// bf16x3 GEMM v4: 128x128 block, 128 threads = 4 warps (2m x 2n),
// warp tile 64x64 = 4x4 wmma accumulators -> 4x fragment reuse, -33% LDS/mma.
// BK=32 double-buffered cp.async. 2 CTAs/SM.
// ---------------------------------------------------------------------------
#define GSM_A_BYTES (2 * 2 * 128 * 40 * 2)
#define GSM_B_BYTES (2 * 2 * 32 * 136 * 2)
#define GSM_TOTAL (GSM_A_BYTES + GSM_B_BYTES)

__device__ __forceinline__ int sA_idx(int buf, int part, int r, int c) {
    return ((buf * 2 + part) * 128 + r) * 40 + c;
}
__device__ __forceinline__ int sB_idx(int buf, int part, int r, int c) {
    return ((buf * 2 + part) * 32 + r) * 136 + c;
}

__global__ __launch_bounds__(128, 2)
void gemm_bf16x3_v4(const __nv_bfloat16* __restrict__ Ahi,
                    const __nv_bfloat16* __restrict__ Alo,
                    const __nv_bfloat16* __restrict__ Bhi,
                    const __nv_bfloat16* __restrict__ Blo,
                    float* __restrict__ C, int M, int N, int K) {
    extern __shared__ __align__(16) unsigned char smraw[];
    __nv_bfloat16* sA = (__nv_bfloat16*)smraw;
    __nv_bfloat16* sB = (__nv_bfloat16*)(smraw + GSM_A_BYTES);

    const int tid = threadIdx.x;
    const int warp = tid >> 5;
    const int m0 = blockIdx.y * 128;
    const int n0 = blockIdx.x * 128;
    const int wm = warp >> 1;       // 0..1, 64 rows each
    const int wn = warp & 1;        // 0..1, 64 cols each

    wmma::fragment<wmma::accumulator, 16, 16, 16, float> acc[4][4];
#pragma unroll
    for (int i = 0; i < 4; i++)
#pragma unroll
        for (int j = 0; j < 4; j++) wmma::fill_fragment(acc[i][j], 0.0f);

    const int nk = K / 32;

    auto load_stage = [&](int buf, int k0) {
        // A: 2 parts x 128 rows x 32 cols, 16B chunks: 1024 total
#pragma unroll
        for (int t = tid; t < 1024; t += 128) {
            int part = t >> 9;
            int c = t & 511;
            int r = c >> 2;
            int cc = (c & 3) * 8;
            size_t g = (size_t)(m0 + r) * K + k0 + cc;
            cp_async16(&sA[sA_idx(buf, part, r, cc)], part ? &Alo[g] : &Ahi[g]);
        }
        // B: 2 parts x 32 rows x 128 cols: 1024 chunks
#pragma unroll
        for (int t = tid; t < 1024; t += 128) {
            int part = t >> 9;
            int c = t & 511;
            int r = c >> 4;
            int cc = (c & 15) * 8;
            size_t g = (size_t)(k0 + r) * N + n0 + cc;
            cp_async16(&sB[sB_idx(buf, part, r, cc)], part ? &Blo[g] : &Bhi[g]);
        }
        cp_commit();
    };

    load_stage(0, 0);

    for (int kt = 0; kt < nk; kt++) {
        int buf = kt & 1;
        if (kt + 1 < nk) {
            load_stage(buf ^ 1, (kt + 1) * 32);
            cp_wait1();
        } else {
            cp_wait0();
        }
        __syncthreads();

#pragma unroll
        for (int ks = 0; ks < 2; ks++) {
            wmma::fragment<wmma::matrix_a, 16, 16, 16, __nv_bfloat16, wmma::row_major> ahi[4], alo[4];
#pragma unroll
            for (int i = 0; i < 4; i++) {
                wmma::load_matrix_sync(ahi[i], &sA[sA_idx(buf, 0, wm * 64 + i * 16, ks * 16)], 40);
                wmma::load_matrix_sync(alo[i], &sA[sA_idx(buf, 1, wm * 64 + i * 16, ks * 16)], 40);
            }
#pragma unroll
            for (int j = 0; j < 4; j++) {
                wmma::fragment<wmma::matrix_b, 16, 16, 16, __nv_bfloat16, wmma::row_major> bhi, blo;
                wmma::load_matrix_sync(bhi, &sB[sB_idx(buf, 0, ks * 16, wn * 64 + j * 16)], 136);
                wmma::load_matrix_sync(blo, &sB[sB_idx(buf, 1, ks * 16, wn * 64 + j * 16)], 136);
#pragma unroll
                for (int i = 0; i < 4; i++) {
                    wmma::mma_sync(acc[i][j], ahi[i], bhi, acc[i][j]);
                    wmma::mma_sync(acc[i][j], ahi[i], blo, acc[i][j]);
                    wmma::mma_sync(acc[i][j], alo[i], bhi, acc[i][j]);
                }
            }
        }
        __syncthreads();
    }

#pragma unroll
    for (int i = 0; i < 4; i++) {
#pragma unroll
        for (int j = 0; j < 4; j++) {
            int row0 = m0 + wm * 64 + i * 16;
            int col0 = n0 + wn * 64 + j * 16;
            wmma::store_matrix_sync(&C[(size_t)row0 * N + col0], acc[i][j], N,
                                    wmma::mem_row_major);
        }
    }
}

// ---------------------------------------------------------------------------
// flash_tc_v3 (unchanged from R10, known-good)
// ---------------------------------------------------------------------------
#define F3_QHI 0
#define F3_QLO 18432
#define F3_KHI 36864
#define F3_KLO 46080
#define F3_VHI 55296
#define F3_VLO 64512
#define F3_SFP 73728
#define F3_PHI 73728
#define F3_PLO 92160
#define F3_M   110592
#define F3_L   111104
#define F3_AL  111616
#define F3_SMEM_TOTAL 112128

__global__ __launch_bounds__(256, 2)
void flash_tc_v3(const __nv_bfloat16* __restrict__ qh,
                 const __nv_bfloat16* __restrict__ ql,
                 __nv_bfloat16* __restrict__ ohi,
                 __nv_bfloat16* __restrict__ olo) {
    extern __shared__ __align__(16) unsigned char fsm[];
    __nv_bfloat16* Qhi = (__nv_bfloat16*)(fsm + F3_QHI);
    __nv_bfloat16* Qlo = (__nv_bfloat16*)(fsm + F3_QLO);
    __nv_bfloat16* Khi = (__nv_bfloat16*)(fsm + F3_KHI);
    __nv_bfloat16* Klo = (__nv_bfloat16*)(fsm + F3_KLO);
    __nv_bfloat16* Vhi = (__nv_bfloat16*)(fsm + F3_VHI);
    __nv_bfloat16* Vlo = (__nv_bfloat16*)(fsm + F3_VLO);
    float* Sf  = (float*)(fsm + F3_SFP);
    __nv_bfloat16* Phi = (__nv_bfloat16*)(fsm + F3_PHI);
    __nv_bfloat16* Plo = (__nv_bfloat16*)(fsm + F3_PLO);
    float* m_sh = (float*)(fsm + F3_M);
    float* l_sh = (float*)(fsm + F3_L);
    float* al_sh= (float*)(fsm + F3_AL);

    const int tid = threadIdx.x;
    const int warp = tid >> 5;
    const int qt = (int)gridDim.x - 1 - (int)blockIdx.x;
    const int kh = blockIdx.y >> 1;
    const int pair = blockIdx.y & 1;
    const int b = blockIdx.z;
    const int s0q = qt * 64;
    const int m0w = warp * 16;

    __nv_bfloat16* kvdst[4] = {Khi, Klo, Vhi, Vlo};
    auto load_kv = [&](int s0k) {
        for (int t = tid; t < 2048; t += 256) {
            int arr = t >> 9;
            int r = (t >> 3) & 63;
            int ch = (t & 7) * 8;
            const __nv_bfloat16* src = (arr & 1) ? ql : qh;
            size_t g = (size_t)(b * SS + s0k + r) * NQKV + 1024 + kh * 64 +
                       ((arr >> 1) ? 256 : 0) + ch;
            cp_async16(&kvdst[arr][r * 72 + ch], &src[g]);
        }
        cp_commit();
    };

    load_kv(0);

    for (int t = tid; t < 2048; t += 256) {
        int part = t >> 10;
        int m = (t >> 3) & 127;
        int ch = (t & 7) * 8;
        int hp = m >> 6;
        int rr = m & 63;
        const __nv_bfloat16* src = part ? ql : qh;
        size_t gaddr = (size_t)(b * SS + s0q + rr) * NQKV +
                       (kh * 4 + pair * 2 + hp) * 64 + ch;
        __nv_bfloat16* dst = part ? Qlo : Qhi;
        *reinterpret_cast<uint4*>(&dst[m * 72 + ch]) =
            *reinterpret_cast<const uint4*>(&src[gaddr]);
    }
    if (tid < 128) { m_sh[tid] = -1e30f; l_sh[tid] = 0.0f; }

    const int srow = tid >> 1;
    const int sc0 = (tid & 1) * 32;
    const int srr = srow & 63;
    float ov[32];
#pragma unroll
    for (int i = 0; i < 32; i++) ov[i] = 0.0f;

    for (int kt = 0; kt <= qt; kt++) {
        const int s0k = kt * 64;
        cp_wait0();
        __syncthreads();

        {
            wmma::fragment<wmma::accumulator, 16, 16, 16, float> accs[4];
#pragma unroll
            for (int j = 0; j < 4; j++) wmma::fill_fragment(accs[j], 0.0f);
#pragma unroll
            for (int ks = 0; ks < 4; ks++) {
                wmma::fragment<wmma::matrix_a, 16, 16, 16, __nv_bfloat16, wmma::row_major> a_hi, a_lo;
                wmma::load_matrix_sync(a_hi, &Qhi[m0w * 72 + ks * 16], 72);
                wmma::load_matrix_sync(a_lo, &Qlo[m0w * 72 + ks * 16], 72);
#pragma unroll
                for (int j = 0; j < 4; j++) {
                    wmma::fragment<wmma::matrix_b, 16, 16, 16, __nv_bfloat16, wmma::col_major> b_hi, b_lo;
                    wmma::load_matrix_sync(b_hi, &Khi[(j * 16) * 72 + ks * 16], 72);
                    wmma::load_matrix_sync(b_lo, &Klo[(j * 16) * 72 + ks * 16], 72);
                    wmma::mma_sync(accs[j], a_hi, b_hi, accs[j]);
                    wmma::mma_sync(accs[j], a_hi, b_lo, accs[j]);
                    wmma::mma_sync(accs[j], a_lo, b_hi, accs[j]);
                }
            }
#pragma unroll
            for (int j = 0; j < 4; j++)
                wmma::store_matrix_sync(&Sf[m0w * 68 + j * 16], accs[j], 68, wmma::mem_row_major);
        }
        __syncthreads();

        float sv[32];
        {
            float vmax = -1e30f;
#pragma unroll
            for (int i = 0; i < 32; i++) {
                float s = Sf[srow * 68 + sc0 + i] * 0.125f;
                if (s0k + sc0 + i > s0q + srr) s = -1e30f;
                sv[i] = s;
                vmax = fmaxf(vmax, s);
            }
            vmax = fmaxf(vmax, __shfl_xor_sync(0xffffffffu, vmax, 1));
            float mo = m_sh[srow];
            float mx = fmaxf(mo, vmax);
            float al = __expf(mo - mx);
            __syncthreads();
            float sum = 0.0f;
#pragma unroll
            for (int i = 0; i < 32; i++) {
                float p = __expf(sv[i] - mx);
                sum += p;
                __nv_bfloat16 ph = __float2bfloat16(p);
                Phi[srow * 72 + sc0 + i] = ph;
                Plo[srow * 72 + sc0 + i] = __float2bfloat16(p - __bfloat162float(ph));
            }
            sum += __shfl_xor_sync(0xffffffffu, sum, 1);
            if ((tid & 1) == 0) {
                m_sh[srow] = mx;
                l_sh[srow] = l_sh[srow] * al + sum;
                al_sh[srow] = al;
            }
        }
        __syncthreads();

        {
            wmma::fragment<wmma::accumulator, 16, 16, 16, float> acco[4];
#pragma unroll
            for (int j = 0; j < 4; j++) wmma::fill_fragment(acco[j], 0.0f);
#pragma unroll
            for (int ks = 0; ks < 4; ks++) {
                wmma::fragment<wmma::matrix_a, 16, 16, 16, __nv_bfloat16, wmma::row_major> p_hi, p_lo;
                wmma::load_matrix_sync(p_hi, &Phi[m0w * 72 + ks * 16], 72);
                wmma::load_matrix_sync(p_lo, &Plo[m0w * 72 + ks * 16], 72);
#pragma unroll
                for (int j = 0; j < 4; j++) {
                    wmma::fragment<wmma::matrix_b, 16, 16, 16, __nv_bfloat16, wmma::row_major> v_hi, v_lo;
                    wmma::load_matrix_sync(v_hi, &Vhi[(ks * 16) * 72 + j * 16], 72);
                    wmma::load_matrix_sync(v_lo, &Vlo[(ks * 16) * 72 + j * 16], 72);
                    wmma::mma_sync(acco[j], p_hi, v_hi, acco[j]);
                    wmma::mma_sync(acco[j], p_hi, v_lo, acco[j]);
                    wmma::mma_sync(acco[j], p_lo, v_hi, acco[j]);
                }
            }
            __syncthreads();

            if (kt < qt) load_kv(s0k + 64);

#pragma unroll
            for (int j = 0; j < 4; j++)
                wmma::store_matrix_sync(&Sf[m0w * 68 + j * 16], acco[j], 68, wmma::mem_row_major);
        }
        __syncthreads();

        {
            float al = al_sh[srow];
#pragma unroll
            for (int i = 0; i < 32; i++)
                ov[i] = ov[i] * al + Sf[srow * 68 + sc0 + i];
        }
    }

    float invl = 1.0f / l_sh[srow];
    int hp = srow >> 6;
#pragma unroll
    for (int i = 0; i < 32; i++) {
        float f = ov[i] * invl;
        size_t oaddr = (size_t)(b * SS + s0q + srr) * DD +
                       (kh * 4 + pair * 2 + hp) * 64 + sc0 + i;
        __nv_bfloat16 h = __float2bfloat16(f);
        ohi[oaddr] = h;
        olo[oaddr] = __float2bfloat16(f - __bfloat162float(h));
    }
}

// ---------------------------------------------------------------------------
// Launch
// ---------------------------------------------------------------------------
extern "C" void kernel_launch(void* const* d_in, const int* in_sizes, int n_in,
                              void* d_out, int out_size) {
    const float* x  = (const float*)d_in[0];
    const float* Wq = (const float*)d_in[2];
    const float* bq = (const float*)d_in[3];
    const float* Wk = (const float*)d_in[4];
    const float* bk = (const float*)d_in[5];
    const float* Wv = (const float*)d_in[6];
    const float* bv = (const float*)d_in[7];
    const float* Wo = (const float*)d_in[8];
    const float* bo = (const float*)d_in[9];
    float* out = (float*)d_out;

    float *gqkv, *gc, *gs, *gbqkv;
    cudaGetSymbolAddress((void**)&gqkv, g_qkv);
    cudaGetSymbolAddress((void**)&gc, g_cos);
    cudaGetSymbolAddress((void**)&gs, g_sin);
    cudaGetSymbolAddress((void**)&gbqkv, g_bqkv);

    __nv_bfloat16 *xhi, *xlo, *ohi, *olo, *wqkvhi, *wqkvlo, *wohi, *wolo, *qkvhi, *qkvlo;
    cudaGetSymbolAddress((void**)&xhi, g_xhi);
    cudaGetSymbolAddress((void**)&xlo, g_xlo);
    cudaGetSymbolAddress((void**)&ohi, g_ohi);
    cudaGetSymbolAddress((void**)&olo, g_olo);
    cudaGetSymbolAddress((void**)&wqkvhi, g_wqkvhi);
    cudaGetSymbolAddress((void**)&wqkvlo, g_wqkvlo);
    cudaGetSymbolAddress((void**)&wohi, g_wohi);
    cudaGetSymbolAddress((void**)&wolo, g_wolo);
    cudaGetSymbolAddress((void**)&qkvhi, g_qkvhi);
    cudaGetSymbolAddress((void**)&qkvlo, g_qkvlo);

    const int M = BB * SS;  // 4096
    dim3 blk(128);

    rope_table_kernel<<<(SS * 32 + 255) / 256, 256>>>(gc, gs);

    int nx = M * DD;
    split_kernel<<<(nx + 255) / 256, 256>>>(x, xhi, xlo, nx);
    pack_wqkv_kernel<<<(DD * NQKV + 255) / 256, 256>>>(Wq, Wk, Wv, bq, bk, bv,
                                                       wqkvhi, wqkvlo, gbqkv);
    split_kernel<<<(DD * DD + 255) / 256, 256>>>(Wo, wohi, wolo, DD * DD);

    cudaFuncSetAttribute(gemm_bf16x3_v4, cudaFuncAttributeMaxDynamicSharedMemorySize,
                         GSM_TOTAL);

    // QKV = x @ Wqkv (bias deferred to rope_split)
    gemm_bf16x3_v4<<<dim3(NQKV / 128, M / 128), blk, GSM_TOTAL>>>(
        xhi, xlo, wqkvhi, wqkvlo, gqkv, M, NQKV, 1024);

    // Fused bias + RoPE + split
    int nrs = BB * SS * 20 * 32 + BB * SS * 256;
    rope_split_kernel<<<(nrs + 255) / 256, 256>>>(gqkv, gbqkv, gc, gs, qkvhi, qkvlo);

    cudaFuncSetAttribute(flash_tc_v3, cudaFuncAttributeMaxDynamicSharedMemorySize,
                         F3_SMEM_TOTAL);
    flash_tc_v3<<<dim3(SS / 64, KHH * 2, BB), 256, F3_SMEM_TOTAL>>>(qkvhi, qkvlo, ohi, olo);

    // out = attn_out @ Wo, then bias
    gemm_bf16x3_v4<<<dim3(1024 / 128, M / 128), blk, GSM_TOTAL>>>(
        ohi, olo, wohi, wolo, out, M, 1024, 1024);
    bias_add_kernel<<<(nx + 255) / 256, 256>>>(out, bo, nx);
}

// round 12
// speedup vs baseline: 1.5308x; 1.0094x over previous
#include <cuda_runtime.h>
#include <cuda_bf16.h>
#include <mma.h>
#include <math.h>
#include <cstdint>

using namespace nvcuda;

#define BB 2
#define SS 2048
#define DD 1024
#define HH 16
#define KHH 4
#define DKK 64
#define REP 4
#define NQKV 1536   // 1024 Q | 256 K | 256 V

// fp32 scratch
__device__ float g_cos[SS * 32];
__device__ float g_sin[SS * 32];
__device__ float g_bqkv[NQKV];

// bf16 split scratch
__device__ __nv_bfloat16 g_xhi[BB * SS * DD],    g_xlo[BB * SS * DD];
__device__ __nv_bfloat16 g_ohi[BB * SS * DD],    g_olo[BB * SS * DD];
__device__ __nv_bfloat16 g_wqkvhi[DD * NQKV],    g_wqkvlo[DD * NQKV];
__device__ __nv_bfloat16 g_wohi[DD * DD],        g_wolo[DD * DD];
__device__ __nv_bfloat16 g_qkvhi[BB * SS * NQKV], g_qkvlo[BB * SS * NQKV];

// ---------------------------------------------------------------------------
// cp.async helpers
// ---------------------------------------------------------------------------
__device__ __forceinline__ void cp_async16(void* sptr, const void* gptr) {
    unsigned int s = (unsigned int)__cvta_generic_to_shared(sptr);
    asm volatile("cp.async.cg.shared.global [%0], [%1], 16;\n" :: "r"(s), "l"(gptr));
}
__device__ __forceinline__ void cp_commit() { asm volatile("cp.async.commit_group;\n"); }
__device__ __forceinline__ void cp_wait1() { asm volatile("cp.async.wait_group 1;\n"); }
__device__ __forceinline__ void cp_wait0() { asm volatile("cp.async.wait_group 0;\n"); }

// ---------------------------------------------------------------------------
// Small kernels
// ---------------------------------------------------------------------------
__global__ void split_kernel(const float* __restrict__ in,
                             __nv_bfloat16* __restrict__ hi,
                             __nv_bfloat16* __restrict__ lo, int n) {
    int i = blockIdx.x * blockDim.x + threadIdx.x;
    if (i >= n) return;
    float f = in[i];
    __nv_bfloat16 h = __float2bfloat16(f);
    hi[i] = h;
    lo[i] = __float2bfloat16(f - __bfloat162float(h));
}

__global__ void pack_wqkv_kernel(const float* __restrict__ Wq, const float* __restrict__ Wk,
                                 const float* __restrict__ Wv, const float* __restrict__ bq,
                                 const float* __restrict__ bk, const float* __restrict__ bv,
                                 __nv_bfloat16* __restrict__ hi, __nv_bfloat16* __restrict__ lo,
                                 float* __restrict__ bqkv) {
    int i = blockIdx.x * blockDim.x + threadIdx.x;
    int n = DD * NQKV;
    if (i < NQKV) {
        int c = i;
        bqkv[c] = (c < 1024) ? bq[c] : (c < 1280 ? bk[c - 1024] : bv[c - 1280]);
    }
    if (i >= n) return;
    int row = i / NQKV;
    int col = i % NQKV;
    float f;
    if (col < 1024)      f = Wq[row * 1024 + col];
    else if (col < 1280) f = Wk[row * 256 + col - 1024];
    else                 f = Wv[row * 256 + col - 1280];
    __nv_bfloat16 h = __float2bfloat16(f);
    hi[i] = h;
    lo[i] = __float2bfloat16(f - __bfloat162float(h));
}

__global__ void bias_add_kernel(float* __restrict__ out, const float* __restrict__ b, int n) {
    int i = blockIdx.x * blockDim.x + threadIdx.x;
    if (i < n) out[i] += b[i & (DD - 1)];
}

__global__ void rope_table_kernel(float* __restrict__ ctab, float* __restrict__ stab) {
    int idx = blockIdx.x * blockDim.x + threadIdx.x;
    if (idx >= SS * 32) return;
    int s = idx >> 5;
    int d = idx & 31;
    double theta = pow(10000.0, -(double)d / 32.0);
    double f = (double)s * theta;
    ctab[idx] = (float)cos(f);
    stab[idx] = (float)sin(f);
}

// ---------------------------------------------------------------------------
// Shared GEMM config (v4 mainloop): 128x128 block, 128 threads = 4 warps
// (2m x 2n), warp tile 64x64, BK=32 double-buffered cp.async, 2 CTAs/SM.
// ---------------------------------------------------------------------------
#define GSM_A_BYTES (2 * 2 * 128 * 40 * 2)
#define GSM_B_BYTES (2 * 2 * 32 * 136 * 2)
#define GSM_TOTAL (GSM_A_BYTES + GSM_B_BYTES)

__device__ __forceinline__ int sA_idx(int buf, int part, int r, int c) {
    return ((buf * 2 + part) * 128 + r) * 40 + c;
}
__device__ __forceinline__ int sB_idx(int buf, int part, int r, int c) {
    return ((buf * 2 + part) * 32 + r) * 136 + c;
}

// Mainloop macro body shared by both GEMM kernels (via device function on acc)
struct GemmCtx {
    const __nv_bfloat16 *Ahi, *Alo, *Bhi, *Blo;
    int M, N, K, m0, n0, tid;
    __nv_bfloat16 *sA, *sB;
};

__device__ __forceinline__ void gemm_mainloop(
    GemmCtx& g, wmma::fragment<wmma::accumulator, 16, 16, 16, float> (&acc)[4][4],
    int wm, int wn) {
    const int nk = g.K / 32;
    auto load_stage = [&](int buf, int k0) {
#pragma unroll
        for (int t = g.tid; t < 1024; t += 128) {
            int part = t >> 9;
            int c = t & 511;
            int r = c >> 2;
            int cc = (c & 3) * 8;
            size_t gm = (size_t)(g.m0 + r) * g.K + k0 + cc;
            cp_async16(&g.sA[sA_idx(buf, part, r, cc)], part ? &g.Alo[gm] : &g.Ahi[gm]);
        }
#pragma unroll
        for (int t = g.tid; t < 1024; t += 128) {
            int part = t >> 9;
            int c = t & 511;
            int r = c >> 4;
            int cc = (c & 15) * 8;
            size_t gm = (size_t)(k0 + r) * g.N + g.n0 + cc;
            cp_async16(&g.sB[sB_idx(buf, part, r, cc)], part ? &g.Blo[gm] : &g.Bhi[gm]);
        }
        cp_commit();
    };

    load_stage(0, 0);

    for (int kt = 0; kt < nk; kt++) {
        int buf = kt & 1;
        if (kt + 1 < nk) {
            load_stage(buf ^ 1, (kt + 1) * 32);
            cp_wait1();
        } else {
            cp_wait0();
        }
        __syncthreads();

#pragma unroll
        for (int ks = 0; ks < 2; ks++) {
            wmma::fragment<wmma::matrix_a, 16, 16, 16, __nv_bfloat16, wmma::row_major> ahi[4], alo[4];
#pragma unroll
            for (int i = 0; i < 4; i++) {
                wmma::load_matrix_sync(ahi[i], &g.sA[sA_idx(buf, 0, wm * 64 + i * 16, ks * 16)], 40);
                wmma::load_matrix_sync(alo[i], &g.sA[sA_idx(buf, 1, wm * 64 + i * 16, ks * 16)], 40);
            }
#pragma unroll
            for (int j = 0; j < 4; j++) {
                wmma::fragment<wmma::matrix_b, 16, 16, 16, __nv_bfloat16, wmma::row_major> bhi, blo;
                wmma::load_matrix_sync(bhi, &g.sB[sB_idx(buf, 0, ks * 16, wn * 64 + j * 16)], 136);
                wmma::load_matrix_sync(blo, &g.sB[sB_idx(buf, 1, ks * 16, wn * 64 + j * 16)], 136);
#pragma unroll
                for (int i = 0; i < 4; i++) {
                    wmma::mma_sync(acc[i][j], ahi[i], bhi, acc[i][j]);
                    wmma::mma_sync(acc[i][j], ahi[i], blo, acc[i][j]);
                    wmma::mma_sync(acc[i][j], alo[i], bhi, acc[i][j]);
                }
            }
        }
        __syncthreads();
    }
}

// ---------------------------------------------------------------------------
// QKV GEMM with fused bias + RoPE + bf16 hi/lo split epilogue.
// Never materializes fp32 QKV. Warp tile (64 cols) == one head.
// ---------------------------------------------------------------------------
__global__ __launch_bounds__(128, 2)
void gemm_qkv_rope(const __nv_bfloat16* __restrict__ Ahi,
                   const __nv_bfloat16* __restrict__ Alo,
                   const __nv_bfloat16* __restrict__ Bhi,
                   const __nv_bfloat16* __restrict__ Blo,
                   const float* __restrict__ bias,
                   const float* __restrict__ ctab,
                   const float* __restrict__ stab,
                   __nv_bfloat16* __restrict__ ohi,
                   __nv_bfloat16* __restrict__ olo,
                   int M, int N, int K) {
    extern __shared__ __align__(16) unsigned char smraw[];
    GemmCtx g;
    g.Ahi = Ahi; g.Alo = Alo; g.Bhi = Bhi; g.Blo = Blo;
    g.M = M; g.N = N; g.K = K;
    g.tid = threadIdx.x;
    g.m0 = blockIdx.y * 128;
    g.n0 = blockIdx.x * 128;
    g.sA = (__nv_bfloat16*)smraw;
    g.sB = (__nv_bfloat16*)(smraw + GSM_A_BYTES);

    const int warp = threadIdx.x >> 5;
    const int lane = threadIdx.x & 31;
    const int wm = warp >> 1;
    const int wn = warp & 1;

    wmma::fragment<wmma::accumulator, 16, 16, 16, float> acc[4][4];
#pragma unroll
    for (int i = 0; i < 4; i++)
#pragma unroll
        for (int j = 0; j < 4; j++) wmma::fill_fragment(acc[i][j], 0.0f);

    gemm_mainloop(g, acc, wm, wn);

    // Epilogue: stage warp's 64x64 fp32 tile in (dead) smem, rope+bias+split.
    float* stg = (float*)(smraw) + warp * (64 * 68);
#pragma unroll
    for (int i = 0; i < 4; i++)
#pragma unroll
        for (int j = 0; j < 4; j++)
            wmma::store_matrix_sync(&stg[(i * 16) * 68 + j * 16], acc[i][j], 68,
                                    wmma::mem_row_major);
    __syncwarp();

    const int col_base = g.n0 + wn * 64;     // head-aligned (64)
    const int row_base = g.m0 + wm * 64;

    if (col_base < 1280) {
        // Q or K head: rope pairs (d, d+32)
        for (int t = lane; t < 2048; t += 32) {
            int r = t >> 5;
            int d = t & 31;
            float x1 = stg[r * 68 + d] + bias[col_base + d];
            float x2 = stg[r * 68 + d + 32] + bias[col_base + d + 32];
            int grow = row_base + r;
            int s = grow & (SS - 1);
            float c = ctab[s * 32 + d];
            float sn = stab[s * 32 + d];
            float r1 = x1 * c - x2 * sn;
            float r2 = x2 * c + x1 * sn;
            size_t base = (size_t)grow * NQKV + col_base + d;
            __nv_bfloat16 h1 = __float2bfloat16(r1);
            __nv_bfloat16 h2 = __float2bfloat16(r2);
            ohi[base] = h1;
            olo[base] = __float2bfloat16(r1 - __bfloat162float(h1));
            ohi[base + 32] = h2;
            olo[base + 32] = __float2bfloat16(r2 - __bfloat162float(h2));
        }
    } else {
        // V head: bias + split only
        for (int t = lane; t < 4096; t += 32) {
            int r = t >> 6;
            int d = t & 63;
            float f = stg[r * 68 + d] + bias[col_base + d];
            size_t base = (size_t)(row_base + r) * NQKV + col_base + d;
            __nv_bfloat16 h = __float2bfloat16(f);
            ohi[base] = h;
            olo[base] = __float2bfloat16(f - __bfloat162float(h));
        }
    }
}

// ---------------------------------------------------------------------------
// Plain bf16x3 GEMM v4 (fp32 out) for the output projection.
// ---------------------------------------------------------------------------
__global__ __launch_bounds__(128, 2)
void gemm_bf16x3_v4(const __nv_bfloat16* __restrict__ Ahi,
                    const __nv_bfloat16* __restrict__ Alo,
                    const __nv_bfloat16* __restrict__ Bhi,
                    const __nv_bfloat16* __restrict__ Blo,
                    float* __restrict__ C, int M, int N, int K) {
    extern __shared__ __align__(16) unsigned char smraw[];
    GemmCtx g;
    g.Ahi = Ahi; g.Alo = Alo; g.Bhi = Bhi; g.Blo = Blo;
    g.M = M; g.N = N; g.K = K;
    g.tid = threadIdx.x;
    g.m0 = blockIdx.y * 128;
    g.n0 = blockIdx.x * 128;
    g.sA = (__nv_bfloat16*)smraw;
    g.sB = (__nv_bfloat16*)(smraw + GSM_A_BYTES);

    const int warp = threadIdx.x >> 5;
    const int wm = warp >> 1;
    const int wn = warp & 1;

    wmma::fragment<wmma::accumulator, 16, 16, 16, float> acc[4][4];
#pragma unroll
    for (int i = 0; i < 4; i++)
#pragma unroll
        for (int j = 0; j < 4; j++) wmma::fill_fragment(acc[i][j], 0.0f);

    gemm_mainloop(g, acc, wm, wn);

#pragma unroll
    for (int i = 0; i < 4; i++) {
#pragma unroll
        for (int j = 0; j < 4; j++) {
            int row0 = g.m0 + wm * 64 + i * 16;
            int col0 = g.n0 + wn * 64 + j * 16;
            wmma::store_matrix_sync(&C[(size_t)row0 * g.N + col0], acc[i][j], g.N,
                                    wmma::mem_row_major);
        }
    }
}

// ---------------------------------------------------------------------------
// flash_tc_v3 (unchanged from R10/R11, known-good)
// ---------------------------------------------------------------------------
#define F3_QHI 0
#define F3_QLO 18432
#define F3_KHI 36864
#define F3_KLO 46080
#define F3_VHI 55296
#define F3_VLO 64512
#define F3_SFP 73728
#define F3_PHI 73728
#define F3_PLO 92160
#define F3_M   110592
#define F3_L   111104
#define F3_AL  111616
#define F3_SMEM_TOTAL 112128

__global__ __launch_bounds__(256, 2)
void flash_tc_v3(const __nv_bfloat16* __restrict__ qh,
                 const __nv_bfloat16* __restrict__ ql,
                 __nv_bfloat16* __restrict__ ohi,
                 __nv_bfloat16* __restrict__ olo) {
    extern __shared__ __align__(16) unsigned char fsm[];
    __nv_bfloat16* Qhi = (__nv_bfloat16*)(fsm + F3_QHI);
    __nv_bfloat16* Qlo = (__nv_bfloat16*)(fsm + F3_QLO);
    __nv_bfloat16* Khi = (__nv_bfloat16*)(fsm + F3_KHI);
    __nv_bfloat16* Klo = (__nv_bfloat16*)(fsm + F3_KLO);
    __nv_bfloat16* Vhi = (__nv_bfloat16*)(fsm + F3_VHI);
    __nv_bfloat16* Vlo = (__nv_bfloat16*)(fsm + F3_VLO);
    float* Sf  = (float*)(fsm + F3_SFP);
    __nv_bfloat16* Phi = (__nv_bfloat16*)(fsm + F3_PHI);
    __nv_bfloat16* Plo = (__nv_bfloat16*)(fsm + F3_PLO);
    float* m_sh = (float*)(fsm + F3_M);
    float* l_sh = (float*)(fsm + F3_L);
    float* al_sh= (float*)(fsm + F3_AL);

    const int tid = threadIdx.x;
    const int warp = tid >> 5;
    const int qt = (int)gridDim.x - 1 - (int)blockIdx.x;
    const int kh = blockIdx.y >> 1;
    const int pair = blockIdx.y & 1;
    const int b = blockIdx.z;
    const int s0q = qt * 64;
    const int m0w = warp * 16;

    __nv_bfloat16* kvdst[4] = {Khi, Klo, Vhi, Vlo};
    auto load_kv = [&](int s0k) {
        for (int t = tid; t < 2048; t += 256) {
            int arr = t >> 9;
            int r = (t >> 3) & 63;
            int ch = (t & 7) * 8;
            const __nv_bfloat16* src = (arr & 1) ? ql : qh;
            size_t g = (size_t)(b * SS + s0k + r) * NQKV + 1024 + kh * 64 +
                       ((arr >> 1) ? 256 : 0) + ch;
            cp_async16(&kvdst[arr][r * 72 + ch], &src[g]);
        }
        cp_commit();
    };

    load_kv(0);

    for (int t = tid; t < 2048; t += 256) {
        int part = t >> 10;
        int m = (t >> 3) & 127;
        int ch = (t & 7) * 8;
        int hp = m >> 6;
        int rr = m & 63;
        const __nv_bfloat16* src = part ? ql : qh;
        size_t gaddr = (size_t)(b * SS + s0q + rr) * NQKV +
                       (kh * 4 + pair * 2 + hp) * 64 + ch;
        __nv_bfloat16* dst = part ? Qlo : Qhi;
        *reinterpret_cast<uint4*>(&dst[m * 72 + ch]) =
            *reinterpret_cast<const uint4*>(&src[gaddr]);
    }
    if (tid < 128) { m_sh[tid] = -1e30f; l_sh[tid] = 0.0f; }

    const int srow = tid >> 1;
    const int sc0 = (tid & 1) * 32;
    const int srr = srow & 63;
    float ov[32];
#pragma unroll
    for (int i = 0; i < 32; i++) ov[i] = 0.0f;

    for (int kt = 0; kt <= qt; kt++) {
        const int s0k = kt * 64;
        cp_wait0();
        __syncthreads();

        {
            wmma::fragment<wmma::accumulator, 16, 16, 16, float> accs[4];
#pragma unroll
            for (int j = 0; j < 4; j++) wmma::fill_fragment(accs[j], 0.0f);
#pragma unroll
            for (int ks = 0; ks < 4; ks++) {
                wmma::fragment<wmma::matrix_a, 16, 16, 16, __nv_bfloat16, wmma::row_major> a_hi, a_lo;
                wmma::load_matrix_sync(a_hi, &Qhi[m0w * 72 + ks * 16], 72);
                wmma::load_matrix_sync(a_lo, &Qlo[m0w * 72 + ks * 16], 72);
#pragma unroll
                for (int j = 0; j < 4; j++) {
                    wmma::fragment<wmma::matrix_b, 16, 16, 16, __nv_bfloat16, wmma::col_major> b_hi, b_lo;
                    wmma::load_matrix_sync(b_hi, &Khi[(j * 16) * 72 + ks * 16], 72);
                    wmma::load_matrix_sync(b_lo, &Klo[(j * 16) * 72 + ks * 16], 72);
                    wmma::mma_sync(accs[j], a_hi, b_hi, accs[j]);
                    wmma::mma_sync(accs[j], a_hi, b_lo, accs[j]);
                    wmma::mma_sync(accs[j], a_lo, b_hi, accs[j]);
                }
            }
#pragma unroll
            for (int j = 0; j < 4; j++)
                wmma::store_matrix_sync(&Sf[m0w * 68 + j * 16], accs[j], 68, wmma::mem_row_major);
        }
        __syncthreads();

        float sv[32];
        {
            float vmax = -1e30f;
#pragma unroll
            for (int i = 0; i < 32; i++) {
                float s = Sf[srow * 68 + sc0 + i] * 0.125f;
                if (s0k + sc0 + i > s0q + srr) s = -1e30f;
                sv[i] = s;
                vmax = fmaxf(vmax, s);
            }
            vmax = fmaxf(vmax, __shfl_xor_sync(0xffffffffu, vmax, 1));
            float mo = m_sh[srow];
            float mx = fmaxf(mo, vmax);
            float al = __expf(mo - mx);
            __syncthreads();
            float sum = 0.0f;
#pragma unroll
            for (int i = 0; i < 32; i++) {
                float p = __expf(sv[i] - mx);
                sum += p;
                __nv_bfloat16 ph = __float2bfloat16(p);
                Phi[srow * 72 + sc0 + i] = ph;
                Plo[srow * 72 + sc0 + i] = __float2bfloat16(p - __bfloat162float(ph));
            }
            sum += __shfl_xor_sync(0xffffffffu, sum, 1);
            if ((tid & 1) == 0) {
                m_sh[srow] = mx;
                l_sh[srow] = l_sh[srow] * al + sum;
                al_sh[srow] = al;
            }
        }
        __syncthreads();

        {
            wmma::fragment<wmma::accumulator, 16, 16, 16, float> acco[4];
#pragma unroll
            for (int j = 0; j < 4; j++) wmma::fill_fragment(acco[j], 0.0f);
#pragma unroll
            for (int ks = 0; ks < 4; ks++) {
                wmma::fragment<wmma::matrix_a, 16, 16, 16, __nv_bfloat16, wmma::row_major> p_hi, p_lo;
                wmma::load_matrix_sync(p_hi, &Phi[m0w * 72 + ks * 16], 72);
                wmma::load_matrix_sync(p_lo, &Plo[m0w * 72 + ks * 16], 72);
#pragma unroll
                for (int j = 0; j < 4; j++) {
                    wmma::fragment<wmma::matrix_b, 16, 16, 16, __nv_bfloat16, wmma::row_major> v_hi, v_lo;
                    wmma::load_matrix_sync(v_hi, &Vhi[(ks * 16) * 72 + j * 16], 72);
                    wmma::load_matrix_sync(v_lo, &Vlo[(ks * 16) * 72 + j * 16], 72);
                    wmma::mma_sync(acco[j], p_hi, v_hi, acco[j]);
                    wmma::mma_sync(acco[j], p_hi, v_lo, acco[j]);
                    wmma::mma_sync(acco[j], p_lo, v_hi, acco[j]);
                }
            }
            __syncthreads();

            if (kt < qt) load_kv(s0k + 64);

#pragma unroll
            for (int j = 0; j < 4; j++)
                wmma::store_matrix_sync(&Sf[m0w * 68 + j * 16], acco[j], 68, wmma::mem_row_major);
        }
        __syncthreads();

        {
            float al = al_sh[srow];
#pragma unroll
            for (int i = 0; i < 32; i++)
                ov[i] = ov[i] * al + Sf[srow * 68 + sc0 + i];
        }
    }

    float invl = 1.0f / l_sh[srow];
    int hp = srow >> 6;
#pragma unroll
    for (int i = 0; i < 32; i++) {
        float f = ov[i] * invl;
        size_t oaddr = (size_t)(b * SS + s0q + srr) * DD +
                       (kh * 4 + pair * 2 + hp) * 64 + sc0 + i;
        __nv_bfloat16 h = __float2bfloat16(f);
        ohi[oaddr] = h;
        olo[oaddr] = __float2bfloat16(f - __bfloat162float(h));
    }
}

// ---------------------------------------------------------------------------
// Launch
// ---------------------------------------------------------------------------
extern "C" void kernel_launch(void* const* d_in, const int* in_sizes, int n_in,
                              void* d_out, int out_size) {
    const float* x  = (const float*)d_in[0];
    const float* Wq = (const float*)d_in[2];
    const float* bq = (const float*)d_in[3];
    const float* Wk = (const float*)d_in[4];
    const float* bk = (const float*)d_in[5];
    const float* Wv = (const float*)d_in[6];
    const float* bv = (const float*)d_in[7];
    const float* Wo = (const float*)d_in[8];
    const float* bo = (const float*)d_in[9];
    float* out = (float*)d_out;

    float *gc, *gs, *gbqkv;
    cudaGetSymbolAddress((void**)&gc, g_cos);
    cudaGetSymbolAddress((void**)&gs, g_sin);
    cudaGetSymbolAddress((void**)&gbqkv, g_bqkv);

    __nv_bfloat16 *xhi, *xlo, *ohi, *olo, *wqkvhi, *wqkvlo, *wohi, *wolo, *qkvhi, *qkvlo;
    cudaGetSymbolAddress((void**)&xhi, g_xhi);
    cudaGetSymbolAddress((void**)&xlo, g_xlo);
    cudaGetSymbolAddress((void**)&ohi, g_ohi);
    cudaGetSymbolAddress((void**)&olo, g_olo);
    cudaGetSymbolAddress((void**)&wqkvhi, g_wqkvhi);
    cudaGetSymbolAddress((void**)&wqkvlo, g_wqkvlo);
    cudaGetSymbolAddress((void**)&wohi, g_wohi);
    cudaGetSymbolAddress((void**)&wolo, g_wolo);
    cudaGetSymbolAddress((void**)&qkvhi, g_qkvhi);
    cudaGetSymbolAddress((void**)&qkvlo, g_qkvlo);

    const int M = BB * SS;  // 4096
    dim3 blk(128);

    rope_table_kernel<<<(SS * 32 + 255) / 256, 256>>>(gc, gs);

    int nx = M * DD;
    split_kernel<<<(nx + 255) / 256, 256>>>(x, xhi, xlo, nx);
    pack_wqkv_kernel<<<(DD * NQKV + 255) / 256, 256>>>(Wq, Wk, Wv, bq, bk, bv,
                                                       wqkvhi, wqkvlo, gbqkv);
    split_kernel<<<(DD * DD + 255) / 256, 256>>>(Wo, wohi, wolo, DD * DD);

    cudaFuncSetAttribute(gemm_qkv_rope, cudaFuncAttributeMaxDynamicSharedMemorySize,
                         GSM_TOTAL);
    cudaFuncSetAttribute(gemm_bf16x3_v4, cudaFuncAttributeMaxDynamicSharedMemorySize,
                         GSM_TOTAL);

    // QKV = x @ Wqkv with fused bias + RoPE + split epilogue
    gemm_qkv_rope<<<dim3(NQKV / 128, M / 128), blk, GSM_TOTAL>>>(
        xhi, xlo, wqkvhi, wqkvlo, gbqkv, gc, gs, qkvhi, qkvlo, M, NQKV, 1024);

    cudaFuncSetAttribute(flash_tc_v3, cudaFuncAttributeMaxDynamicSharedMemorySize,
                         F3_SMEM_TOTAL);
    flash_tc_v3<<<dim3(SS / 64, KHH * 2, BB), 256, F3_SMEM_TOTAL>>>(qkvhi, qkvlo, ohi, olo);

    // out = attn_out @ Wo, then bias
    gemm_bf16x3_v4<<<dim3(1024 / 128, M / 128), blk, GSM_TOTAL>>>(
        ohi, olo, wohi, wolo, out, M, 1024, 1024);
    bias_add_kernel<<<(nx + 255) / 256, 256>>>(out, bo, nx);
}

// round 13
// speedup vs baseline: 1.6279x; 1.0634x over previous
#include <cuda_runtime.h>
#include <cuda_bf16.h>
#include <mma.h>
#include <math.h>
#include <cstdint>

using namespace nvcuda;

#define BB 2
#define SS 2048
#define DD 1024
#define HH 16
#define KHH 4
#define DKK 64
#define REP 4
#define NQKV 1536   // 1024 Q | 256 K | 256 V

// fp32 scratch
__device__ float g_cos[SS * 32];
__device__ float g_sin[SS * 32];
__device__ float g_bqkv[NQKV];

// bf16 split scratch
__device__ __nv_bfloat16 g_xhi[BB * SS * DD],    g_xlo[BB * SS * DD];
__device__ __nv_bfloat16 g_ohi[BB * SS * DD],    g_olo[BB * SS * DD];
__device__ __nv_bfloat16 g_wqkvhi[DD * NQKV],    g_wqkvlo[DD * NQKV];
__device__ __nv_bfloat16 g_wohi[DD * DD],        g_wolo[DD * DD];
__device__ __nv_bfloat16 g_qkvhi[BB * SS * NQKV], g_qkvlo[BB * SS * NQKV];

// ---------------------------------------------------------------------------
// cp.async helpers
// ---------------------------------------------------------------------------
__device__ __forceinline__ void cp_async16(void* sptr, const void* gptr) {
    unsigned int s = (unsigned int)__cvta_generic_to_shared(sptr);
    asm volatile("cp.async.cg.shared.global [%0], [%1], 16;\n" :: "r"(s), "l"(gptr));
}
__device__ __forceinline__ void cp_commit() { asm volatile("cp.async.commit_group;\n"); }
__device__ __forceinline__ void cp_wait1() { asm volatile("cp.async.wait_group 1;\n"); }
__device__ __forceinline__ void cp_wait0() { asm volatile("cp.async.wait_group 0;\n"); }

// ---------------------------------------------------------------------------
// Small kernels
// ---------------------------------------------------------------------------
__global__ void split_kernel(const float* __restrict__ in,
                             __nv_bfloat16* __restrict__ hi,
                             __nv_bfloat16* __restrict__ lo, int n) {
    int i = blockIdx.x * blockDim.x + threadIdx.x;
    if (i >= n) return;
    float f = in[i];
    __nv_bfloat16 h = __float2bfloat16(f);
    hi[i] = h;
    lo[i] = __float2bfloat16(f - __bfloat162float(h));
}

__global__ void pack_wqkv_kernel(const float* __restrict__ Wq, const float* __restrict__ Wk,
                                 const float* __restrict__ Wv, const float* __restrict__ bq,
                                 const float* __restrict__ bk, const float* __restrict__ bv,
                                 __nv_bfloat16* __restrict__ hi, __nv_bfloat16* __restrict__ lo,
                                 float* __restrict__ bqkv) {
    int i = blockIdx.x * blockDim.x + threadIdx.x;
    int n = DD * NQKV;
    if (i < NQKV) {
        int c = i;
        bqkv[c] = (c < 1024) ? bq[c] : (c < 1280 ? bk[c - 1024] : bv[c - 1280]);
    }
    if (i >= n) return;
    int row = i / NQKV;
    int col = i % NQKV;
    float f;
    if (col < 1024)      f = Wq[row * 1024 + col];
    else if (col < 1280) f = Wk[row * 256 + col - 1024];
    else                 f = Wv[row * 256 + col - 1280];
    __nv_bfloat16 h = __float2bfloat16(f);
    hi[i] = h;
    lo[i] = __float2bfloat16(f - __bfloat162float(h));
}

__global__ void rope_table_kernel(float* __restrict__ ctab, float* __restrict__ stab) {
    int idx = blockIdx.x * blockDim.x + threadIdx.x;
    if (idx >= SS * 32) return;
    int s = idx >> 5;
    int d = idx & 31;
    double theta = pow(10000.0, -(double)d / 32.0);
    double f = (double)s * theta;
    ctab[idx] = (float)cos(f);
    stab[idx] = (float)sin(f);
}

// ---------------------------------------------------------------------------
// Shared GEMM config (v4 mainloop): 128x128 block, 128 threads = 4 warps
// (2m x 2n), warp tile 64x64, BK=32 double-buffered cp.async, 2 CTAs/SM.
// ---------------------------------------------------------------------------
#define GSM_A_BYTES (2 * 2 * 128 * 40 * 2)
#define GSM_B_BYTES (2 * 2 * 32 * 136 * 2)
#define GSM_TOTAL (GSM_A_BYTES + GSM_B_BYTES)

__device__ __forceinline__ int sA_idx(int buf, int part, int r, int c) {
    return ((buf * 2 + part) * 128 + r) * 40 + c;
}
__device__ __forceinline__ int sB_idx(int buf, int part, int r, int c) {
    return ((buf * 2 + part) * 32 + r) * 136 + c;
}

struct GemmCtx {
    const __nv_bfloat16 *Ahi, *Alo, *Bhi, *Blo;
    int M, N, K, m0, n0, tid;
    __nv_bfloat16 *sA, *sB;
};

__device__ __forceinline__ void gemm_mainloop(
    GemmCtx& g, wmma::fragment<wmma::accumulator, 16, 16, 16, float> (&acc)[4][4],
    int wm, int wn) {
    const int nk = g.K / 32;
    auto load_stage = [&](int buf, int k0) {
#pragma unroll
        for (int t = g.tid; t < 1024; t += 128) {
            int part = t >> 9;
            int c = t & 511;
            int r = c >> 2;
            int cc = (c & 3) * 8;
            size_t gm = (size_t)(g.m0 + r) * g.K + k0 + cc;
            cp_async16(&g.sA[sA_idx(buf, part, r, cc)], part ? &g.Alo[gm] : &g.Ahi[gm]);
        }
#pragma unroll
        for (int t = g.tid; t < 1024; t += 128) {
            int part = t >> 9;
            int c = t & 511;
            int r = c >> 4;
            int cc = (c & 15) * 8;
            size_t gm = (size_t)(k0 + r) * g.N + g.n0 + cc;
            cp_async16(&g.sB[sB_idx(buf, part, r, cc)], part ? &g.Blo[gm] : &g.Bhi[gm]);
        }
        cp_commit();
    };

    load_stage(0, 0);

    for (int kt = 0; kt < nk; kt++) {
        int buf = kt & 1;
        if (kt + 1 < nk) {
            load_stage(buf ^ 1, (kt + 1) * 32);
            cp_wait1();
        } else {
            cp_wait0();
        }
        __syncthreads();

#pragma unroll
        for (int ks = 0; ks < 2; ks++) {
            wmma::fragment<wmma::matrix_a, 16, 16, 16, __nv_bfloat16, wmma::row_major> ahi[4], alo[4];
#pragma unroll
            for (int i = 0; i < 4; i++) {
                wmma::load_matrix_sync(ahi[i], &g.sA[sA_idx(buf, 0, wm * 64 + i * 16, ks * 16)], 40);
                wmma::load_matrix_sync(alo[i], &g.sA[sA_idx(buf, 1, wm * 64 + i * 16, ks * 16)], 40);
            }
#pragma unroll
            for (int j = 0; j < 4; j++) {
                wmma::fragment<wmma::matrix_b, 16, 16, 16, __nv_bfloat16, wmma::row_major> bhi, blo;
                wmma::load_matrix_sync(bhi, &g.sB[sB_idx(buf, 0, ks * 16, wn * 64 + j * 16)], 136);
                wmma::load_matrix_sync(blo, &g.sB[sB_idx(buf, 1, ks * 16, wn * 64 + j * 16)], 136);
#pragma unroll
                for (int i = 0; i < 4; i++) {
                    wmma::mma_sync(acc[i][j], ahi[i], bhi, acc[i][j]);
                    wmma::mma_sync(acc[i][j], ahi[i], blo, acc[i][j]);
                    wmma::mma_sync(acc[i][j], alo[i], bhi, acc[i][j]);
                }
            }
        }
        __syncthreads();
    }
}

// ---------------------------------------------------------------------------
// QKV GEMM with fused bias + RoPE + bf16 hi/lo split epilogue. m_off selects
// the batch's row range so the two batches run on separate streams.
// ---------------------------------------------------------------------------
__global__ __launch_bounds__(128, 2)
void gemm_qkv_rope(const __nv_bfloat16* __restrict__ Ahi,
                   const __nv_bfloat16* __restrict__ Alo,
                   const __nv_bfloat16* __restrict__ Bhi,
                   const __nv_bfloat16* __restrict__ Blo,
                   const float* __restrict__ bias,
                   const float* __restrict__ ctab,
                   const float* __restrict__ stab,
                   __nv_bfloat16* __restrict__ ohi,
                   __nv_bfloat16* __restrict__ olo,
                   int M, int N, int K, int m_off) {
    extern __shared__ __align__(16) unsigned char smraw[];
    GemmCtx g;
    g.Ahi = Ahi; g.Alo = Alo; g.Bhi = Bhi; g.Blo = Blo;
    g.M = M; g.N = N; g.K = K;
    g.tid = threadIdx.x;
    g.m0 = m_off + blockIdx.y * 128;
    g.n0 = blockIdx.x * 128;
    g.sA = (__nv_bfloat16*)smraw;
    g.sB = (__nv_bfloat16*)(smraw + GSM_A_BYTES);

    const int warp = threadIdx.x >> 5;
    const int lane = threadIdx.x & 31;
    const int wm = warp >> 1;
    const int wn = warp & 1;

    wmma::fragment<wmma::accumulator, 16, 16, 16, float> acc[4][4];
#pragma unroll
    for (int i = 0; i < 4; i++)
#pragma unroll
        for (int j = 0; j < 4; j++) wmma::fill_fragment(acc[i][j], 0.0f);

    gemm_mainloop(g, acc, wm, wn);

    float* stg = (float*)(smraw) + warp * (64 * 68);
#pragma unroll
    for (int i = 0; i < 4; i++)
#pragma unroll
        for (int j = 0; j < 4; j++)
            wmma::store_matrix_sync(&stg[(i * 16) * 68 + j * 16], acc[i][j], 68,
                                    wmma::mem_row_major);
    __syncwarp();

    const int col_base = g.n0 + wn * 64;
    const int row_base = g.m0 + wm * 64;

    if (col_base < 1280) {
        for (int t = lane; t < 2048; t += 32) {
            int r = t >> 5;
            int d = t & 31;
            float x1 = stg[r * 68 + d] + bias[col_base + d];
            float x2 = stg[r * 68 + d + 32] + bias[col_base + d + 32];
            int grow = row_base + r;
            int s = grow & (SS - 1);
            float c = ctab[s * 32 + d];
            float sn = stab[s * 32 + d];
            float r1 = x1 * c - x2 * sn;
            float r2 = x2 * c + x1 * sn;
            size_t base = (size_t)grow * NQKV + col_base + d;
            __nv_bfloat16 h1 = __float2bfloat16(r1);
            __nv_bfloat16 h2 = __float2bfloat16(r2);
            ohi[base] = h1;
            olo[base] = __float2bfloat16(r1 - __bfloat162float(h1));
            ohi[base + 32] = h2;
            olo[base + 32] = __float2bfloat16(r2 - __bfloat162float(h2));
        }
    } else {
        for (int t = lane; t < 4096; t += 32) {
            int r = t >> 6;
            int d = t & 63;
            float f = stg[r * 68 + d] + bias[col_base + d];
            size_t base = (size_t)(row_base + r) * NQKV + col_base + d;
            __nv_bfloat16 h = __float2bfloat16(f);
            ohi[base] = h;
            olo[base] = __float2bfloat16(f - __bfloat162float(h));
        }
    }
}

// ---------------------------------------------------------------------------
// Output-projection GEMM with fused bias epilogue (fp32 out, m_off for batch)
// ---------------------------------------------------------------------------
__global__ __launch_bounds__(128, 2)
void gemm_out_bias(const __nv_bfloat16* __restrict__ Ahi,
                   const __nv_bfloat16* __restrict__ Alo,
                   const __nv_bfloat16* __restrict__ Bhi,
                   const __nv_bfloat16* __restrict__ Blo,
                   const float* __restrict__ bias,
                   float* __restrict__ C, int M, int N, int K, int m_off) {
    extern __shared__ __align__(16) unsigned char smraw[];
    GemmCtx g;
    g.Ahi = Ahi; g.Alo = Alo; g.Bhi = Bhi; g.Blo = Blo;
    g.M = M; g.N = N; g.K = K;
    g.tid = threadIdx.x;
    g.m0 = m_off + blockIdx.y * 128;
    g.n0 = blockIdx.x * 128;
    g.sA = (__nv_bfloat16*)smraw;
    g.sB = (__nv_bfloat16*)(smraw + GSM_A_BYTES);

    const int warp = threadIdx.x >> 5;
    const int lane = threadIdx.x & 31;
    const int wm = warp >> 1;
    const int wn = warp & 1;

    wmma::fragment<wmma::accumulator, 16, 16, 16, float> acc[4][4];
#pragma unroll
    for (int i = 0; i < 4; i++)
#pragma unroll
        for (int j = 0; j < 4; j++) wmma::fill_fragment(acc[i][j], 0.0f);

    gemm_mainloop(g, acc, wm, wn);

    float* stg = (float*)(smraw) + warp * (64 * 68);
#pragma unroll
    for (int i = 0; i < 4; i++)
#pragma unroll
        for (int j = 0; j < 4; j++)
            wmma::store_matrix_sync(&stg[(i * 16) * 68 + j * 16], acc[i][j], 68,
                                    wmma::mem_row_major);
    __syncwarp();

    const int col_base = g.n0 + wn * 64;
    const int row_base = g.m0 + wm * 64;
    for (int t = lane; t < 4096; t += 32) {
        int r = t >> 6;
        int d = t & 63;
        C[(size_t)(row_base + r) * g.N + col_base + d] =
            stg[r * 68 + d] + bias[col_base + d];
    }
}

// ---------------------------------------------------------------------------
// flash_tc_v3 (R10-known-good), batch passed as parameter for stream split.
// ---------------------------------------------------------------------------
#define F3_QHI 0
#define F3_QLO 18432
#define F3_KHI 36864
#define F3_KLO 46080
#define F3_VHI 55296
#define F3_VLO 64512
#define F3_SFP 73728
#define F3_PHI 73728
#define F3_PLO 92160
#define F3_M   110592
#define F3_L   111104
#define F3_AL  111616
#define F3_SMEM_TOTAL 112128

__global__ __launch_bounds__(256, 2)
void flash_tc_v3(const __nv_bfloat16* __restrict__ qh,
                 const __nv_bfloat16* __restrict__ ql,
                 __nv_bfloat16* __restrict__ ohi,
                 __nv_bfloat16* __restrict__ olo, int b) {
    extern __shared__ __align__(16) unsigned char fsm[];
    __nv_bfloat16* Qhi = (__nv_bfloat16*)(fsm + F3_QHI);
    __nv_bfloat16* Qlo = (__nv_bfloat16*)(fsm + F3_QLO);
    __nv_bfloat16* Khi = (__nv_bfloat16*)(fsm + F3_KHI);
    __nv_bfloat16* Klo = (__nv_bfloat16*)(fsm + F3_KLO);
    __nv_bfloat16* Vhi = (__nv_bfloat16*)(fsm + F3_VHI);
    __nv_bfloat16* Vlo = (__nv_bfloat16*)(fsm + F3_VLO);
    float* Sf  = (float*)(fsm + F3_SFP);
    __nv_bfloat16* Phi = (__nv_bfloat16*)(fsm + F3_PHI);
    __nv_bfloat16* Plo = (__nv_bfloat16*)(fsm + F3_PLO);
    float* m_sh = (float*)(fsm + F3_M);
    float* l_sh = (float*)(fsm + F3_L);
    float* al_sh= (float*)(fsm + F3_AL);

    const int tid = threadIdx.x;
    const int warp = tid >> 5;
    const int qt = (int)gridDim.x - 1 - (int)blockIdx.x;
    const int kh = blockIdx.y >> 1;
    const int pair = blockIdx.y & 1;
    const int s0q = qt * 64;
    const int m0w = warp * 16;

    __nv_bfloat16* kvdst[4] = {Khi, Klo, Vhi, Vlo};
    auto load_kv = [&](int s0k) {
        for (int t = tid; t < 2048; t += 256) {
            int arr = t >> 9;
            int r = (t >> 3) & 63;
            int ch = (t & 7) * 8;
            const __nv_bfloat16* src = (arr & 1) ? ql : qh;
            size_t g = (size_t)(b * SS + s0k + r) * NQKV + 1024 + kh * 64 +
                       ((arr >> 1) ? 256 : 0) + ch;
            cp_async16(&kvdst[arr][r * 72 + ch], &src[g]);
        }
        cp_commit();
    };

    load_kv(0);

    for (int t = tid; t < 2048; t += 256) {
        int part = t >> 10;
        int m = (t >> 3) & 127;
        int ch = (t & 7) * 8;
        int hp = m >> 6;
        int rr = m & 63;
        const __nv_bfloat16* src = part ? ql : qh;
        size_t gaddr = (size_t)(b * SS + s0q + rr) * NQKV +
                       (kh * 4 + pair * 2 + hp) * 64 + ch;
        __nv_bfloat16* dst = part ? Qlo : Qhi;
        *reinterpret_cast<uint4*>(&dst[m * 72 + ch]) =
            *reinterpret_cast<const uint4*>(&src[gaddr]);
    }
    if (tid < 128) { m_sh[tid] = -1e30f; l_sh[tid] = 0.0f; }

    const int srow = tid >> 1;
    const int sc0 = (tid & 1) * 32;
    const int srr = srow & 63;
    float ov[32];
#pragma unroll
    for (int i = 0; i < 32; i++) ov[i] = 0.0f;

    for (int kt = 0; kt <= qt; kt++) {
        const int s0k = kt * 64;
        cp_wait0();
        __syncthreads();

        {
            wmma::fragment<wmma::accumulator, 16, 16, 16, float> accs[4];
#pragma unroll
            for (int j = 0; j < 4; j++) wmma::fill_fragment(accs[j], 0.0f);
#pragma unroll
            for (int ks = 0; ks < 4; ks++) {
                wmma::fragment<wmma::matrix_a, 16, 16, 16, __nv_bfloat16, wmma::row_major> a_hi, a_lo;
                wmma::load_matrix_sync(a_hi, &Qhi[m0w * 72 + ks * 16], 72);
                wmma::load_matrix_sync(a_lo, &Qlo[m0w * 72 + ks * 16], 72);
#pragma unroll
                for (int j = 0; j < 4; j++) {
                    wmma::fragment<wmma::matrix_b, 16, 16, 16, __nv_bfloat16, wmma::col_major> b_hi, b_lo;
                    wmma::load_matrix_sync(b_hi, &Khi[(j * 16) * 72 + ks * 16], 72);
                    wmma::load_matrix_sync(b_lo, &Klo[(j * 16) * 72 + ks * 16], 72);
                    wmma::mma_sync(accs[j], a_hi, b_hi, accs[j]);
                    wmma::mma_sync(accs[j], a_hi, b_lo, accs[j]);
                    wmma::mma_sync(accs[j], a_lo, b_hi, accs[j]);
                }
            }
#pragma unroll
            for (int j = 0; j < 4; j++)
                wmma::store_matrix_sync(&Sf[m0w * 68 + j * 16], accs[j], 68, wmma::mem_row_major);
        }
        __syncthreads();

        float sv[32];
        {
            float vmax = -1e30f;
#pragma unroll
            for (int i = 0; i < 32; i++) {
                float s = Sf[srow * 68 + sc0 + i] * 0.125f;
                if (s0k + sc0 + i > s0q + srr) s = -1e30f;
                sv[i] = s;
                vmax = fmaxf(vmax, s);
            }
            vmax = fmaxf(vmax, __shfl_xor_sync(0xffffffffu, vmax, 1));
            float mo = m_sh[srow];
            float mx = fmaxf(mo, vmax);
            float al = __expf(mo - mx);
            __syncthreads();
            float sum = 0.0f;
#pragma unroll
            for (int i = 0; i < 32; i++) {
                float p = __expf(sv[i] - mx);
                sum += p;
                __nv_bfloat16 ph = __float2bfloat16(p);
                Phi[srow * 72 + sc0 + i] = ph;
                Plo[srow * 72 + sc0 + i] = __float2bfloat16(p - __bfloat162float(ph));
            }
            sum += __shfl_xor_sync(0xffffffffu, sum, 1);
            if ((tid & 1) == 0) {
                m_sh[srow] = mx;
                l_sh[srow] = l_sh[srow] * al + sum;
                al_sh[srow] = al;
            }
        }
        __syncthreads();

        {
            wmma::fragment<wmma::accumulator, 16, 16, 16, float> acco[4];
#pragma unroll
            for (int j = 0; j < 4; j++) wmma::fill_fragment(acco[j], 0.0f);
#pragma unroll
            for (int ks = 0; ks < 4; ks++) {
                wmma::fragment<wmma::matrix_a, 16, 16, 16, __nv_bfloat16, wmma::row_major> p_hi, p_lo;
                wmma::load_matrix_sync(p_hi, &Phi[m0w * 72 + ks * 16], 72);
                wmma::load_matrix_sync(p_lo, &Plo[m0w * 72 + ks * 16], 72);
#pragma unroll
                for (int j = 0; j < 4; j++) {
                    wmma::fragment<wmma::matrix_b, 16, 16, 16, __nv_bfloat16, wmma::row_major> v_hi, v_lo;
                    wmma::load_matrix_sync(v_hi, &Vhi[(ks * 16) * 72 + j * 16], 72);
                    wmma::load_matrix_sync(v_lo, &Vlo[(ks * 16) * 72 + j * 16], 72);
                    wmma::mma_sync(acco[j], p_hi, v_hi, acco[j]);
                    wmma::mma_sync(acco[j], p_hi, v_lo, acco[j]);
                    wmma::mma_sync(acco[j], p_lo, v_hi, acco[j]);
                }
            }
            __syncthreads();

            if (kt < qt) load_kv(s0k + 64);

#pragma unroll
            for (int j = 0; j < 4; j++)
                wmma::store_matrix_sync(&Sf[m0w * 68 + j * 16], acco[j], 68, wmma::mem_row_major);
        }
        __syncthreads();

        {
            float al = al_sh[srow];
#pragma unroll
            for (int i = 0; i < 32; i++)
                ov[i] = ov[i] * al + Sf[srow * 68 + sc0 + i];
        }
    }

    float invl = 1.0f / l_sh[srow];
    int hp = srow >> 6;
#pragma unroll
    for (int i = 0; i < 32; i++) {
        float f = ov[i] * invl;
        size_t oaddr = (size_t)(b * SS + s0q + srr) * DD +
                       (kh * 4 + pair * 2 + hp) * 64 + sc0 + i;
        __nv_bfloat16 h = __float2bfloat16(f);
        ohi[oaddr] = h;
        olo[oaddr] = __float2bfloat16(f - __bfloat162float(h));
    }
}

// ---------------------------------------------------------------------------
// Launch: preprocessing on origin stream, then batch-pipelined fork/join.
// ---------------------------------------------------------------------------
extern "C" void kernel_launch(void* const* d_in, const int* in_sizes, int n_in,
                              void* d_out, int out_size) {
    const float* x  = (const float*)d_in[0];
    const float* Wq = (const float*)d_in[2];
    const float* bq = (const float*)d_in[3];
    const float* Wk = (const float*)d_in[4];
    const float* bk = (const float*)d_in[5];
    const float* Wv = (const float*)d_in[6];
    const float* bv = (const float*)d_in[7];
    const float* Wo = (const float*)d_in[8];
    const float* bo = (const float*)d_in[9];
    float* out = (float*)d_out;

    float *gc, *gs, *gbqkv;
    cudaGetSymbolAddress((void**)&gc, g_cos);
    cudaGetSymbolAddress((void**)&gs, g_sin);
    cudaGetSymbolAddress((void**)&gbqkv, g_bqkv);

    __nv_bfloat16 *xhi, *xlo, *ohi, *olo, *wqkvhi, *wqkvlo, *wohi, *wolo, *qkvhi, *qkvlo;
    cudaGetSymbolAddress((void**)&xhi, g_xhi);
    cudaGetSymbolAddress((void**)&xlo, g_xlo);
    cudaGetSymbolAddress((void**)&ohi, g_ohi);
    cudaGetSymbolAddress((void**)&olo, g_olo);
    cudaGetSymbolAddress((void**)&wqkvhi, g_wqkvhi);
    cudaGetSymbolAddress((void**)&wqkvlo, g_wqkvlo);
    cudaGetSymbolAddress((void**)&wohi, g_wohi);
    cudaGetSymbolAddress((void**)&wolo, g_wolo);
    cudaGetSymbolAddress((void**)&qkvhi, g_qkvhi);
    cudaGetSymbolAddress((void**)&qkvlo, g_qkvlo);

    // One-time stream/event setup (host resources only; created outside capture
    // on the first correctness call).
    static cudaStream_t s2 = nullptr;
    static cudaEvent_t eFork = nullptr, eJoin = nullptr;
    static bool attr_set = false;
    if (s2 == nullptr) {
        cudaStreamCreateWithFlags(&s2, cudaStreamNonBlocking);
        cudaEventCreateWithFlags(&eFork, cudaEventDisableTiming);
        cudaEventCreateWithFlags(&eJoin, cudaEventDisableTiming);
    }
    if (!attr_set) {
        cudaFuncSetAttribute(gemm_qkv_rope, cudaFuncAttributeMaxDynamicSharedMemorySize,
                             GSM_TOTAL);
        cudaFuncSetAttribute(gemm_out_bias, cudaFuncAttributeMaxDynamicSharedMemorySize,
                             GSM_TOTAL);
        cudaFuncSetAttribute(flash_tc_v3, cudaFuncAttributeMaxDynamicSharedMemorySize,
                             F3_SMEM_TOTAL);
        attr_set = true;
    }

    const int M = BB * SS;   // 4096
    const int MB = SS;       // rows per batch = 2048
    dim3 blk(128);

    // ---- preprocessing on origin stream ----
    rope_table_kernel<<<(SS * 32 + 255) / 256, 256>>>(gc, gs);
    int nx = M * DD;
    split_kernel<<<(nx + 255) / 256, 256>>>(x, xhi, xlo, nx);
    pack_wqkv_kernel<<<(DD * NQKV + 255) / 256, 256>>>(Wq, Wk, Wv, bq, bk, bv,
                                                       wqkvhi, wqkvlo, gbqkv);
    split_kernel<<<(DD * DD + 255) / 256, 256>>>(Wo, wohi, wolo, DD * DD);

    // ---- fork: batch 1 pipeline on s2 ----
    cudaEventRecord(eFork, 0);
    cudaStreamWaitEvent(s2, eFork, 0);

    // batch 0 (origin stream)
    gemm_qkv_rope<<<dim3(NQKV / 128, MB / 128), blk, GSM_TOTAL>>>(
        xhi, xlo, wqkvhi, wqkvlo, gbqkv, gc, gs, qkvhi, qkvlo, M, NQKV, 1024, 0);
    flash_tc_v3<<<dim3(SS / 64, KHH * 2, 1), 256, F3_SMEM_TOTAL>>>(
        qkvhi, qkvlo, ohi, olo, 0);
    gemm_out_bias<<<dim3(1024 / 128, MB / 128), blk, GSM_TOTAL>>>(
        ohi, olo, wohi, wolo, bo, out, M, 1024, 1024, 0);

    // batch 1 (s2)
    gemm_qkv_rope<<<dim3(NQKV / 128, MB / 128), blk, GSM_TOTAL, s2>>>(
        xhi, xlo, wqkvhi, wqkvlo, gbqkv, gc, gs, qkvhi, qkvlo, M, NQKV, 1024, MB);
    flash_tc_v3<<<dim3(SS / 64, KHH * 2, 1), 256, F3_SMEM_TOTAL, s2>>>(
        qkvhi, qkvlo, ohi, olo, 1);
    gemm_out_bias<<<dim3(1024 / 128, MB / 128), blk, GSM_TOTAL, s2>>>(
        ohi, olo, wohi, wolo, bo, out, M, 1024, 1024, MB);

    // ---- join ----
    cudaEventRecord(eJoin, s2);
    cudaStreamWaitEvent(0, eJoin, 0);
}

// round 14
// speedup vs baseline: 1.6540x; 1.0160x over previous
#include <cuda_runtime.h>
#include <cuda_bf16.h>
#include <mma.h>
#include <math.h>
#include <cstdint>

using namespace nvcuda;

#define BB 2
#define SS 2048
#define DD 1024
#define HH 16
#define KHH 4
#define DKK 64
#define REP 4
#define NQKV 1536   // 1024 Q | 256 K | 256 V

// fp32 scratch
__device__ float g_cos[SS * 32];
__device__ float g_sin[SS * 32];
__device__ float g_bqkv[NQKV];

// bf16 split scratch
__device__ __nv_bfloat16 g_xhi[BB * SS * DD],    g_xlo[BB * SS * DD];
__device__ __nv_bfloat16 g_ohi[BB * SS * DD],    g_olo[BB * SS * DD];
__device__ __nv_bfloat16 g_wqkvhi[DD * NQKV],    g_wqkvlo[DD * NQKV];
__device__ __nv_bfloat16 g_wohi[DD * DD],        g_wolo[DD * DD];
__device__ __nv_bfloat16 g_qkvhi[BB * SS * NQKV], g_qkvlo[BB * SS * NQKV];

// ---------------------------------------------------------------------------
// cp.async helpers
// ---------------------------------------------------------------------------
__device__ __forceinline__ void cp_async16(void* sptr, const void* gptr) {
    unsigned int s = (unsigned int)__cvta_generic_to_shared(sptr);
    asm volatile("cp.async.cg.shared.global [%0], [%1], 16;\n" :: "r"(s), "l"(gptr));
}
__device__ __forceinline__ void cp_commit() { asm volatile("cp.async.commit_group;\n"); }
__device__ __forceinline__ void cp_wait1() { asm volatile("cp.async.wait_group 1;\n"); }
__device__ __forceinline__ void cp_wait0() { asm volatile("cp.async.wait_group 0;\n"); }

// ---------------------------------------------------------------------------
// Small kernels
// ---------------------------------------------------------------------------
__global__ void split_kernel(const float* __restrict__ in,
                             __nv_bfloat16* __restrict__ hi,
                             __nv_bfloat16* __restrict__ lo, int n) {
    int i = blockIdx.x * blockDim.x + threadIdx.x;
    if (i >= n) return;
    float f = in[i];
    __nv_bfloat16 h = __float2bfloat16(f);
    hi[i] = h;
    lo[i] = __float2bfloat16(f - __bfloat162float(h));
}

__global__ void pack_wqkv_kernel(const float* __restrict__ Wq, const float* __restrict__ Wk,
                                 const float* __restrict__ Wv, const float* __restrict__ bq,
                                 const float* __restrict__ bk, const float* __restrict__ bv,
                                 __nv_bfloat16* __restrict__ hi, __nv_bfloat16* __restrict__ lo,
                                 float* __restrict__ bqkv) {
    int i = blockIdx.x * blockDim.x + threadIdx.x;
    int n = DD * NQKV;
    if (i < NQKV) {
        int c = i;
        bqkv[c] = (c < 1024) ? bq[c] : (c < 1280 ? bk[c - 1024] : bv[c - 1280]);
    }
    if (i >= n) return;
    int row = i / NQKV;
    int col = i % NQKV;
    float f;
    if (col < 1024)      f = Wq[row * 1024 + col];
    else if (col < 1280) f = Wk[row * 256 + col - 1024];
    else                 f = Wv[row * 256 + col - 1280];
    __nv_bfloat16 h = __float2bfloat16(f);
    hi[i] = h;
    lo[i] = __float2bfloat16(f - __bfloat162float(h));
}

__global__ void rope_table_kernel(float* __restrict__ ctab, float* __restrict__ stab) {
    int idx = blockIdx.x * blockDim.x + threadIdx.x;
    if (idx >= SS * 32) return;
    int s = idx >> 5;
    int d = idx & 31;
    double theta = pow(10000.0, -(double)d / 32.0);
    double f = (double)s * theta;
    ctab[idx] = (float)cos(f);
    stab[idx] = (float)sin(f);
}

// ---------------------------------------------------------------------------
// Shared GEMM config (v4 mainloop): 128x128 block, 128 threads = 4 warps
// (2m x 2n), warp tile 64x64, BK=32 double-buffered cp.async, 2 CTAs/SM.
// ---------------------------------------------------------------------------
#define GSM_A_BYTES (2 * 2 * 128 * 40 * 2)
#define GSM_B_BYTES (2 * 2 * 32 * 136 * 2)
#define GSM_TOTAL (GSM_A_BYTES + GSM_B_BYTES)

__device__ __forceinline__ int sA_idx(int buf, int part, int r, int c) {
    return ((buf * 2 + part) * 128 + r) * 40 + c;
}
__device__ __forceinline__ int sB_idx(int buf, int part, int r, int c) {
    return ((buf * 2 + part) * 32 + r) * 136 + c;
}

struct GemmCtx {
    const __nv_bfloat16 *Ahi, *Alo, *Bhi, *Blo;
    int M, N, K, m0, n0, tid;
    __nv_bfloat16 *sA, *sB;
};

__device__ __forceinline__ void gemm_mainloop(
    GemmCtx& g, wmma::fragment<wmma::accumulator, 16, 16, 16, float> (&acc)[4][4],
    int wm, int wn) {
    const int nk = g.K / 32;
    auto load_stage = [&](int buf, int k0) {
#pragma unroll
        for (int t = g.tid; t < 1024; t += 128) {
            int part = t >> 9;
            int c = t & 511;
            int r = c >> 2;
            int cc = (c & 3) * 8;
            size_t gm = (size_t)(g.m0 + r) * g.K + k0 + cc;
            cp_async16(&g.sA[sA_idx(buf, part, r, cc)], part ? &g.Alo[gm] : &g.Ahi[gm]);
        }
#pragma unroll
        for (int t = g.tid; t < 1024; t += 128) {
            int part = t >> 9;
            int c = t & 511;
            int r = c >> 4;
            int cc = (c & 15) * 8;
            size_t gm = (size_t)(k0 + r) * g.N + g.n0 + cc;
            cp_async16(&g.sB[sB_idx(buf, part, r, cc)], part ? &g.Blo[gm] : &g.Bhi[gm]);
        }
        cp_commit();
    };

    load_stage(0, 0);

    for (int kt = 0; kt < nk; kt++) {
        int buf = kt & 1;
        if (kt + 1 < nk) {
            load_stage(buf ^ 1, (kt + 1) * 32);
            cp_wait1();
        } else {
            cp_wait0();
        }
        __syncthreads();

#pragma unroll
        for (int ks = 0; ks < 2; ks++) {
            wmma::fragment<wmma::matrix_a, 16, 16, 16, __nv_bfloat16, wmma::row_major> ahi[4], alo[4];
#pragma unroll
            for (int i = 0; i < 4; i++) {
                wmma::load_matrix_sync(ahi[i], &g.sA[sA_idx(buf, 0, wm * 64 + i * 16, ks * 16)], 40);
                wmma::load_matrix_sync(alo[i], &g.sA[sA_idx(buf, 1, wm * 64 + i * 16, ks * 16)], 40);
            }
#pragma unroll
            for (int j = 0; j < 4; j++) {
                wmma::fragment<wmma::matrix_b, 16, 16, 16, __nv_bfloat16, wmma::row_major> bhi, blo;
                wmma::load_matrix_sync(bhi, &g.sB[sB_idx(buf, 0, ks * 16, wn * 64 + j * 16)], 136);
                wmma::load_matrix_sync(blo, &g.sB[sB_idx(buf, 1, ks * 16, wn * 64 + j * 16)], 136);
#pragma unroll
                for (int i = 0; i < 4; i++) {
                    wmma::mma_sync(acc[i][j], ahi[i], bhi, acc[i][j]);
                    wmma::mma_sync(acc[i][j], ahi[i], blo, acc[i][j]);
                    wmma::mma_sync(acc[i][j], alo[i], bhi, acc[i][j]);
                }
            }
        }
        __syncthreads();
    }
}

// ---------------------------------------------------------------------------
// QKV GEMM with fused bias + RoPE + bf16 hi/lo split epilogue. m_off selects
// the batch's row range so the two batches run on separate streams.
// ---------------------------------------------------------------------------
__global__ __launch_bounds__(128, 2)
void gemm_qkv_rope(const __nv_bfloat16* __restrict__ Ahi,
                   const __nv_bfloat16* __restrict__ Alo,
                   const __nv_bfloat16* __restrict__ Bhi,
                   const __nv_bfloat16* __restrict__ Blo,
                   const float* __restrict__ bias,
                   const float* __restrict__ ctab,
                   const float* __restrict__ stab,
                   __nv_bfloat16* __restrict__ ohi,
                   __nv_bfloat16* __restrict__ olo,
                   int M, int N, int K, int m_off) {
    extern __shared__ __align__(16) unsigned char smraw[];
    GemmCtx g;
    g.Ahi = Ahi; g.Alo = Alo; g.Bhi = Bhi; g.Blo = Blo;
    g.M = M; g.N = N; g.K = K;
    g.tid = threadIdx.x;
    g.m0 = m_off + blockIdx.y * 128;
    g.n0 = blockIdx.x * 128;
    g.sA = (__nv_bfloat16*)smraw;
    g.sB = (__nv_bfloat16*)(smraw + GSM_A_BYTES);

    const int warp = threadIdx.x >> 5;
    const int lane = threadIdx.x & 31;
    const int wm = warp >> 1;
    const int wn = warp & 1;

    wmma::fragment<wmma::accumulator, 16, 16, 16, float> acc[4][4];
#pragma unroll
    for (int i = 0; i < 4; i++)
#pragma unroll
        for (int j = 0; j < 4; j++) wmma::fill_fragment(acc[i][j], 0.0f);

    gemm_mainloop(g, acc, wm, wn);

    float* stg = (float*)(smraw) + warp * (64 * 68);
#pragma unroll
    for (int i = 0; i < 4; i++)
#pragma unroll
        for (int j = 0; j < 4; j++)
            wmma::store_matrix_sync(&stg[(i * 16) * 68 + j * 16], acc[i][j], 68,
                                    wmma::mem_row_major);
    __syncwarp();

    const int col_base = g.n0 + wn * 64;
    const int row_base = g.m0 + wm * 64;

    if (col_base < 1280) {
        for (int t = lane; t < 2048; t += 32) {
            int r = t >> 5;
            int d = t & 31;
            float x1 = stg[r * 68 + d] + bias[col_base + d];
            float x2 = stg[r * 68 + d + 32] + bias[col_base + d + 32];
            int grow = row_base + r;
            int s = grow & (SS - 1);
            float c = ctab[s * 32 + d];
            float sn = stab[s * 32 + d];
            float r1 = x1 * c - x2 * sn;
            float r2 = x2 * c + x1 * sn;
            size_t base = (size_t)grow * NQKV + col_base + d;
            __nv_bfloat16 h1 = __float2bfloat16(r1);
            __nv_bfloat16 h2 = __float2bfloat16(r2);
            ohi[base] = h1;
            olo[base] = __float2bfloat16(r1 - __bfloat162float(h1));
            ohi[base + 32] = h2;
            olo[base + 32] = __float2bfloat16(r2 - __bfloat162float(h2));
        }
    } else {
        for (int t = lane; t < 4096; t += 32) {
            int r = t >> 6;
            int d = t & 63;
            float f = stg[r * 68 + d] + bias[col_base + d];
            size_t base = (size_t)(row_base + r) * NQKV + col_base + d;
            __nv_bfloat16 h = __float2bfloat16(f);
            ohi[base] = h;
            olo[base] = __float2bfloat16(f - __bfloat162float(h));
        }
    }
}

// ---------------------------------------------------------------------------
// Output-projection GEMM with fused bias epilogue (fp32 out, m_off for batch)
// ---------------------------------------------------------------------------
__global__ __launch_bounds__(128, 2)
void gemm_out_bias(const __nv_bfloat16* __restrict__ Ahi,
                   const __nv_bfloat16* __restrict__ Alo,
                   const __nv_bfloat16* __restrict__ Bhi,
                   const __nv_bfloat16* __restrict__ Blo,
                   const float* __restrict__ bias,
                   float* __restrict__ C, int M, int N, int K, int m_off) {
    extern __shared__ __align__(16) unsigned char smraw[];
    GemmCtx g;
    g.Ahi = Ahi; g.Alo = Alo; g.Bhi = Bhi; g.Blo = Blo;
    g.M = M; g.N = N; g.K = K;
    g.tid = threadIdx.x;
    g.m0 = m_off + blockIdx.y * 128;
    g.n0 = blockIdx.x * 128;
    g.sA = (__nv_bfloat16*)smraw;
    g.sB = (__nv_bfloat16*)(smraw + GSM_A_BYTES);

    const int warp = threadIdx.x >> 5;
    const int lane = threadIdx.x & 31;
    const int wm = warp >> 1;
    const int wn = warp & 1;

    wmma::fragment<wmma::accumulator, 16, 16, 16, float> acc[4][4];
#pragma unroll
    for (int i = 0; i < 4; i++)
#pragma unroll
        for (int j = 0; j < 4; j++) wmma::fill_fragment(acc[i][j], 0.0f);

    gemm_mainloop(g, acc, wm, wn);

    float* stg = (float*)(smraw) + warp * (64 * 68);
#pragma unroll
    for (int i = 0; i < 4; i++)
#pragma unroll
        for (int j = 0; j < 4; j++)
            wmma::store_matrix_sync(&stg[(i * 16) * 68 + j * 16], acc[i][j], 68,
                                    wmma::mem_row_major);
    __syncwarp();

    const int col_base = g.n0 + wn * 64;
    const int row_base = g.m0 + wm * 64;
    for (int t = lane; t < 4096; t += 32) {
        int r = t >> 6;
        int d = t & 63;
        C[(size_t)(row_base + r) * g.N + col_base + d] =
            stg[r * 68 + d] + bias[col_base + d];
    }
}

// ---------------------------------------------------------------------------
// flash_tc_v3 (R10-known-good), batch passed as parameter for stream split.
// ---------------------------------------------------------------------------
#define F3_QHI 0
#define F3_QLO 18432
#define F3_KHI 36864
#define F3_KLO 46080
#define F3_VHI 55296
#define F3_VLO 64512
#define F3_SFP 73728
#define F3_PHI 73728
#define F3_PLO 92160
#define F3_M   110592
#define F3_L   111104
#define F3_AL  111616
#define F3_SMEM_TOTAL 112128

__global__ __launch_bounds__(256, 2)
void flash_tc_v3(const __nv_bfloat16* __restrict__ qh,
                 const __nv_bfloat16* __restrict__ ql,
                 __nv_bfloat16* __restrict__ ohi,
                 __nv_bfloat16* __restrict__ olo, int b) {
    extern __shared__ __align__(16) unsigned char fsm[];
    __nv_bfloat16* Qhi = (__nv_bfloat16*)(fsm + F3_QHI);
    __nv_bfloat16* Qlo = (__nv_bfloat16*)(fsm + F3_QLO);
    __nv_bfloat16* Khi = (__nv_bfloat16*)(fsm + F3_KHI);
    __nv_bfloat16* Klo = (__nv_bfloat16*)(fsm + F3_KLO);
    __nv_bfloat16* Vhi = (__nv_bfloat16*)(fsm + F3_VHI);
    __nv_bfloat16* Vlo = (__nv_bfloat16*)(fsm + F3_VLO);
    float* Sf  = (float*)(fsm + F3_SFP);
    __nv_bfloat16* Phi = (__nv_bfloat16*)(fsm + F3_PHI);
    __nv_bfloat16* Plo = (__nv_bfloat16*)(fsm + F3_PLO);
    float* m_sh = (float*)(fsm + F3_M);
    float* l_sh = (float*)(fsm + F3_L);
    float* al_sh= (float*)(fsm + F3_AL);

    const int tid = threadIdx.x;
    const int warp = tid >> 5;
    const int qt = (int)gridDim.x - 1 - (int)blockIdx.x;
    const int kh = blockIdx.y >> 1;
    const int pair = blockIdx.y & 1;
    const int s0q = qt * 64;
    const int m0w = warp * 16;

    __nv_bfloat16* kvdst[4] = {Khi, Klo, Vhi, Vlo};
    auto load_kv = [&](int s0k) {
        for (int t = tid; t < 2048; t += 256) {
            int arr = t >> 9;
            int r = (t >> 3) & 63;
            int ch = (t & 7) * 8;
            const __nv_bfloat16* src = (arr & 1) ? ql : qh;
            size_t g = (size_t)(b * SS + s0k + r) * NQKV + 1024 + kh * 64 +
                       ((arr >> 1) ? 256 : 0) + ch;
            cp_async16(&kvdst[arr][r * 72 + ch], &src[g]);
        }
        cp_commit();
    };

    load_kv(0);

    for (int t = tid; t < 2048; t += 256) {
        int part = t >> 10;
        int m = (t >> 3) & 127;
        int ch = (t & 7) * 8;
        int hp = m >> 6;
        int rr = m & 63;
        const __nv_bfloat16* src = part ? ql : qh;
        size_t gaddr = (size_t)(b * SS + s0q + rr) * NQKV +
                       (kh * 4 + pair * 2 + hp) * 64 + ch;
        __nv_bfloat16* dst = part ? Qlo : Qhi;
        *reinterpret_cast<uint4*>(&dst[m * 72 + ch]) =
            *reinterpret_cast<const uint4*>(&src[gaddr]);
    }
    if (tid < 128) { m_sh[tid] = -1e30f; l_sh[tid] = 0.0f; }

    const int srow = tid >> 1;
    const int sc0 = (tid & 1) * 32;
    const int srr = srow & 63;
    float ov[32];
#pragma unroll
    for (int i = 0; i < 32; i++) ov[i] = 0.0f;

    for (int kt = 0; kt <= qt; kt++) {
        const int s0k = kt * 64;
        cp_wait0();
        __syncthreads();

        {
            wmma::fragment<wmma::accumulator, 16, 16, 16, float> accs[4];
#pragma unroll
            for (int j = 0; j < 4; j++) wmma::fill_fragment(accs[j], 0.0f);
#pragma unroll
            for (int ks = 0; ks < 4; ks++) {
                wmma::fragment<wmma::matrix_a, 16, 16, 16, __nv_bfloat16, wmma::row_major> a_hi, a_lo;
                wmma::load_matrix_sync(a_hi, &Qhi[m0w * 72 + ks * 16], 72);
                wmma::load_matrix_sync(a_lo, &Qlo[m0w * 72 + ks * 16], 72);
#pragma unroll
                for (int j = 0; j < 4; j++) {
                    wmma::fragment<wmma::matrix_b, 16, 16, 16, __nv_bfloat16, wmma::col_major> b_hi, b_lo;
                    wmma::load_matrix_sync(b_hi, &Khi[(j * 16) * 72 + ks * 16], 72);
                    wmma::load_matrix_sync(b_lo, &Klo[(j * 16) * 72 + ks * 16], 72);
                    wmma::mma_sync(accs[j], a_hi, b_hi, accs[j]);
                    wmma::mma_sync(accs[j], a_hi, b_lo, accs[j]);
                    wmma::mma_sync(accs[j], a_lo, b_hi, accs[j]);
                }
            }
#pragma unroll
            for (int j = 0; j < 4; j++)
                wmma::store_matrix_sync(&Sf[m0w * 68 + j * 16], accs[j], 68, wmma::mem_row_major);
        }
        __syncthreads();

        float sv[32];
        {
            float vmax = -1e30f;
#pragma unroll
            for (int i = 0; i < 32; i++) {
                float s = Sf[srow * 68 + sc0 + i] * 0.125f;
                if (s0k + sc0 + i > s0q + srr) s = -1e30f;
                sv[i] = s;
                vmax = fmaxf(vmax, s);
            }
            vmax = fmaxf(vmax, __shfl_xor_sync(0xffffffffu, vmax, 1));
            float mo = m_sh[srow];
            float mx = fmaxf(mo, vmax);
            float al = __expf(mo - mx);
            __syncthreads();
            float sum = 0.0f;
#pragma unroll
            for (int i = 0; i < 32; i++) {
                float p = __expf(sv[i] - mx);
                sum += p;
                __nv_bfloat16 ph = __float2bfloat16(p);
                Phi[srow * 72 + sc0 + i] = ph;
                Plo[srow * 72 + sc0 + i] = __float2bfloat16(p - __bfloat162float(ph));
            }
            sum += __shfl_xor_sync(0xffffffffu, sum, 1);
            if ((tid & 1) == 0) {
                m_sh[srow] = mx;
                l_sh[srow] = l_sh[srow] * al + sum;
                al_sh[srow] = al;
            }
        }
        __syncthreads();

        {
            wmma::fragment<wmma::accumulator, 16, 16, 16, float> acco[4];
#pragma unroll
            for (int j = 0; j < 4; j++) wmma::fill_fragment(acco[j], 0.0f);
#pragma unroll
            for (int ks = 0; ks < 4; ks++) {
                wmma::fragment<wmma::matrix_a, 16, 16, 16, __nv_bfloat16, wmma::row_major> p_hi, p_lo;
                wmma::load_matrix_sync(p_hi, &Phi[m0w * 72 + ks * 16], 72);
                wmma::load_matrix_sync(p_lo, &Plo[m0w * 72 + ks * 16], 72);
#pragma unroll
                for (int j = 0; j < 4; j++) {
                    wmma::fragment<wmma::matrix_b, 16, 16, 16, __nv_bfloat16, wmma::row_major> v_hi, v_lo;
                    wmma::load_matrix_sync(v_hi, &Vhi[(ks * 16) * 72 + j * 16], 72);
                    wmma::load_matrix_sync(v_lo, &Vlo[(ks * 16) * 72 + j * 16], 72);
                    wmma::mma_sync(acco[j], p_hi, v_hi, acco[j]);
                    wmma::mma_sync(acco[j], p_hi, v_lo, acco[j]);
                    wmma::mma_sync(acco[j], p_lo, v_hi, acco[j]);
                }
            }
            __syncthreads();

            if (kt < qt) load_kv(s0k + 64);

#pragma unroll
            for (int j = 0; j < 4; j++)
                wmma::store_matrix_sync(&Sf[m0w * 68 + j * 16], acco[j], 68, wmma::mem_row_major);
        }
        __syncthreads();

        {
            float al = al_sh[srow];
#pragma unroll
            for (int i = 0; i < 32; i++)
                ov[i] = ov[i] * al + Sf[srow * 68 + sc0 + i];
        }
    }

    float invl = 1.0f / l_sh[srow];
    int hp = srow >> 6;
#pragma unroll
    for (int i = 0; i < 32; i++) {
        float f = ov[i] * invl;
        size_t oaddr = (size_t)(b * SS + s0q + srr) * DD +
                       (kh * 4 + pair * 2 + hp) * 64 + sc0 + i;
        __nv_bfloat16 h = __float2bfloat16(f);
        ohi[oaddr] = h;
        olo[oaddr] = __float2bfloat16(f - __bfloat162float(h));
    }
}

// ---------------------------------------------------------------------------
// Launch: preprocessing on origin stream, then batch-pipelined fork/join.
// ---------------------------------------------------------------------------
extern "C" void kernel_launch(void* const* d_in, const int* in_sizes, int n_in,
                              void* d_out, int out_size) {
    const float* x  = (const float*)d_in[0];
    const float* Wq = (const float*)d_in[2];
    const float* bq = (const float*)d_in[3];
    const float* Wk = (const float*)d_in[4];
    const float* bk = (const float*)d_in[5];
    const float* Wv = (const float*)d_in[6];
    const float* bv = (const float*)d_in[7];
    const float* Wo = (const float*)d_in[8];
    const float* bo = (const float*)d_in[9];
    float* out = (float*)d_out;

    float *gc, *gs, *gbqkv;
    cudaGetSymbolAddress((void**)&gc, g_cos);
    cudaGetSymbolAddress((void**)&gs, g_sin);
    cudaGetSymbolAddress((void**)&gbqkv, g_bqkv);

    __nv_bfloat16 *xhi, *xlo, *ohi, *olo, *wqkvhi, *wqkvlo, *wohi, *wolo, *qkvhi, *qkvlo;
    cudaGetSymbolAddress((void**)&xhi, g_xhi);
    cudaGetSymbolAddress((void**)&xlo, g_xlo);
    cudaGetSymbolAddress((void**)&ohi, g_ohi);
    cudaGetSymbolAddress((void**)&olo, g_olo);
    cudaGetSymbolAddress((void**)&wqkvhi, g_wqkvhi);
    cudaGetSymbolAddress((void**)&wqkvlo, g_wqkvlo);
    cudaGetSymbolAddress((void**)&wohi, g_wohi);
    cudaGetSymbolAddress((void**)&wolo, g_wolo);
    cudaGetSymbolAddress((void**)&qkvhi, g_qkvhi);
    cudaGetSymbolAddress((void**)&qkvlo, g_qkvlo);

    // One-time stream/event setup (host resources only; created outside capture
    // on the first correctness call).
    static cudaStream_t s2 = nullptr;
    static cudaEvent_t eFork = nullptr, eJoin = nullptr;
    static bool attr_set = false;
    if (s2 == nullptr) {
        cudaStreamCreateWithFlags(&s2, cudaStreamNonBlocking);
        cudaEventCreateWithFlags(&eFork, cudaEventDisableTiming);
        cudaEventCreateWithFlags(&eJoin, cudaEventDisableTiming);
    }
    if (!attr_set) {
        cudaFuncSetAttribute(gemm_qkv_rope, cudaFuncAttributeMaxDynamicSharedMemorySize,
                             GSM_TOTAL);
        cudaFuncSetAttribute(gemm_out_bias, cudaFuncAttributeMaxDynamicSharedMemorySize,
                             GSM_TOTAL);
        cudaFuncSetAttribute(flash_tc_v3, cudaFuncAttributeMaxDynamicSharedMemorySize,
                             F3_SMEM_TOTAL);
        attr_set = true;
    }

    const int M = BB * SS;   // 4096
    const int MB = SS;       // rows per batch = 2048
    dim3 blk(128);

    // ---- preprocessing on origin stream ----
    rope_table_kernel<<<(SS * 32 + 255) / 256, 256>>>(gc, gs);
    int nx = M * DD;
    split_kernel<<<(nx + 255) / 256, 256>>>(x, xhi, xlo, nx);
    pack_wqkv_kernel<<<(DD * NQKV + 255) / 256, 256>>>(Wq, Wk, Wv, bq, bk, bv,
                                                       wqkvhi, wqkvlo, gbqkv);
    split_kernel<<<(DD * DD + 255) / 256, 256>>>(Wo, wohi, wolo, DD * DD);

    // ---- fork: batch 1 pipeline on s2 ----
    cudaEventRecord(eFork, 0);
    cudaStreamWaitEvent(s2, eFork, 0);

    // batch 0 (origin stream)
    gemm_qkv_rope<<<dim3(NQKV / 128, MB / 128), blk, GSM_TOTAL>>>(
        xhi, xlo, wqkvhi, wqkvlo, gbqkv, gc, gs, qkvhi, qkvlo, M, NQKV, 1024, 0);
    flash_tc_v3<<<dim3(SS / 64, KHH * 2, 1), 256, F3_SMEM_TOTAL>>>(
        qkvhi, qkvlo, ohi, olo, 0);
    gemm_out_bias<<<dim3(1024 / 128, MB / 128), blk, GSM_TOTAL>>>(
        ohi, olo, wohi, wolo, bo, out, M, 1024, 1024, 0);

    // batch 1 (s2)
    gemm_qkv_rope<<<dim3(NQKV / 128, MB / 128), blk, GSM_TOTAL, s2>>>(
        xhi, xlo, wqkvhi, wqkvlo, gbqkv, gc, gs, qkvhi, qkvlo, M, NQKV, 1024, MB);
    flash_tc_v3<<<dim3(SS / 64, KHH * 2, 1), 256, F3_SMEM_TOTAL, s2>>>(
        qkvhi, qkvlo, ohi, olo, 1);
    gemm_out_bias<<<dim3(1024 / 128, MB / 128), blk, GSM_TOTAL, s2>>>(
        ohi, olo, wohi, wolo, bo, out, M, 1024, 1024, MB);

    // ---- join ----
    cudaEventRecord(eJoin, s2);
    cudaStreamWaitEvent(0, eJoin, 0);
}